// round 2
// baseline (speedup 1.0000x reference)
#include <cuda_runtime.h>
#include <cuda_bf16.h>
#include <math.h>

#define Nn 20000
#define Ee 320000
#define Ff 64
#define Hh 256
#define Ss 32
#define Ll 128
#define Bb 16
#define EPS_F 1e-9f

// ---------------- scratch (device globals; no allocation allowed) ----------------
__device__ float d_P[Nn * Hh];
__device__ float d_Q[Nn * Hh];
__device__ float d_agg[Nn * Hh];
__device__ float d_x[Nn * Hh];
__device__ float d_pooled[Bb * Ss * Hh];
__device__ float d_t2[Bb * Ss * Hh];
__device__ float d_colsum[Ss];
__device__ float d_entsum[1];
__device__ int   d_bstart[Bb + 1];

// ---------------- zero ----------------
__global__ void zero_kernel(float* p, int n) {
    int i = blockIdx.x * blockDim.x + threadIdx.x;
    if (i < n) p[i] = 0.f;
}

// ---------------- generic row-tiled GEMM: C[M,NCOL] = act(A[M,K] @ W[K,NCOL] + bias) ----------------
// blockDim = 256. RPB rows per block. Thread covers column (t % NCOL), rows strided by 256/NCOL.
template <int NCOL, int RPB>
__global__ __launch_bounds__(256) void gemm_tiled(
    const float* __restrict__ A, int K,
    const float* __restrict__ W, const float* __restrict__ bias,
    float* __restrict__ C, int M, int do_relu)
{
    __shared__ float As[RPB * 256];
    const int row0 = blockIdx.x * RPB;
    const int tot = RPB * K;
    for (int idx = threadIdx.x; idx < tot; idx += 256) {
        int r = idx / K, k = idx - r * K;
        int gr = row0 + r;
        As[idx] = (gr < M) ? A[gr * K + k] : 0.f;
    }
    __syncthreads();

    const int RG = 256 / NCOL;       // row groups
    const int RPT = RPB / RG;        // rows per thread
    const int col = threadIdx.x % NCOL;
    const int rg = threadIdx.x / NCOL;

    float acc[RPT];
    float bv = bias ? bias[col] : 0.f;
#pragma unroll
    for (int i = 0; i < RPT; i++) acc[i] = bv;

    for (int k = 0; k < K; k += 4) {
        float wv0 = W[(k + 0) * NCOL + col];
        float wv1 = W[(k + 1) * NCOL + col];
        float wv2 = W[(k + 2) * NCOL + col];
        float wv3 = W[(k + 3) * NCOL + col];
#pragma unroll
        for (int i = 0; i < RPT; i++) {
            const float4 a = *(const float4*)&As[(rg + i * RG) * K + k];
            acc[i] = fmaf(a.x, wv0, acc[i]);
            acc[i] = fmaf(a.y, wv1, acc[i]);
            acc[i] = fmaf(a.z, wv2, acc[i]);
            acc[i] = fmaf(a.w, wv3, acc[i]);
        }
    }
#pragma unroll
    for (int i = 0; i < RPT; i++) {
        int gr = row0 + rg + i * RG;
        if (gr < M) {
            float v = acc[i];
            if (do_relu) v = fmaxf(v, 0.f);
            C[gr * NCOL + col] = v;
        }
    }
}

// ---------------- fused per-edge MLP: h1=relu(P[dst]+Q[src]); h2=relu(h1@w2+b2); m=h2@w3+b3; agg[dst]+=m ----------------
__global__ __launch_bounds__(256) void edge_mlp_kernel(
    const int* __restrict__ src, const int* __restrict__ dst,
    const float* __restrict__ P, const float* __restrict__ Q,
    const float* __restrict__ w2, const float* __restrict__ b2,
    const float* __restrict__ w3, const float* __restrict__ b3,
    float* __restrict__ agg)
{
    const int TE = 32;
    __shared__ float hs[TE * Hh];     // 32 KB, reused for h1 then h2
    __shared__ int ssrc[TE];
    __shared__ int sdst[TE];

    const int e0 = blockIdx.x * TE;
    const int j = threadIdx.x;

    if (j < TE) sdst[j] = dst[e0 + j];
    else if (j < 2 * TE) ssrc[j - TE] = src[e0 + j - TE];
    __syncthreads();

    // h1
#pragma unroll 4
    for (int e = 0; e < TE; e++) {
        float v = P[sdst[e] * Hh + j] + Q[ssrc[e] * Hh + j];
        hs[e * Hh + j] = fmaxf(v, 0.f);
    }
    __syncthreads();

    // GEMM1: h2 = relu(h1 @ w2 + b2)
    float acc[TE];
    {
        float bv = b2[j];
#pragma unroll
        for (int e = 0; e < TE; e++) acc[e] = bv;
        for (int k = 0; k < Hh; k += 4) {
            float wv0 = w2[(k + 0) * Hh + j];
            float wv1 = w2[(k + 1) * Hh + j];
            float wv2 = w2[(k + 2) * Hh + j];
            float wv3 = w2[(k + 3) * Hh + j];
#pragma unroll
            for (int e = 0; e < TE; e++) {
                const float4 a = *(const float4*)&hs[e * Hh + k];
                acc[e] = fmaf(a.x, wv0, acc[e]);
                acc[e] = fmaf(a.y, wv1, acc[e]);
                acc[e] = fmaf(a.z, wv2, acc[e]);
                acc[e] = fmaf(a.w, wv3, acc[e]);
            }
        }
    }
    __syncthreads();
#pragma unroll
    for (int e = 0; e < TE; e++) hs[e * Hh + j] = fmaxf(acc[e], 0.f);
    __syncthreads();

    // GEMM2: m = h2 @ w3 + b3 ; scatter-add to agg[dst]
    {
        float bv = b3[j];
#pragma unroll
        for (int e = 0; e < TE; e++) acc[e] = bv;
        for (int k = 0; k < Hh; k += 4) {
            float wv0 = w3[(k + 0) * Hh + j];
            float wv1 = w3[(k + 1) * Hh + j];
            float wv2 = w3[(k + 2) * Hh + j];
            float wv3 = w3[(k + 3) * Hh + j];
#pragma unroll
            for (int e = 0; e < TE; e++) {
                const float4 a = *(const float4*)&hs[e * Hh + k];
                acc[e] = fmaf(a.x, wv0, acc[e]);
                acc[e] = fmaf(a.y, wv1, acc[e]);
                acc[e] = fmaf(a.z, wv2, acc[e]);
                acc[e] = fmaf(a.w, wv3, acc[e]);
            }
        }
    }
#pragma unroll
    for (int e = 0; e < TE; e++) {
        atomicAdd(&agg[sdst[e] * Hh + j], acc[e]);
    }
}

// ---------------- relu + layernorm per node ----------------
__device__ __forceinline__ float warp_sum(float v) {
#pragma unroll
    for (int o = 16; o > 0; o >>= 1) v += __shfl_xor_sync(0xFFFFFFFFu, v, o);
    return v;
}

__global__ __launch_bounds__(256) void relu_ln_kernel(
    const float* __restrict__ agg, const float* __restrict__ g,
    const float* __restrict__ b, float* __restrict__ xout)
{
    const int n = blockIdx.x;
    const int j = threadIdx.x;
    const int lane = j & 31, warp = j >> 5;
    __shared__ float red[8];
    __shared__ float s_mu, s_rstd;

    float v = fmaxf(agg[n * Hh + j], 0.f);
    float t = warp_sum(v);
    if (lane == 0) red[warp] = t;
    __syncthreads();
    if (j == 0) {
        float s = 0.f;
#pragma unroll
        for (int i = 0; i < 8; i++) s += red[i];
        s_mu = s / (float)Hh;
    }
    __syncthreads();
    float d = v - s_mu;
    float t2 = warp_sum(d * d);
    if (lane == 0) red[warp] = t2;
    __syncthreads();
    if (j == 0) {
        float s = 0.f;
#pragma unroll
        for (int i = 0; i < 8; i++) s += red[i];
        s_rstd = rsqrtf(s / (float)Hh + 1e-5f);
    }
    __syncthreads();
    xout[n * Hh + j] = d * s_rstd * g[j] + b[j];
}

// ---------------- assignment: logits GEMV + gumbel + softmax + entropy/colsum ----------------
__global__ __launch_bounds__(256) void assign_kernel(
    const float* __restrict__ t1, const float* __restrict__ aw2,
    const float* __restrict__ ab2, const float* __restrict__ u,
    float* __restrict__ s_out, float* __restrict__ entsum, float* __restrict__ colsum)
{
    __shared__ float rows[8 * Hh];
    __shared__ float blk_col[Ss];
    __shared__ float blk_ent;

    const int lane = threadIdx.x & 31, warp = threadIdx.x >> 5;
    if (threadIdx.x < Ss) blk_col[threadIdx.x] = 0.f;
    if (threadIdx.x == 0) blk_ent = 0.f;
    const int n0 = blockIdx.x * 8;
    for (int idx = threadIdx.x; idx < 8 * Hh; idx += 256)
        rows[idx] = t1[n0 * Hh + idx];
    __syncthreads();

    const int n = n0 + warp;
    float acc = ab2[lane];
    for (int k = 0; k < Hh; k += 4) {
        const float4 a = *(const float4*)&rows[warp * Hh + k];
        acc = fmaf(a.x, aw2[(k + 0) * Ss + lane], acc);
        acc = fmaf(a.y, aw2[(k + 1) * Ss + lane], acc);
        acc = fmaf(a.z, aw2[(k + 2) * Ss + lane], acc);
        acc = fmaf(a.w, aw2[(k + 3) * Ss + lane], acc);
    }
    float uu = u[n * Ss + lane];
    float gmb = -logf(-logf(uu + EPS_F) + EPS_F);
    float z = acc + gmb;  // TAU = 1
    float m = z;
#pragma unroll
    for (int o = 16; o > 0; o >>= 1) m = fmaxf(m, __shfl_xor_sync(0xFFFFFFFFu, m, o));
    float p = expf(z - m);
    float sum = warp_sum(p);
    float sv = p / sum;
    s_out[n * Ss + lane] = sv;

    float ent = warp_sum(sv * logf(sv + EPS_F));
    if (lane == 0) atomicAdd(&blk_ent, ent);
    atomicAdd(&blk_col[lane], sv);
    __syncthreads();
    if (threadIdx.x == 0) atomicAdd(entsum, blk_ent);
    if (threadIdx.x < Ss) atomicAdd(&colsum[threadIdx.x], blk_col[threadIdx.x]);
}

// ---------------- batch segment starts ----------------
__global__ void bstart_kernel(const int* __restrict__ batch, int* __restrict__ bstart) {
    int b = threadIdx.x;
    if (b > Bb) return;
    if (b == Bb) { bstart[Bb] = Nn; return; }
    // lower bound: first i with batch[i] >= b
    int lo = 0, hi = Nn;
    while (lo < hi) {
        int mid = (lo + hi) >> 1;
        if (batch[mid] < b) lo = mid + 1; else hi = mid;
    }
    bstart[b] = lo;
}

// ---------------- pooled[b,s,h] = sum_{n in batch b} x[n,h]*s[n,s] ----------------
__global__ __launch_bounds__(256) void pool_kernel(
    const float* __restrict__ x, const float* __restrict__ s_out,
    const int* __restrict__ bstart, float* __restrict__ pooled)
{
    const int b = blockIdx.x;
    const int chunk = blockIdx.y;
    const int NCHUNK = gridDim.y;
    const int lo = bstart[b], hi = bstart[b + 1];
    const int cnt = hi - lo;
    const int c0 = lo + (int)(((long long)cnt * chunk) / NCHUNK);
    const int c1 = lo + (int)(((long long)cnt * (chunk + 1)) / NCHUNK);

    __shared__ float ss[Ss];
    const int t = threadIdx.x;
    float acc[Ss];
#pragma unroll
    for (int sl = 0; sl < Ss; sl++) acc[sl] = 0.f;

    for (int n = c0; n < c1; n++) {
        __syncthreads();
        if (t < Ss) ss[t] = s_out[n * Ss + t];
        __syncthreads();
        float xv = x[n * Hh + t];
#pragma unroll
        for (int sl = 0; sl < Ss; sl++) acc[sl] = fmaf(xv, ss[sl], acc[sl]);
    }
#pragma unroll
    for (int sl = 0; sl < Ss; sl++)
        atomicAdd(&pooled[(b * Ss + sl) * Hh + t], acc[sl]);
}

// ---------------- final scalar loss ----------------
__global__ void finalize_kernel(const float* __restrict__ colsum,
                                const float* __restrict__ entsum,
                                float* __restrict__ out_loss)
{
    int l = threadIdx.x;
    float avg = colsum[l] / (float)Nn;
    float dv = avg * logf(avg + EPS_F);
    dv = warp_sum(dv);
    if (l == 0) {
        float entropy = -(entsum[0] / (float)Nn);
        out_loss[0] = entropy + dv;
    }
}

// ---------------- launch ----------------
extern "C" void kernel_launch(void* const* d_in, const int* in_sizes, int n_in,
                              void* d_out, int out_size)
{
    const float* x    = (const float*)d_in[0];
    const float* u    = (const float*)d_in[1];
    const int* eidx   = (const int*)d_in[2];
    const int* batch  = (const int*)d_in[3];
    const float* g1w1 = (const float*)d_in[4];
    const float* g1b1 = (const float*)d_in[5];
    const float* g1w2 = (const float*)d_in[6];
    const float* g1b2 = (const float*)d_in[7];
    const float* g1w3 = (const float*)d_in[8];
    const float* g1b3 = (const float*)d_in[9];
    const float* ln1g = (const float*)d_in[10];
    const float* ln1b = (const float*)d_in[11];
    const float* g2w1 = (const float*)d_in[12];
    const float* g2b1 = (const float*)d_in[13];
    const float* g2w2 = (const float*)d_in[14];
    const float* g2b2 = (const float*)d_in[15];
    const float* g2w3 = (const float*)d_in[16];
    const float* g2b3 = (const float*)d_in[17];
    const float* ln2g = (const float*)d_in[18];
    const float* ln2b = (const float*)d_in[19];
    const float* aw1  = (const float*)d_in[20];
    const float* ab1  = (const float*)d_in[21];
    const float* aw2  = (const float*)d_in[22];
    const float* ab2  = (const float*)d_in[23];
    const float* ow1  = (const float*)d_in[24];
    const float* ob1  = (const float*)d_in[25];
    const float* ow2  = (const float*)d_in[26];
    const float* ob2  = (const float*)d_in[27];

    const int* src = eidx;           // edge_index[0]
    const int* dst = eidx + Ee;      // edge_index[1]

    float* out = (float*)d_out;
    float* out_latent = out;                         // [B,S,L] = 65536
    float* out_s = out + Bb * Ss * Ll;               // [N,S]   = 640000
    float* out_loss = out + Bb * Ss * Ll + Nn * Ss;  // [1]

    float *P, *Q, *agg, *xc, *pooled, *t2, *colsum, *entsum;
    int* bstart;
    cudaGetSymbolAddress((void**)&P, d_P);
    cudaGetSymbolAddress((void**)&Q, d_Q);
    cudaGetSymbolAddress((void**)&agg, d_agg);
    cudaGetSymbolAddress((void**)&xc, d_x);
    cudaGetSymbolAddress((void**)&pooled, d_pooled);
    cudaGetSymbolAddress((void**)&t2, d_t2);
    cudaGetSymbolAddress((void**)&colsum, d_colsum);
    cudaGetSymbolAddress((void**)&entsum, d_entsum);
    cudaGetSymbolAddress((void**)&bstart, d_bstart);

    const int NH = Nn * Hh;
    const int ZB = 256;

    // ---- zero accumulators ----
    zero_kernel<<<(NH + ZB - 1) / ZB, ZB>>>(agg, NH);
    zero_kernel<<<(Bb * Ss * Hh + ZB - 1) / ZB, ZB>>>(pooled, Bb * Ss * Hh);
    zero_kernel<<<1, ZB>>>(colsum, Ss);
    zero_kernel<<<1, ZB>>>(entsum, 1);

    // ---- GNN layer 1 ----
    // P = x @ g1w1[0:F,:]   (dst part);  Q = x @ g1w1[F:2F,:] + g1b1  (src part)
    gemm_tiled<Hh, 32><<<Nn / 32, 256>>>(x, Ff, g1w1, nullptr, P, Nn, 0);
    gemm_tiled<Hh, 32><<<Nn / 32, 256>>>(x, Ff, g1w1 + Ff * Hh, g1b1, Q, Nn, 0);
    edge_mlp_kernel<<<Ee / 32, 256>>>(src, dst, P, Q, g1w2, g1b2, g1w3, g1b3, agg);
    relu_ln_kernel<<<Nn, 256>>>(agg, ln1g, ln1b, xc);

    // ---- GNN layer 2 ----
    gemm_tiled<Hh, 32><<<Nn / 32, 256>>>(xc, Hh, g2w1, nullptr, P, Nn, 0);
    gemm_tiled<Hh, 32><<<Nn / 32, 256>>>(xc, Hh, g2w1 + Hh * Hh, g2b1, Q, Nn, 0);
    zero_kernel<<<(NH + ZB - 1) / ZB, ZB>>>(agg, NH);
    edge_mlp_kernel<<<Ee / 32, 256>>>(src, dst, P, Q, g2w2, g2b2, g2w3, g2b3, agg);
    relu_ln_kernel<<<Nn, 256>>>(agg, ln2g, ln2b, xc);

    // ---- assignment: t1 = relu(x @ aw1 + ab1) -> logits/gumbel/softmax ----
    gemm_tiled<Hh, 32><<<Nn / 32, 256>>>(xc, Hh, aw1, ab1, P, Nn, 1);   // reuse P as t1
    assign_kernel<<<Nn / 8, 256>>>(P, aw2, ab2, u, out_s, entsum, colsum);

    // ---- pooling ----
    bstart_kernel<<<1, 32>>>(batch, bstart);
    {
        dim3 grid(Bb, 8);
        pool_kernel<<<grid, 256>>>(xc, out_s, bstart, pooled);
    }

    // ---- output MLP: latent = relu(pooled @ ow1 + ob1) @ ow2 + ob2 ----
    gemm_tiled<Hh, 32><<<(Bb * Ss) / 32, 256>>>(pooled, Hh, ow1, ob1, t2, Bb * Ss, 1);
    gemm_tiled<Ll, 32><<<(Bb * Ss) / 32, 256>>>(t2, Hh, ow2, ob2, out_latent, Bb * Ss, 0);

    // ---- loss scalar ----
    finalize_kernel<<<1, 32>>>(colsum, entsum, out_loss);
}

// round 6
// speedup vs baseline: 1.7804x; 1.7804x over previous
#include <cuda_runtime.h>
#include <cuda_bf16.h>
#include <math.h>
#include <stdint.h>

#define Nn 20000
#define Ee 320000
#define Ff 64
#define Hh 256
#define Ss 32
#define Ll 128
#define Bb 16
#define EPS_F 1e-9f

// ---------------- scratch (device globals; no allocation allowed) ----------------
__device__ float d_P[Nn * Hh];
__device__ float d_Q[Nn * Hh];
__device__ float d_agg[Nn * Hh];
__device__ float d_x[Nn * Hh];
__device__ float d_pooled[Bb * Ss * Hh];
__device__ float d_t2[Bb * Ss * Hh];
__device__ float d_colsum[Ss];
__device__ float d_entsum[1];
__device__ int   d_bstart[Bb + 1];
__device__ __align__(256) __nv_bfloat16 d_wbf[8 * Hh * Hh]; // [w2hi,w2lo,w3hi,w3lo] x 2 layers

// ================= warp-MMA helpers (sm_80-compatible PTX) =================
__device__ __forceinline__ uint32_t smem_u32(const void* p) {
    uint32_t a;
    asm("{ .reg .u64 t; cvta.to.shared.u64 t, %1; cvt.u32.u64 %0, t; }" : "=r"(a) : "l"(p));
    return a;
}
__device__ __forceinline__ void cp16(uint32_t saddr, const void* g) {
    asm volatile("cp.async.cg.shared.global [%0], [%1], 16;" :: "r"(saddr), "l"(g));
}
#define CP_COMMIT() asm volatile("cp.async.commit_group;" ::: "memory")
#define CP_WAIT1()  asm volatile("cp.async.wait_group 1;" ::: "memory")
#define CP_WAIT0()  asm volatile("cp.async.wait_group 0;" ::: "memory")

#define LDSM4(r0, r1, r2, r3, addr) \
    asm volatile("ldmatrix.sync.aligned.m8n8.x4.shared.b16 {%0,%1,%2,%3}, [%4];" \
        : "=r"(r0), "=r"(r1), "=r"(r2), "=r"(r3) : "r"(addr))

__device__ __forceinline__ void mma16816(float* c,
    uint32_t a0, uint32_t a1, uint32_t a2, uint32_t a3, uint32_t b0, uint32_t b1) {
    asm volatile("mma.sync.aligned.m16n8k16.row.col.f32.bf16.bf16.f32 "
        "{%0,%1,%2,%3}, {%4,%5,%6,%7}, {%8,%9}, {%0,%1,%2,%3};"
        : "+f"(c[0]), "+f"(c[1]), "+f"(c[2]), "+f"(c[3])
        : "r"(a0), "r"(a1), "r"(a2), "r"(a3), "r"(b0), "r"(b1));
}

// ================= SMEM layout for edge kernel (bytes) =================
#define AROW    528                      // 256 bf16 + 16B pad (conflict-free ldmatrix)
#define SM_AHI  0
#define SM_ALO  (128 * AROW)             // 67584
#define SM_BBUF (2 * 128 * AROW)         // 135168 : 2 x (8KB hi + 8KB lo)
#define SM_IDS  (SM_BBUF + 32768)        // 167936 : sdst[128], ssrc[128]
#define SM_B2   (SM_IDS + 1024)          // 168960
#define SM_B3   (SM_B2 + 1024)           // 169984
#define SM_TOT  (SM_B3 + 1024)           // 171008

// ---------------- weight transpose + bf16 split ----------------
__global__ void wsplit_kernel(const float* __restrict__ w,
                              __nv_bfloat16* __restrict__ hi, __nv_bfloat16* __restrict__ lo) {
    int i = blockIdx.x * 256 + threadIdx.x;   // i = n*256 + k
    int n = i >> 8, k = i & 255;
    float v = w[k * Hh + n];
    __nv_bfloat16 h = __float2bfloat16(v);
    hi[i] = h;
    lo[i] = __float2bfloat16(v - __bfloat162float(h));
}

// ---------------- B-slice loader: 16 k-rows x 256 n, hi+lo, xor-swizzled ----------------
__device__ __forceinline__ void load_slice(int s, uint32_t sb, int t,
    const __nv_bfloat16* w2hi, const __nv_bfloat16* w2lo,
    const __nv_bfloat16* w3hi, const __nv_bfloat16* w3lo)
{
    const __nv_bfloat16* Wh = (s < 16) ? w2hi : w3hi;
    const __nv_bfloat16* Wl = (s < 16) ? w2lo : w3lo;
    const int kt = s & 15;
    const uint32_t base = sb + SM_BBUF + (uint32_t)(s & 1) * 16384u;
    const int n = t;                                  // 256 threads -> 256 n-rows
    const char* gh = (const char*)(Wh + (size_t)n * Hh + kt * 16);
    const char* gl = (const char*)(Wl + (size_t)n * Hh + kt * 16);
    const uint32_t sw4 = (n & 4) ? 16u : 0u;
    const uint32_t doff = base + (uint32_t)n * 32u;
    cp16(doff + (0u ^ sw4), gh);
    cp16(doff + (16u ^ sw4), gh + 16);
    cp16(doff + 8192u + (0u ^ sw4), gl);
    cp16(doff + 8192u + (16u ^ sw4), gl + 16);
}

// ---------------- fused tensor-core edge MLP (warp mma.sync) ----------------
__global__ __launch_bounds__(256, 1) void edge_mma_kernel(
    const int* __restrict__ src, const int* __restrict__ dst,
    const float* __restrict__ P, const float* __restrict__ Q,
    const __nv_bfloat16* __restrict__ w2hi, const __nv_bfloat16* __restrict__ w2lo,
    const __nv_bfloat16* __restrict__ w3hi, const __nv_bfloat16* __restrict__ w3lo,
    const float* __restrict__ b2, const float* __restrict__ b3,
    float* __restrict__ agg)
{
    extern __shared__ char sm[];
    const uint32_t sb = smem_u32(sm);
    const int t = threadIdx.x;
    const int w = t >> 5, l = t & 31;

    int* sdst = (int*)(sm + SM_IDS);
    int* ssrc = sdst + 128;
    float* sb2 = (float*)(sm + SM_B2);
    float* sb3 = (float*)(sm + SM_B3);

    if (t < 128) {
        sdst[t] = dst[blockIdx.x * 128 + t];
        ssrc[t] = src[blockIdx.x * 128 + t];
    }
    sb2[t] = b2[t];
    sb3[t] = b3[t];
    __syncthreads();

    // ---- build A = split(relu(P[dst] + Q[src])) : 2 threads per edge row ----
    {
        const int e = t & 127, h = t >> 7;
        const int de = sdst[e], se = ssrc[e];
        const float4* Pr = reinterpret_cast<const float4*>(P) + (size_t)de * 64 + h * 32;
        const float4* Qr = reinterpret_cast<const float4*>(Q) + (size_t)se * 64 + h * 32;
        const uint32_t arow = (uint32_t)e * AROW + (uint32_t)h * 256u;
#pragma unroll
        for (int j = 0; j < 16; j++) {
            float4 p0 = Pr[2 * j], q0 = Qr[2 * j];
            float4 p1 = Pr[2 * j + 1], q1 = Qr[2 * j + 1];
            float v[8] = { p0.x + q0.x, p0.y + q0.y, p0.z + q0.z, p0.w + q0.w,
                           p1.x + q1.x, p1.y + q1.y, p1.z + q1.z, p1.w + q1.w };
            union { uint4 u; __nv_bfloat162 h2[4]; } HI, LO;
#pragma unroll
            for (int p = 0; p < 4; p++) {
                float v0 = fmaxf(v[p * 2], 0.f), v1 = fmaxf(v[p * 2 + 1], 0.f);
                __nv_bfloat16 h0 = __float2bfloat16(v0), h1 = __float2bfloat16(v1);
                HI.h2[p] = __halves2bfloat162(h0, h1);
                LO.h2[p] = __floats2bfloat162_rn(v0 - __bfloat162float(h0),
                                                 v1 - __bfloat162float(h1));
            }
            *(uint4*)(sm + SM_AHI + arow + j * 16) = HI.u;
            *(uint4*)(sm + SM_ALO + arow + j * 16) = LO.u;
        }
    }

    // ---- accumulators: warp w owns rows [16w,16w+16) x 256 cols ----
    float acc[32][4];
#pragma unroll
    for (int i = 0; i < 32; i++) {
        acc[i][0] = 0.f; acc[i][1] = 0.f; acc[i][2] = 0.f; acc[i][3] = 0.f;
    }

    // per-lane ldmatrix offsets
    const uint32_t a_off = sb + (uint32_t)((w * 16 + (l % 16)) * AROW + (l / 16) * 16);
    const uint32_t b_off = (uint32_t)((l % 16) * 32) +
                           (uint32_t)(((l / 16) * 16) ^ (((l % 16) & 4) ? 16 : 0));

    load_slice(0, sb, t, w2hi, w2lo, w3hi, w3lo); CP_COMMIT();
    load_slice(1, sb, t, w2hi, w2lo, w3hi, w3lo); CP_COMMIT();

#pragma unroll 1
    for (int s = 0; s < 32; s++) {
        if (s < 30) { CP_WAIT1(); } else { CP_WAIT0(); }
        __syncthreads();

        const int kt = s & 15;
        uint32_t ah0, ah1, ah2, ah3, al0, al1, al2, al3;
        LDSM4(ah0, ah1, ah2, ah3, a_off + SM_AHI + kt * 32);
        LDSM4(al0, al1, al2, al3, a_off + SM_ALO + kt * 32);

        const uint32_t bbase = sb + SM_BBUF + (uint32_t)(s & 1) * 16384u + b_off;
#pragma unroll
        for (int ntp = 0; ntp < 16; ntp++) {
            uint32_t bh0, bh1, bh2, bh3, bl0, bl1, bl2, bl3;
            LDSM4(bh0, bh1, bh2, bh3, bbase + ntp * 512);
            LDSM4(bl0, bl1, bl2, bl3, bbase + 8192 + ntp * 512);
            // even n-tile: (b0=r0, b1=r2); odd n-tile: (b0=r1, b1=r3)
            mma16816(acc[2 * ntp],     ah0, ah1, ah2, ah3, bh0, bh2);  // Ahi*Bhi
            mma16816(acc[2 * ntp],     ah0, ah1, ah2, ah3, bl0, bl2);  // Ahi*Blo
            mma16816(acc[2 * ntp],     al0, al1, al2, al3, bh0, bh2);  // Alo*Bhi
            mma16816(acc[2 * ntp + 1], ah0, ah1, ah2, ah3, bh1, bh3);
            mma16816(acc[2 * ntp + 1], ah0, ah1, ah2, ah3, bl1, bl3);
            mma16816(acc[2 * ntp + 1], al0, al1, al2, al3, bh1, bh3);
        }

        if (s == 15) {
            // ---- epilogue 1 (warp-local): A := split(relu(D1 + b2)) into own rows ----
            const int r0 = w * 16 + l / 4;
            const int cb = (l % 4) * 2;
#pragma unroll
            for (int nt = 0; nt < 32; nt++) {
                const int cn = nt * 8 + cb;
                const float bz0 = sb2[cn], bz1 = sb2[cn + 1];
                float v0 = fmaxf(acc[nt][0] + bz0, 0.f);
                float v1 = fmaxf(acc[nt][1] + bz1, 0.f);
                float v2 = fmaxf(acc[nt][2] + bz0, 0.f);
                float v3 = fmaxf(acc[nt][3] + bz1, 0.f);
                __nv_bfloat16 h0 = __float2bfloat16(v0), h1 = __float2bfloat16(v1);
                __nv_bfloat16 h2 = __float2bfloat16(v2), h3 = __float2bfloat16(v3);
                __nv_bfloat162 hp0 = __halves2bfloat162(h0, h1);
                __nv_bfloat162 hp1 = __halves2bfloat162(h2, h3);
                __nv_bfloat162 lp0 = __floats2bfloat162_rn(v0 - __bfloat162float(h0),
                                                           v1 - __bfloat162float(h1));
                __nv_bfloat162 lp1 = __floats2bfloat162_rn(v2 - __bfloat162float(h2),
                                                           v3 - __bfloat162float(h3));
                *(uint32_t*)(sm + SM_AHI + r0 * AROW + cn * 2)       = *(uint32_t*)&hp0;
                *(uint32_t*)(sm + SM_AHI + (r0 + 8) * AROW + cn * 2) = *(uint32_t*)&hp1;
                *(uint32_t*)(sm + SM_ALO + r0 * AROW + cn * 2)       = *(uint32_t*)&lp0;
                *(uint32_t*)(sm + SM_ALO + (r0 + 8) * AROW + cn * 2) = *(uint32_t*)&lp1;
                acc[nt][0] = 0.f; acc[nt][1] = 0.f; acc[nt][2] = 0.f; acc[nt][3] = 0.f;
            }
            __syncwarp();
        }
        __syncthreads();
        if (s + 2 < 32) {
            load_slice(s + 2, sb, t, w2hi, w2lo, w3hi, w3lo);
            CP_COMMIT();
        }
    }

    // ---- epilogue 2: agg[dst] += D2 + b3 ----
    {
        const int er = w * 16 + l / 4;
        const int cb = (l % 4) * 2;
        const int d0 = sdst[er], d1 = sdst[er + 8];
        float* a0 = agg + (size_t)d0 * Hh;
        float* a1 = agg + (size_t)d1 * Hh;
#pragma unroll
        for (int nt = 0; nt < 32; nt++) {
            const int cn = nt * 8 + cb;
            const float bz0 = sb3[cn], bz1 = sb3[cn + 1];
            atomicAdd(a0 + cn,     acc[nt][0] + bz0);
            atomicAdd(a0 + cn + 1, acc[nt][1] + bz1);
            atomicAdd(a1 + cn,     acc[nt][2] + bz0);
            atomicAdd(a1 + cn + 1, acc[nt][3] + bz1);
        }
    }
}

// ---------------- zero ----------------
__global__ void zero_kernel(float* p, int n) {
    int i = blockIdx.x * blockDim.x + threadIdx.x;
    if (i < n) p[i] = 0.f;
}

// ---------------- generic row-tiled fp32 GEMM ----------------
template <int NCOL, int RPB>
__global__ __launch_bounds__(256) void gemm_tiled(
    const float* __restrict__ A, int K,
    const float* __restrict__ W, const float* __restrict__ bias,
    float* __restrict__ C, int M, int do_relu)
{
    __shared__ float As[RPB * 256];
    const int row0 = blockIdx.x * RPB;
    const int tot = RPB * K;
    for (int idx = threadIdx.x; idx < tot; idx += 256) {
        int r = idx / K, k = idx - r * K;
        int gr = row0 + r;
        As[idx] = (gr < M) ? A[gr * K + k] : 0.f;
    }
    __syncthreads();

    const int RG = 256 / NCOL;
    const int RPT = RPB / RG;
    const int col = threadIdx.x % NCOL;
    const int rg = threadIdx.x / NCOL;

    float acc[RPT];
    float bv = bias ? bias[col] : 0.f;
#pragma unroll
    for (int i = 0; i < RPT; i++) acc[i] = bv;

    for (int k = 0; k < K; k += 4) {
        float wv0 = W[(k + 0) * NCOL + col];
        float wv1 = W[(k + 1) * NCOL + col];
        float wv2 = W[(k + 2) * NCOL + col];
        float wv3 = W[(k + 3) * NCOL + col];
#pragma unroll
        for (int i = 0; i < RPT; i++) {
            const float4 a = *(const float4*)&As[(rg + i * RG) * K + k];
            acc[i] = fmaf(a.x, wv0, acc[i]);
            acc[i] = fmaf(a.y, wv1, acc[i]);
            acc[i] = fmaf(a.z, wv2, acc[i]);
            acc[i] = fmaf(a.w, wv3, acc[i]);
        }
    }
#pragma unroll
    for (int i = 0; i < RPT; i++) {
        int gr = row0 + rg + i * RG;
        if (gr < M) {
            float v = acc[i];
            if (do_relu) v = fmaxf(v, 0.f);
            C[gr * NCOL + col] = v;
        }
    }
}

// ---------------- relu + layernorm per node ----------------
__device__ __forceinline__ float warp_sum(float v) {
#pragma unroll
    for (int o = 16; o > 0; o >>= 1) v += __shfl_xor_sync(0xFFFFFFFFu, v, o);
    return v;
}

__global__ __launch_bounds__(256) void relu_ln_kernel(
    const float* __restrict__ agg, const float* __restrict__ g,
    const float* __restrict__ b, float* __restrict__ xout)
{
    const int n = blockIdx.x;
    const int j = threadIdx.x;
    const int lane = j & 31, warp = j >> 5;
    __shared__ float red[8];
    __shared__ float s_mu, s_rstd;

    float v = fmaxf(agg[n * Hh + j], 0.f);
    float t = warp_sum(v);
    if (lane == 0) red[warp] = t;
    __syncthreads();
    if (j == 0) {
        float s = 0.f;
#pragma unroll
        for (int i = 0; i < 8; i++) s += red[i];
        s_mu = s / (float)Hh;
    }
    __syncthreads();
    float d = v - s_mu;
    float t2 = warp_sum(d * d);
    if (lane == 0) red[warp] = t2;
    __syncthreads();
    if (j == 0) {
        float s = 0.f;
#pragma unroll
        for (int i = 0; i < 8; i++) s += red[i];
        s_rstd = rsqrtf(s / (float)Hh + 1e-5f);
    }
    __syncthreads();
    xout[n * Hh + j] = d * s_rstd * g[j] + b[j];
}

// ---------------- assignment ----------------
__global__ __launch_bounds__(256) void assign_kernel(
    const float* __restrict__ t1, const float* __restrict__ aw2,
    const float* __restrict__ ab2, const float* __restrict__ u,
    float* __restrict__ s_out, float* __restrict__ entsum, float* __restrict__ colsum)
{
    __shared__ float rows[8 * Hh];
    __shared__ float blk_col[Ss];
    __shared__ float blk_ent;

    const int lane = threadIdx.x & 31, warp = threadIdx.x >> 5;
    if (threadIdx.x < Ss) blk_col[threadIdx.x] = 0.f;
    if (threadIdx.x == 0) blk_ent = 0.f;
    const int n0 = blockIdx.x * 8;
    for (int idx = threadIdx.x; idx < 8 * Hh; idx += 256)
        rows[idx] = t1[n0 * Hh + idx];
    __syncthreads();

    const int n = n0 + warp;
    float acc = ab2[lane];
    for (int k = 0; k < Hh; k += 4) {
        const float4 a = *(const float4*)&rows[warp * Hh + k];
        acc = fmaf(a.x, aw2[(k + 0) * Ss + lane], acc);
        acc = fmaf(a.y, aw2[(k + 1) * Ss + lane], acc);
        acc = fmaf(a.z, aw2[(k + 2) * Ss + lane], acc);
        acc = fmaf(a.w, aw2[(k + 3) * Ss + lane], acc);
    }
    float uu = u[n * Ss + lane];
    float gmb = -logf(-logf(uu + EPS_F) + EPS_F);
    float z = acc + gmb;
    float m = z;
#pragma unroll
    for (int o = 16; o > 0; o >>= 1) m = fmaxf(m, __shfl_xor_sync(0xFFFFFFFFu, m, o));
    float p = expf(z - m);
    float sum = warp_sum(p);
    float sv = p / sum;
    s_out[n * Ss + lane] = sv;

    float ent = warp_sum(sv * logf(sv + EPS_F));
    if (lane == 0) atomicAdd(&blk_ent, ent);
    atomicAdd(&blk_col[lane], sv);
    __syncthreads();
    if (threadIdx.x == 0) atomicAdd(entsum, blk_ent);
    if (threadIdx.x < Ss) atomicAdd(&colsum[threadIdx.x], blk_col[threadIdx.x]);
}

// ---------------- batch segment starts ----------------
__global__ void bstart_kernel(const int* __restrict__ batch, int* __restrict__ bstart) {
    int b = threadIdx.x;
    if (b > Bb) return;
    if (b == Bb) { bstart[Bb] = Nn; return; }
    int lo = 0, hi = Nn;
    while (lo < hi) {
        int mid = (lo + hi) >> 1;
        if (batch[mid] < b) lo = mid + 1; else hi = mid;
    }
    bstart[b] = lo;
}

// ---------------- pooling ----------------
__global__ __launch_bounds__(256) void pool_kernel(
    const float* __restrict__ x, const float* __restrict__ s_out,
    const int* __restrict__ bstart, float* __restrict__ pooled)
{
    const int b = blockIdx.x;
    const int chunk = blockIdx.y;
    const int NCHUNK = gridDim.y;
    const int lo = bstart[b], hi = bstart[b + 1];
    const int cnt = hi - lo;
    const int c0 = lo + (int)(((long long)cnt * chunk) / NCHUNK);
    const int c1 = lo + (int)(((long long)cnt * (chunk + 1)) / NCHUNK);

    __shared__ float ss[Ss];
    const int t = threadIdx.x;
    float acc[Ss];
#pragma unroll
    for (int sl = 0; sl < Ss; sl++) acc[sl] = 0.f;

    for (int n = c0; n < c1; n++) {
        __syncthreads();
        if (t < Ss) ss[t] = s_out[n * Ss + t];
        __syncthreads();
        float xv = x[n * Hh + t];
#pragma unroll
        for (int sl = 0; sl < Ss; sl++) acc[sl] = fmaf(xv, ss[sl], acc[sl]);
    }
#pragma unroll
    for (int sl = 0; sl < Ss; sl++)
        atomicAdd(&pooled[(b * Ss + sl) * Hh + t], acc[sl]);
}

// ---------------- final scalar loss ----------------
__global__ void finalize_kernel(const float* __restrict__ colsum,
                                const float* __restrict__ entsum,
                                float* __restrict__ out_loss)
{
    int l = threadIdx.x;
    float avg = colsum[l] / (float)Nn;
    float dv = avg * logf(avg + EPS_F);
    dv = warp_sum(dv);
    if (l == 0) {
        float entropy = -(entsum[0] / (float)Nn);
        out_loss[0] = entropy + dv;
    }
}

// ---------------- launch ----------------
extern "C" void kernel_launch(void* const* d_in, const int* in_sizes, int n_in,
                              void* d_out, int out_size)
{
    const float* x    = (const float*)d_in[0];
    const float* u    = (const float*)d_in[1];
    const int* eidx   = (const int*)d_in[2];
    const int* batch  = (const int*)d_in[3];
    const float* g1w1 = (const float*)d_in[4];
    const float* g1b1 = (const float*)d_in[5];
    const float* g1w2 = (const float*)d_in[6];
    const float* g1b2 = (const float*)d_in[7];
    const float* g1w3 = (const float*)d_in[8];
    const float* g1b3 = (const float*)d_in[9];
    const float* ln1g = (const float*)d_in[10];
    const float* ln1b = (const float*)d_in[11];
    const float* g2w1 = (const float*)d_in[12];
    const float* g2b1 = (const float*)d_in[13];
    const float* g2w2 = (const float*)d_in[14];
    const float* g2b2 = (const float*)d_in[15];
    const float* g2w3 = (const float*)d_in[16];
    const float* g2b3 = (const float*)d_in[17];
    const float* ln2g = (const float*)d_in[18];
    const float* ln2b = (const float*)d_in[19];
    const float* aw1  = (const float*)d_in[20];
    const float* ab1  = (const float*)d_in[21];
    const float* aw2  = (const float*)d_in[22];
    const float* ab2  = (const float*)d_in[23];
    const float* ow1  = (const float*)d_in[24];
    const float* ob1  = (const float*)d_in[25];
    const float* ow2  = (const float*)d_in[26];
    const float* ob2  = (const float*)d_in[27];

    const int* src = eidx;
    const int* dst = eidx + Ee;

    float* out = (float*)d_out;
    float* out_latent = out;
    float* out_s = out + Bb * Ss * Ll;
    float* out_loss = out + Bb * Ss * Ll + Nn * Ss;

    float *P, *Q, *agg, *xc, *pooled, *t2, *colsum, *entsum;
    int* bstart;
    __nv_bfloat16* wbf;
    cudaGetSymbolAddress((void**)&P, d_P);
    cudaGetSymbolAddress((void**)&Q, d_Q);
    cudaGetSymbolAddress((void**)&agg, d_agg);
    cudaGetSymbolAddress((void**)&xc, d_x);
    cudaGetSymbolAddress((void**)&pooled, d_pooled);
    cudaGetSymbolAddress((void**)&t2, d_t2);
    cudaGetSymbolAddress((void**)&colsum, d_colsum);
    cudaGetSymbolAddress((void**)&entsum, d_entsum);
    cudaGetSymbolAddress((void**)&bstart, d_bstart);
    cudaGetSymbolAddress((void**)&wbf, d_wbf);

    cudaFuncSetAttribute(edge_mma_kernel, cudaFuncAttributeMaxDynamicSharedMemorySize, SM_TOT);

    const int NH = Nn * Hh;
    const int ZB = 256;
    const int WN = Hh * Hh;   // 65536

    // ---- zero accumulators ----
    zero_kernel<<<(NH + ZB - 1) / ZB, ZB>>>(agg, NH);
    zero_kernel<<<(Bb * Ss * Hh + ZB - 1) / ZB, ZB>>>(pooled, Bb * Ss * Hh);
    zero_kernel<<<1, ZB>>>(colsum, Ss);
    zero_kernel<<<1, ZB>>>(entsum, 1);

    // ---- transpose + split weights to bf16 hi/lo ([n][k] layout) ----
    wsplit_kernel<<<256, 256>>>(g1w2, wbf + 0 * WN, wbf + 1 * WN);
    wsplit_kernel<<<256, 256>>>(g1w3, wbf + 2 * WN, wbf + 3 * WN);
    wsplit_kernel<<<256, 256>>>(g2w2, wbf + 4 * WN, wbf + 5 * WN);
    wsplit_kernel<<<256, 256>>>(g2w3, wbf + 6 * WN, wbf + 7 * WN);

    // ---- GNN layer 1 ----
    gemm_tiled<Hh, 32><<<Nn / 32, 256>>>(x, Ff, g1w1, nullptr, P, Nn, 0);
    gemm_tiled<Hh, 32><<<Nn / 32, 256>>>(x, Ff, g1w1 + Ff * Hh, g1b1, Q, Nn, 0);
    edge_mma_kernel<<<Ee / 128, 256, SM_TOT>>>(src, dst, P, Q,
        wbf + 0 * WN, wbf + 1 * WN, wbf + 2 * WN, wbf + 3 * WN, g1b2, g1b3, agg);
    relu_ln_kernel<<<Nn, 256>>>(agg, ln1g, ln1b, xc);

    // ---- GNN layer 2 ----
    gemm_tiled<Hh, 32><<<Nn / 32, 256>>>(xc, Hh, g2w1, nullptr, P, Nn, 0);
    gemm_tiled<Hh, 32><<<Nn / 32, 256>>>(xc, Hh, g2w1 + Hh * Hh, g2b1, Q, Nn, 0);
    zero_kernel<<<(NH + ZB - 1) / ZB, ZB>>>(agg, NH);
    edge_mma_kernel<<<Ee / 128, 256, SM_TOT>>>(src, dst, P, Q,
        wbf + 4 * WN, wbf + 5 * WN, wbf + 6 * WN, wbf + 7 * WN, g2b2, g2b3, agg);
    relu_ln_kernel<<<Nn, 256>>>(agg, ln2g, ln2b, xc);

    // ---- assignment ----
    gemm_tiled<Hh, 32><<<Nn / 32, 256>>>(xc, Hh, aw1, ab1, P, Nn, 1);
    assign_kernel<<<Nn / 8, 256>>>(P, aw2, ab2, u, out_s, entsum, colsum);

    // ---- pooling ----
    bstart_kernel<<<1, 32>>>(batch, bstart);
    {
        dim3 grid(Bb, 8);
        pool_kernel<<<grid, 256>>>(xc, out_s, bstart, pooled);
    }

    // ---- output MLP ----
    gemm_tiled<Hh, 32><<<(Bb * Ss) / 32, 256>>>(pooled, Hh, ow1, ob1, t2, Bb * Ss, 1);
    gemm_tiled<Ll, 32><<<(Bb * Ss) / 32, 256>>>(t2, Hh, ow2, ob2, out_latent, Bb * Ss, 0);

    // ---- loss scalar ----
    finalize_kernel<<<1, 32>>>(colsum, entsum, out_loss);
}

// round 7
// speedup vs baseline: 1.8450x; 1.0363x over previous
#include <cuda_runtime.h>
#include <cuda_bf16.h>
#include <math.h>
#include <stdint.h>

#define Nn 20000
#define Ee 320000
#define Ff 64
#define Hh 256
#define Ss 32
#define Ll 128
#define Bb 16
#define EPS_F 1e-9f

// ---------------- scratch (device globals; no allocation allowed) ----------------
__device__ float d_P[Nn * Hh];
__device__ float d_Q[Nn * Hh];
__device__ float d_agg[Nn * Hh];
__device__ float d_x[Nn * Hh];
__device__ float d_pooled[Bb * Ss * Hh];
__device__ float d_t2[Bb * Ss * Hh];
__device__ float d_colsum[Ss];
__device__ float d_entsum[1];
__device__ int   d_bstart[Bb + 1];
__device__ __align__(256) __nv_bfloat16 d_wbf[8 * Hh * Hh]; // [w2hi,w2lo,w3hi,w3lo] x 2 layers

// ================= warp-MMA helpers (sm_80-compatible PTX) =================
__device__ __forceinline__ uint32_t smem_u32(const void* p) {
    uint32_t a;
    asm("{ .reg .u64 t; cvta.to.shared.u64 t, %1; cvt.u32.u64 %0, t; }" : "=r"(a) : "l"(p));
    return a;
}
__device__ __forceinline__ void cp16(uint32_t saddr, const void* g) {
    asm volatile("cp.async.cg.shared.global [%0], [%1], 16;" :: "r"(saddr), "l"(g));
}
#define CP_COMMIT() asm volatile("cp.async.commit_group;" ::: "memory")
#define CP_WAIT1()  asm volatile("cp.async.wait_group 1;" ::: "memory")
#define CP_WAIT0()  asm volatile("cp.async.wait_group 0;" ::: "memory")

#define LDSM4(r0, r1, r2, r3, addr) \
    asm volatile("ldmatrix.sync.aligned.m8n8.x4.shared.b16 {%0,%1,%2,%3}, [%4];" \
        : "=r"(r0), "=r"(r1), "=r"(r2), "=r"(r3) : "r"(addr))

__device__ __forceinline__ void mma16816(float* c,
    uint32_t a0, uint32_t a1, uint32_t a2, uint32_t a3, uint32_t b0, uint32_t b1) {
    asm volatile("mma.sync.aligned.m16n8k16.row.col.f32.bf16.bf16.f32 "
        "{%0,%1,%2,%3}, {%4,%5,%6,%7}, {%8,%9}, {%0,%1,%2,%3};"
        : "+f"(c[0]), "+f"(c[1]), "+f"(c[2]), "+f"(c[3])
        : "r"(a0), "r"(a1), "r"(a2), "r"(a3), "r"(b0), "r"(b1));
}

// ================= SMEM layout for edge kernel (bytes) =================
#define AROW    528                      // 256 bf16 + 16B pad (conflict-free ldmatrix)
#define SM_AHI  0
#define SM_ALO  (128 * AROW)             // 67584
#define SM_BBUF (2 * 128 * AROW)         // 135168 : 2 x (8KB hi + 8KB lo)
#define SM_IDS  (SM_BBUF + 32768)        // 167936 : sdst[128], ssrc[128]
#define SM_B2   (SM_IDS + 1024)          // 168960
#define SM_B3   (SM_B2 + 1024)           // 169984
#define SM_TOT  (SM_B3 + 1024)           // 171008

// ---------------- weight transpose + bf16 split ----------------
__global__ void wsplit_kernel(const float* __restrict__ w,
                              __nv_bfloat16* __restrict__ hi, __nv_bfloat16* __restrict__ lo) {
    int i = blockIdx.x * 256 + threadIdx.x;   // i = n*256 + k
    int n = i >> 8, k = i & 255;
    float v = w[k * Hh + n];
    __nv_bfloat16 h = __float2bfloat16(v);
    hi[i] = h;
    lo[i] = __float2bfloat16(v - __bfloat162float(h));
}

// ---------------- B-slice loader: 16 k-rows x 256 n, hi+lo, xor-swizzled ----------------
__device__ __forceinline__ void load_slice(int s, uint32_t sb, int t,
    const __nv_bfloat16* w2hi, const __nv_bfloat16* w2lo,
    const __nv_bfloat16* w3hi, const __nv_bfloat16* w3lo)
{
    const __nv_bfloat16* Wh = (s < 16) ? w2hi : w3hi;
    const __nv_bfloat16* Wl = (s < 16) ? w2lo : w3lo;
    const int kt = s & 15;
    const uint32_t base = sb + SM_BBUF + (uint32_t)(s & 1) * 16384u;
    const int n = t;                                  // 256 threads -> 256 n-rows
    const char* gh = (const char*)(Wh + (size_t)n * Hh + kt * 16);
    const char* gl = (const char*)(Wl + (size_t)n * Hh + kt * 16);
    const uint32_t sw4 = (n & 4) ? 16u : 0u;
    const uint32_t doff = base + (uint32_t)n * 32u;
    cp16(doff + (0u ^ sw4), gh);
    cp16(doff + (16u ^ sw4), gh + 16);
    cp16(doff + 8192u + (0u ^ sw4), gl);
    cp16(doff + 8192u + (16u ^ sw4), gl + 16);
}

// ---------------- fused tensor-core edge MLP (warp mma.sync, 64x64 warp tiles) ----------------
__global__ __launch_bounds__(256, 1) void edge_mma_kernel(
    const int* __restrict__ src, const int* __restrict__ dst,
    const float* __restrict__ P, const float* __restrict__ Q,
    const __nv_bfloat16* __restrict__ w2hi, const __nv_bfloat16* __restrict__ w2lo,
    const __nv_bfloat16* __restrict__ w3hi, const __nv_bfloat16* __restrict__ w3lo,
    const float* __restrict__ b2, const float* __restrict__ b3,
    float* __restrict__ agg)
{
    extern __shared__ char sm[];
    const uint32_t sb = smem_u32(sm);
    const int t = threadIdx.x;
    const int w = t >> 5, l = t & 31;
    const int wm = w & 1;        // row half: rows [64*wm, 64*wm+64)
    const int wn = w >> 1;       // col quarter: cols [64*wn, 64*wn+64)

    int* sdst = (int*)(sm + SM_IDS);
    int* ssrc = sdst + 128;
    float* sb2 = (float*)(sm + SM_B2);
    float* sb3 = (float*)(sm + SM_B3);

    if (t < 128) {
        sdst[t] = dst[blockIdx.x * 128 + t];
        ssrc[t] = src[blockIdx.x * 128 + t];
    }
    sb2[t] = b2[t];
    sb3[t] = b3[t];
    __syncthreads();

    // ---- build A = split(relu(P[dst] + Q[src])) : 2 threads per edge row ----
    {
        const int e = t & 127, h = t >> 7;
        const int de = sdst[e], se = ssrc[e];
        const float4* Pr = reinterpret_cast<const float4*>(P) + (size_t)de * 64 + h * 32;
        const float4* Qr = reinterpret_cast<const float4*>(Q) + (size_t)se * 64 + h * 32;
        const uint32_t arow = (uint32_t)e * AROW + (uint32_t)h * 256u;
#pragma unroll
        for (int j = 0; j < 16; j++) {
            float4 p0 = Pr[2 * j], q0 = Qr[2 * j];
            float4 p1 = Pr[2 * j + 1], q1 = Qr[2 * j + 1];
            float v[8] = { p0.x + q0.x, p0.y + q0.y, p0.z + q0.z, p0.w + q0.w,
                           p1.x + q1.x, p1.y + q1.y, p1.z + q1.z, p1.w + q1.w };
            union { uint4 u; __nv_bfloat162 h2[4]; } HI, LO;
#pragma unroll
            for (int p = 0; p < 4; p++) {
                float v0 = fmaxf(v[p * 2], 0.f), v1 = fmaxf(v[p * 2 + 1], 0.f);
                __nv_bfloat16 h0 = __float2bfloat16(v0), h1 = __float2bfloat16(v1);
                HI.h2[p] = __halves2bfloat162(h0, h1);
                LO.h2[p] = __floats2bfloat162_rn(v0 - __bfloat162float(h0),
                                                 v1 - __bfloat162float(h1));
            }
            *(uint4*)(sm + SM_AHI + arow + j * 16) = HI.u;
            *(uint4*)(sm + SM_ALO + arow + j * 16) = LO.u;
        }
    }

    // ---- accumulators: warp owns 64 rows x 64 cols : acc[mi][nj][4] ----
    float acc[4][8][4];
#pragma unroll
    for (int mi = 0; mi < 4; mi++)
#pragma unroll
        for (int nj = 0; nj < 8; nj++) {
            acc[mi][nj][0] = 0.f; acc[mi][nj][1] = 0.f;
            acc[mi][nj][2] = 0.f; acc[mi][nj][3] = 0.f;
        }

    // per-lane ldmatrix offsets
    // A: per m-tile mi, rows 64*wm + 16*mi + (l%16), 16B half (l/16)
    const uint32_t a_base = sb + (uint32_t)((64 * wm + (l % 16)) * AROW + (l / 16) * 16);
    // B: within a 16-col chunk: lane(l%16) -> n-row, halves swizzled
    const uint32_t b_off = (uint32_t)((l % 16) * 32) +
                           (uint32_t)(((l / 16) * 16) ^ (((l % 16) & 4) ? 16 : 0));

    load_slice(0, sb, t, w2hi, w2lo, w3hi, w3lo); CP_COMMIT();
    load_slice(1, sb, t, w2hi, w2lo, w3hi, w3lo); CP_COMMIT();

#pragma unroll 1
    for (int s = 0; s < 32; s++) {
        if (s < 30) { CP_WAIT1(); } else { CP_WAIT0(); }
        __syncthreads();

        const int kt = s & 15;
        // load A fragments: 4 m-tiles, hi+lo
        uint32_t ah[4][4], al[4][4];
#pragma unroll
        for (int mi = 0; mi < 4; mi++) {
            const uint32_t aa = a_base + (uint32_t)(16 * mi * AROW) + kt * 32;
            LDSM4(ah[mi][0], ah[mi][1], ah[mi][2], ah[mi][3], aa + SM_AHI);
            LDSM4(al[mi][0], al[mi][1], al[mi][2], al[mi][3], aa + SM_ALO);
        }

        const uint32_t bbase = sb + SM_BBUF + (uint32_t)(s & 1) * 16384u + b_off
                             + (uint32_t)(wn * 2048);   // 4 chunks x 512B per wn
#pragma unroll
        for (int c = 0; c < 4; c++) {
            uint32_t bh0, bh1, bh2, bh3, bl0, bl1, bl2, bl3;
            LDSM4(bh0, bh1, bh2, bh3, bbase + c * 512);
            LDSM4(bl0, bl1, bl2, bl3, bbase + 8192 + c * 512);
#pragma unroll
            for (int mi = 0; mi < 4; mi++) {
                float* c0 = acc[mi][2 * c];
                float* c1 = acc[mi][2 * c + 1];
                mma16816(c0, ah[mi][0], ah[mi][1], ah[mi][2], ah[mi][3], bh0, bh2);
                mma16816(c0, ah[mi][0], ah[mi][1], ah[mi][2], ah[mi][3], bl0, bl2);
                mma16816(c0, al[mi][0], al[mi][1], al[mi][2], al[mi][3], bh0, bh2);
                mma16816(c1, ah[mi][0], ah[mi][1], ah[mi][2], ah[mi][3], bh1, bh3);
                mma16816(c1, ah[mi][0], ah[mi][1], ah[mi][2], ah[mi][3], bl1, bl3);
                mma16816(c1, al[mi][0], al[mi][1], al[mi][2], al[mi][3], bh1, bh3);
            }
        }

        if (s == 15) {
            // all warps must finish reading A (slice-15 frags) before overwrite
            __syncthreads();
            // ---- epilogue 1: A := split(relu(D1 + b2)) for this warp's 64x64 tile ----
            const int cb = (l % 4) * 2;
#pragma unroll
            for (int mi = 0; mi < 4; mi++) {
                const int r0 = 64 * wm + 16 * mi + l / 4;
#pragma unroll
                for (int nj = 0; nj < 8; nj++) {
                    const int cn = 64 * wn + 8 * nj + cb;
                    const float bz0 = sb2[cn], bz1 = sb2[cn + 1];
                    float v0 = fmaxf(acc[mi][nj][0] + bz0, 0.f);
                    float v1 = fmaxf(acc[mi][nj][1] + bz1, 0.f);
                    float v2 = fmaxf(acc[mi][nj][2] + bz0, 0.f);
                    float v3 = fmaxf(acc[mi][nj][3] + bz1, 0.f);
                    __nv_bfloat16 h0 = __float2bfloat16(v0), h1 = __float2bfloat16(v1);
                    __nv_bfloat16 h2 = __float2bfloat16(v2), h3 = __float2bfloat16(v3);
                    __nv_bfloat162 hp0 = __halves2bfloat162(h0, h1);
                    __nv_bfloat162 hp1 = __halves2bfloat162(h2, h3);
                    __nv_bfloat162 lp0 = __floats2bfloat162_rn(v0 - __bfloat162float(h0),
                                                               v1 - __bfloat162float(h1));
                    __nv_bfloat162 lp1 = __floats2bfloat162_rn(v2 - __bfloat162float(h2),
                                                               v3 - __bfloat162float(h3));
                    *(uint32_t*)(sm + SM_AHI + r0 * AROW + cn * 2)       = *(uint32_t*)&hp0;
                    *(uint32_t*)(sm + SM_AHI + (r0 + 8) * AROW + cn * 2) = *(uint32_t*)&hp1;
                    *(uint32_t*)(sm + SM_ALO + r0 * AROW + cn * 2)       = *(uint32_t*)&lp0;
                    *(uint32_t*)(sm + SM_ALO + (r0 + 8) * AROW + cn * 2) = *(uint32_t*)&lp1;
                    acc[mi][nj][0] = 0.f; acc[mi][nj][1] = 0.f;
                    acc[mi][nj][2] = 0.f; acc[mi][nj][3] = 0.f;
                }
            }
        }
        __syncthreads();
        if (s + 2 < 32) {
            load_slice(s + 2, sb, t, w2hi, w2lo, w3hi, w3lo);
            CP_COMMIT();
        }
    }

    // ---- epilogue 2: agg[dst] += D2 + b3 ----
    {
        const int cb = (l % 4) * 2;
#pragma unroll
        for (int mi = 0; mi < 4; mi++) {
            const int er = 64 * wm + 16 * mi + l / 4;
            const int d0 = sdst[er], d1 = sdst[er + 8];
            float* a0 = agg + (size_t)d0 * Hh;
            float* a1 = agg + (size_t)d1 * Hh;
#pragma unroll
            for (int nj = 0; nj < 8; nj++) {
                const int cn = 64 * wn + 8 * nj + cb;
                const float bz0 = sb3[cn], bz1 = sb3[cn + 1];
                atomicAdd(a0 + cn,     acc[mi][nj][0] + bz0);
                atomicAdd(a0 + cn + 1, acc[mi][nj][1] + bz1);
                atomicAdd(a1 + cn,     acc[mi][nj][2] + bz0);
                atomicAdd(a1 + cn + 1, acc[mi][nj][3] + bz1);
            }
        }
    }
}

// ---------------- zero ----------------
__global__ void zero_kernel(float* p, int n) {
    int i = blockIdx.x * blockDim.x + threadIdx.x;
    if (i < n) p[i] = 0.f;
}

// ---------------- generic row-tiled fp32 GEMM ----------------
template <int NCOL, int RPB>
__global__ __launch_bounds__(256) void gemm_tiled(
    const float* __restrict__ A, int K,
    const float* __restrict__ W, const float* __restrict__ bias,
    float* __restrict__ C, int M, int do_relu)
{
    __shared__ float As[RPB * 256];
    const int row0 = blockIdx.x * RPB;
    const int tot = RPB * K;
    for (int idx = threadIdx.x; idx < tot; idx += 256) {
        int r = idx / K, k = idx - r * K;
        int gr = row0 + r;
        As[idx] = (gr < M) ? A[gr * K + k] : 0.f;
    }
    __syncthreads();

    const int RG = 256 / NCOL;
    const int RPT = RPB / RG;
    const int col = threadIdx.x % NCOL;
    const int rg = threadIdx.x / NCOL;

    float acc[RPT];
    float bv = bias ? bias[col] : 0.f;
#pragma unroll
    for (int i = 0; i < RPT; i++) acc[i] = bv;

    for (int k = 0; k < K; k += 4) {
        float wv0 = W[(k + 0) * NCOL + col];
        float wv1 = W[(k + 1) * NCOL + col];
        float wv2 = W[(k + 2) * NCOL + col];
        float wv3 = W[(k + 3) * NCOL + col];
#pragma unroll
        for (int i = 0; i < RPT; i++) {
            const float4 a = *(const float4*)&As[(rg + i * RG) * K + k];
            acc[i] = fmaf(a.x, wv0, acc[i]);
            acc[i] = fmaf(a.y, wv1, acc[i]);
            acc[i] = fmaf(a.z, wv2, acc[i]);
            acc[i] = fmaf(a.w, wv3, acc[i]);
        }
    }
#pragma unroll
    for (int i = 0; i < RPT; i++) {
        int gr = row0 + rg + i * RG;
        if (gr < M) {
            float v = acc[i];
            if (do_relu) v = fmaxf(v, 0.f);
            C[gr * NCOL + col] = v;
        }
    }
}

// ---------------- relu + layernorm per node ----------------
__device__ __forceinline__ float warp_sum(float v) {
#pragma unroll
    for (int o = 16; o > 0; o >>= 1) v += __shfl_xor_sync(0xFFFFFFFFu, v, o);
    return v;
}

__global__ __launch_bounds__(256) void relu_ln_kernel(
    const float* __restrict__ agg, const float* __restrict__ g,
    const float* __restrict__ b, float* __restrict__ xout)
{
    const int n = blockIdx.x;
    const int j = threadIdx.x;
    const int lane = j & 31, warp = j >> 5;
    __shared__ float red[8];
    __shared__ float s_mu, s_rstd;

    float v = fmaxf(agg[n * Hh + j], 0.f);
    float t = warp_sum(v);
    if (lane == 0) red[warp] = t;
    __syncthreads();
    if (j == 0) {
        float s = 0.f;
#pragma unroll
        for (int i = 0; i < 8; i++) s += red[i];
        s_mu = s / (float)Hh;
    }
    __syncthreads();
    float d = v - s_mu;
    float t2 = warp_sum(d * d);
    if (lane == 0) red[warp] = t2;
    __syncthreads();
    if (j == 0) {
        float s = 0.f;
#pragma unroll
        for (int i = 0; i < 8; i++) s += red[i];
        s_rstd = rsqrtf(s / (float)Hh + 1e-5f);
    }
    __syncthreads();
    xout[n * Hh + j] = d * s_rstd * g[j] + b[j];
}

// ---------------- assignment ----------------
__global__ __launch_bounds__(256) void assign_kernel(
    const float* __restrict__ t1, const float* __restrict__ aw2,
    const float* __restrict__ ab2, const float* __restrict__ u,
    float* __restrict__ s_out, float* __restrict__ entsum, float* __restrict__ colsum)
{
    __shared__ float rows[8 * Hh];
    __shared__ float blk_col[Ss];
    __shared__ float blk_ent;

    const int lane = threadIdx.x & 31, warp = threadIdx.x >> 5;
    if (threadIdx.x < Ss) blk_col[threadIdx.x] = 0.f;
    if (threadIdx.x == 0) blk_ent = 0.f;
    const int n0 = blockIdx.x * 8;
    for (int idx = threadIdx.x; idx < 8 * Hh; idx += 256)
        rows[idx] = t1[n0 * Hh + idx];
    __syncthreads();

    const int n = n0 + warp;
    float acc = ab2[lane];
    for (int k = 0; k < Hh; k += 4) {
        const float4 a = *(const float4*)&rows[warp * Hh + k];
        acc = fmaf(a.x, aw2[(k + 0) * Ss + lane], acc);
        acc = fmaf(a.y, aw2[(k + 1) * Ss + lane], acc);
        acc = fmaf(a.z, aw2[(k + 2) * Ss + lane], acc);
        acc = fmaf(a.w, aw2[(k + 3) * Ss + lane], acc);
    }
    float uu = u[n * Ss + lane];
    float gmb = -logf(-logf(uu + EPS_F) + EPS_F);
    float z = acc + gmb;
    float m = z;
#pragma unroll
    for (int o = 16; o > 0; o >>= 1) m = fmaxf(m, __shfl_xor_sync(0xFFFFFFFFu, m, o));
    float p = expf(z - m);
    float sum = warp_sum(p);
    float sv = p / sum;
    s_out[n * Ss + lane] = sv;

    float ent = warp_sum(sv * logf(sv + EPS_F));
    if (lane == 0) atomicAdd(&blk_ent, ent);
    atomicAdd(&blk_col[lane], sv);
    __syncthreads();
    if (threadIdx.x == 0) atomicAdd(entsum, blk_ent);
    if (threadIdx.x < Ss) atomicAdd(&colsum[threadIdx.x], blk_col[threadIdx.x]);
}

// ---------------- batch segment starts ----------------
__global__ void bstart_kernel(const int* __restrict__ batch, int* __restrict__ bstart) {
    int b = threadIdx.x;
    if (b > Bb) return;
    if (b == Bb) { bstart[Bb] = Nn; return; }
    int lo = 0, hi = Nn;
    while (lo < hi) {
        int mid = (lo + hi) >> 1;
        if (batch[mid] < b) lo = mid + 1; else hi = mid;
    }
    bstart[b] = lo;
}

// ---------------- pooling ----------------
__global__ __launch_bounds__(256) void pool_kernel(
    const float* __restrict__ x, const float* __restrict__ s_out,
    const int* __restrict__ bstart, float* __restrict__ pooled)
{
    const int b = blockIdx.x;
    const int chunk = blockIdx.y;
    const int NCHUNK = gridDim.y;
    const int lo = bstart[b], hi = bstart[b + 1];
    const int cnt = hi - lo;
    const int c0 = lo + (int)(((long long)cnt * chunk) / NCHUNK);
    const int c1 = lo + (int)(((long long)cnt * (chunk + 1)) / NCHUNK);

    __shared__ float ss[Ss];
    const int t = threadIdx.x;
    float acc[Ss];
#pragma unroll
    for (int sl = 0; sl < Ss; sl++) acc[sl] = 0.f;

    for (int n = c0; n < c1; n++) {
        __syncthreads();
        if (t < Ss) ss[t] = s_out[n * Ss + t];
        __syncthreads();
        float xv = x[n * Hh + t];
#pragma unroll
        for (int sl = 0; sl < Ss; sl++) acc[sl] = fmaf(xv, ss[sl], acc[sl]);
    }
#pragma unroll
    for (int sl = 0; sl < Ss; sl++)
        atomicAdd(&pooled[(b * Ss + sl) * Hh + t], acc[sl]);
}

// ---------------- final scalar loss ----------------
__global__ void finalize_kernel(const float* __restrict__ colsum,
                                const float* __restrict__ entsum,
                                float* __restrict__ out_loss)
{
    int l = threadIdx.x;
    float avg = colsum[l] / (float)Nn;
    float dv = avg * logf(avg + EPS_F);
    dv = warp_sum(dv);
    if (l == 0) {
        float entropy = -(entsum[0] / (float)Nn);
        out_loss[0] = entropy + dv;
    }
}

// ---------------- launch ----------------
extern "C" void kernel_launch(void* const* d_in, const int* in_sizes, int n_in,
                              void* d_out, int out_size)
{
    const float* x    = (const float*)d_in[0];
    const float* u    = (const float*)d_in[1];
    const int* eidx   = (const int*)d_in[2];
    const int* batch  = (const int*)d_in[3];
    const float* g1w1 = (const float*)d_in[4];
    const float* g1b1 = (const float*)d_in[5];
    const float* g1w2 = (const float*)d_in[6];
    const float* g1b2 = (const float*)d_in[7];
    const float* g1w3 = (const float*)d_in[8];
    const float* g1b3 = (const float*)d_in[9];
    const float* ln1g = (const float*)d_in[10];
    const float* ln1b = (const float*)d_in[11];
    const float* g2w1 = (const float*)d_in[12];
    const float* g2b1 = (const float*)d_in[13];
    const float* g2w2 = (const float*)d_in[14];
    const float* g2b2 = (const float*)d_in[15];
    const float* g2w3 = (const float*)d_in[16];
    const float* g2b3 = (const float*)d_in[17];
    const float* ln2g = (const float*)d_in[18];
    const float* ln2b = (const float*)d_in[19];
    const float* aw1  = (const float*)d_in[20];
    const float* ab1  = (const float*)d_in[21];
    const float* aw2  = (const float*)d_in[22];
    const float* ab2  = (const float*)d_in[23];
    const float* ow1  = (const float*)d_in[24];
    const float* ob1  = (const float*)d_in[25];
    const float* ow2  = (const float*)d_in[26];
    const float* ob2  = (const float*)d_in[27];

    const int* src = eidx;
    const int* dst = eidx + Ee;

    float* out = (float*)d_out;
    float* out_latent = out;
    float* out_s = out + Bb * Ss * Ll;
    float* out_loss = out + Bb * Ss * Ll + Nn * Ss;

    float *P, *Q, *agg, *xc, *pooled, *t2, *colsum, *entsum;
    int* bstart;
    __nv_bfloat16* wbf;
    cudaGetSymbolAddress((void**)&P, d_P);
    cudaGetSymbolAddress((void**)&Q, d_Q);
    cudaGetSymbolAddress((void**)&agg, d_agg);
    cudaGetSymbolAddress((void**)&xc, d_x);
    cudaGetSymbolAddress((void**)&pooled, d_pooled);
    cudaGetSymbolAddress((void**)&t2, d_t2);
    cudaGetSymbolAddress((void**)&colsum, d_colsum);
    cudaGetSymbolAddress((void**)&entsum, d_entsum);
    cudaGetSymbolAddress((void**)&bstart, d_bstart);
    cudaGetSymbolAddress((void**)&wbf, d_wbf);

    cudaFuncSetAttribute(edge_mma_kernel, cudaFuncAttributeMaxDynamicSharedMemorySize, SM_TOT);

    const int NH = Nn * Hh;
    const int ZB = 256;
    const int WN = Hh * Hh;   // 65536

    // ---- zero accumulators ----
    zero_kernel<<<(NH + ZB - 1) / ZB, ZB>>>(agg, NH);
    zero_kernel<<<(Bb * Ss * Hh + ZB - 1) / ZB, ZB>>>(pooled, Bb * Ss * Hh);
    zero_kernel<<<1, ZB>>>(colsum, Ss);
    zero_kernel<<<1, ZB>>>(entsum, 1);

    // ---- transpose + split weights to bf16 hi/lo ([n][k] layout) ----
    wsplit_kernel<<<256, 256>>>(g1w2, wbf + 0 * WN, wbf + 1 * WN);
    wsplit_kernel<<<256, 256>>>(g1w3, wbf + 2 * WN, wbf + 3 * WN);
    wsplit_kernel<<<256, 256>>>(g2w2, wbf + 4 * WN, wbf + 5 * WN);
    wsplit_kernel<<<256, 256>>>(g2w3, wbf + 6 * WN, wbf + 7 * WN);

    // ---- GNN layer 1 ----
    gemm_tiled<Hh, 32><<<Nn / 32, 256>>>(x, Ff, g1w1, nullptr, P, Nn, 0);
    gemm_tiled<Hh, 32><<<Nn / 32, 256>>>(x, Ff, g1w1 + Ff * Hh, g1b1, Q, Nn, 0);
    edge_mma_kernel<<<Ee / 128, 256, SM_TOT>>>(src, dst, P, Q,
        wbf + 0 * WN, wbf + 1 * WN, wbf + 2 * WN, wbf + 3 * WN, g1b2, g1b3, agg);
    relu_ln_kernel<<<Nn, 256>>>(agg, ln1g, ln1b, xc);

    // ---- GNN layer 2 ----
    gemm_tiled<Hh, 32><<<Nn / 32, 256>>>(xc, Hh, g2w1, nullptr, P, Nn, 0);
    gemm_tiled<Hh, 32><<<Nn / 32, 256>>>(xc, Hh, g2w1 + Hh * Hh, g2b1, Q, Nn, 0);
    zero_kernel<<<(NH + ZB - 1) / ZB, ZB>>>(agg, NH);
    edge_mma_kernel<<<Ee / 128, 256, SM_TOT>>>(src, dst, P, Q,
        wbf + 4 * WN, wbf + 5 * WN, wbf + 6 * WN, wbf + 7 * WN, g2b2, g2b3, agg);
    relu_ln_kernel<<<Nn, 256>>>(agg, ln2g, ln2b, xc);

    // ---- assignment ----
    gemm_tiled<Hh, 32><<<Nn / 32, 256>>>(xc, Hh, aw1, ab1, P, Nn, 1);
    assign_kernel<<<Nn / 8, 256>>>(P, aw2, ab2, u, out_s, entsum, colsum);

    // ---- pooling ----
    bstart_kernel<<<1, 32>>>(batch, bstart);
    {
        dim3 grid(Bb, 8);
        pool_kernel<<<grid, 256>>>(xc, out_s, bstart, pooled);
    }

    // ---- output MLP ----
    gemm_tiled<Hh, 32><<<(Bb * Ss) / 32, 256>>>(pooled, Hh, ow1, ob1, t2, Bb * Ss, 1);
    gemm_tiled<Ll, 32><<<(Bb * Ss) / 32, 256>>>(t2, Hh, ow2, ob2, out_latent, Bb * Ss, 0);

    // ---- loss scalar ----
    finalize_kernel<<<1, 32>>>(colsum, entsum, out_loss);
}

// round 8
// speedup vs baseline: 2.0084x; 1.0886x over previous
#include <cuda_runtime.h>
#include <cuda_bf16.h>
#include <math.h>
#include <stdint.h>

#define Nn 20000
#define Ee 320000
#define Ff 64
#define Hh 256
#define Ss 32
#define Ll 128
#define Bb 16
#define EPS_F 1e-9f

// ---------------- scratch (device globals; no allocation allowed) ----------------
__device__ float d_P[Nn * Hh];
__device__ float d_Q[Nn * Hh];
__device__ float d_agg[Nn * Hh];
__device__ float d_x[Nn * Hh];
__device__ float d_pooled[Bb * Ss * Hh];
__device__ float d_t2[Bb * Ss * Hh];
__device__ float d_colsum[Ss];
__device__ float d_entsum[1];
__device__ int   d_bstart[Bb + 1];
__device__ __align__(256) __nv_bfloat16 d_wbf[8 * Hh * Hh]; // [w2hi,w2lo,w3hi,w3lo] x 2 layers

// ================= warp-MMA helpers (sm_80-compatible PTX) =================
__device__ __forceinline__ uint32_t smem_u32(const void* p) {
    uint32_t a;
    asm("{ .reg .u64 t; cvta.to.shared.u64 t, %1; cvt.u32.u64 %0, t; }" : "=r"(a) : "l"(p));
    return a;
}
__device__ __forceinline__ void cp16(uint32_t saddr, const void* g) {
    asm volatile("cp.async.cg.shared.global [%0], [%1], 16;" :: "r"(saddr), "l"(g));
}
#define CP_COMMIT() asm volatile("cp.async.commit_group;" ::: "memory")
#define CP_WAIT1()  asm volatile("cp.async.wait_group 1;" ::: "memory")
#define CP_WAIT0()  asm volatile("cp.async.wait_group 0;" ::: "memory")

#define LDSM4(r0, r1, r2, r3, addr) \
    asm volatile("ldmatrix.sync.aligned.m8n8.x4.shared.b16 {%0,%1,%2,%3}, [%4];" \
        : "=r"(r0), "=r"(r1), "=r"(r2), "=r"(r3) : "r"(addr))

__device__ __forceinline__ void mma16816(float* c,
    uint32_t a0, uint32_t a1, uint32_t a2, uint32_t a3, uint32_t b0, uint32_t b1) {
    asm volatile("mma.sync.aligned.m16n8k16.row.col.f32.bf16.bf16.f32 "
        "{%0,%1,%2,%3}, {%4,%5,%6,%7}, {%8,%9}, {%0,%1,%2,%3};"
        : "+f"(c[0]), "+f"(c[1]), "+f"(c[2]), "+f"(c[3])
        : "r"(a0), "r"(a1), "r"(a2), "r"(a3), "r"(b0), "r"(b1));
}

// ================= SMEM layout for edge kernel (bytes) =================
#define AROW    528                      // 256 bf16 + 16B pad (conflict-free ldmatrix)
#define SM_AHI  0
#define SM_ALO  (128 * AROW)             // 67584
#define SM_BBUF (2 * 128 * AROW)         // 135168 : 2 x (8KB hi + 8KB lo)
#define SM_IDS  (SM_BBUF + 32768)        // 167936 : sdst[128], ssrc[128]
#define SM_B2   (SM_IDS + 1024)          // 168960
#define SM_B3   (SM_B2 + 1024)           // 169984
#define SM_TOT  (SM_B3 + 1024)           // 171008

// ---------------- weight transpose + bf16 split ----------------
__global__ void wsplit_kernel(const float* __restrict__ w,
                              __nv_bfloat16* __restrict__ hi, __nv_bfloat16* __restrict__ lo) {
    int i = blockIdx.x * 256 + threadIdx.x;   // i = n*256 + k
    int n = i >> 8, k = i & 255;
    float v = w[k * Hh + n];
    __nv_bfloat16 h = __float2bfloat16(v);
    hi[i] = h;
    lo[i] = __float2bfloat16(v - __bfloat162float(h));
}

// ---------------- B-slice loader: 16 k-rows x 256 n, hi+lo, xor-swizzled (512 thr) ----------------
__device__ __forceinline__ void load_slice(int s, uint32_t sb, int t,
    const __nv_bfloat16* w2hi, const __nv_bfloat16* w2lo,
    const __nv_bfloat16* w3hi, const __nv_bfloat16* w3lo)
{
    const __nv_bfloat16* Wh = (s < 16) ? w2hi : w3hi;
    const __nv_bfloat16* Wl = (s < 16) ? w2lo : w3lo;
    const int kt = s & 15;
    const uint32_t base = sb + SM_BBUF + (uint32_t)(s & 1) * 16384u;
    const int n = t >> 1;                 // 512 threads -> 256 n-rows, 2 thr each
    const int h = t & 1;                  // 16B half
    const char* gh = (const char*)(Wh + (size_t)n * Hh + kt * 16) + h * 16;
    const char* gl = (const char*)(Wl + (size_t)n * Hh + kt * 16) + h * 16;
    const uint32_t sw4 = (n & 4) ? 16u : 0u;
    const uint32_t doff = base + (uint32_t)n * 32u + (((uint32_t)h * 16u) ^ sw4);
    cp16(doff, gh);
    cp16(doff + 8192u, gl);
}

// ---------------- fused tensor-core edge MLP (16 warps, 32x64 warp tiles) ----------------
__global__ __launch_bounds__(512, 1) void edge_mma_kernel(
    const int* __restrict__ src, const int* __restrict__ dst,
    const float* __restrict__ P, const float* __restrict__ Q,
    const __nv_bfloat16* __restrict__ w2hi, const __nv_bfloat16* __restrict__ w2lo,
    const __nv_bfloat16* __restrict__ w3hi, const __nv_bfloat16* __restrict__ w3lo,
    const float* __restrict__ b2, const float* __restrict__ b3,
    float* __restrict__ agg)
{
    extern __shared__ char sm[];
    const uint32_t sb = smem_u32(sm);
    const int t = threadIdx.x;
    const int w = t >> 5, l = t & 31;
    const int wm = w & 3;        // row quarter: rows [32*wm, 32*wm+32)
    const int wn = w >> 2;       // col quarter: cols [64*wn, 64*wn+64)

    int* sdst = (int*)(sm + SM_IDS);
    int* ssrc = sdst + 128;
    float* sb2 = (float*)(sm + SM_B2);
    float* sb3 = (float*)(sm + SM_B3);

    if (t < 128) {
        sdst[t] = dst[blockIdx.x * 128 + t];
        ssrc[t] = src[blockIdx.x * 128 + t];
    }
    if (t < 256) {
        sb2[t] = b2[t];
        sb3[t] = b3[t];
    }
    __syncthreads();

    // ---- build A = split(relu(P[dst] + Q[src])) : 4 threads per edge row ----
    {
        const int e = t & 127, h = t >> 7;        // h in 0..3, 64 cols each
        const int de = sdst[e], se = ssrc[e];
        const float4* Pr = reinterpret_cast<const float4*>(P) + (size_t)de * 64 + h * 16;
        const float4* Qr = reinterpret_cast<const float4*>(Q) + (size_t)se * 64 + h * 16;
        const uint32_t arow = (uint32_t)e * AROW + (uint32_t)h * 128u;
#pragma unroll
        for (int j = 0; j < 8; j++) {
            float4 p0 = Pr[2 * j], q0 = Qr[2 * j];
            float4 p1 = Pr[2 * j + 1], q1 = Qr[2 * j + 1];
            float v[8] = { p0.x + q0.x, p0.y + q0.y, p0.z + q0.z, p0.w + q0.w,
                           p1.x + q1.x, p1.y + q1.y, p1.z + q1.z, p1.w + q1.w };
            union { uint4 u; __nv_bfloat162 h2[4]; } HI, LO;
#pragma unroll
            for (int p = 0; p < 4; p++) {
                float v0 = fmaxf(v[p * 2], 0.f), v1 = fmaxf(v[p * 2 + 1], 0.f);
                __nv_bfloat16 h0 = __float2bfloat16(v0), h1 = __float2bfloat16(v1);
                HI.h2[p] = __halves2bfloat162(h0, h1);
                LO.h2[p] = __floats2bfloat162_rn(v0 - __bfloat162float(h0),
                                                 v1 - __bfloat162float(h1));
            }
            *(uint4*)(sm + SM_AHI + arow + j * 16) = HI.u;
            *(uint4*)(sm + SM_ALO + arow + j * 16) = LO.u;
        }
    }

    // ---- accumulators: warp owns 32 rows x 64 cols : acc[mi][nj][4] ----
    float acc[2][8][4];
#pragma unroll
    for (int mi = 0; mi < 2; mi++)
#pragma unroll
        for (int nj = 0; nj < 8; nj++) {
            acc[mi][nj][0] = 0.f; acc[mi][nj][1] = 0.f;
            acc[mi][nj][2] = 0.f; acc[mi][nj][3] = 0.f;
        }

    // per-lane ldmatrix offsets
    const uint32_t a_base = sb + (uint32_t)((32 * wm + (l % 16)) * AROW + (l / 16) * 16);
    const uint32_t b_off = (uint32_t)((l % 16) * 32) +
                           (uint32_t)(((l / 16) * 16) ^ (((l % 16) & 4) ? 16 : 0));

    load_slice(0, sb, t, w2hi, w2lo, w3hi, w3lo); CP_COMMIT();
    load_slice(1, sb, t, w2hi, w2lo, w3hi, w3lo); CP_COMMIT();

#pragma unroll 1
    for (int s = 0; s < 32; s++) {
        if (s < 30) { CP_WAIT1(); } else { CP_WAIT0(); }
        __syncthreads();

        const int kt = s & 15;
        // load A fragments: 2 m-tiles, hi+lo
        uint32_t ah[2][4], al[2][4];
#pragma unroll
        for (int mi = 0; mi < 2; mi++) {
            const uint32_t aa = a_base + (uint32_t)(16 * mi * AROW) + kt * 32;
            LDSM4(ah[mi][0], ah[mi][1], ah[mi][2], ah[mi][3], aa + SM_AHI);
            LDSM4(al[mi][0], al[mi][1], al[mi][2], al[mi][3], aa + SM_ALO);
        }

        const uint32_t bbase = sb + SM_BBUF + (uint32_t)(s & 1) * 16384u + b_off
                             + (uint32_t)(wn * 2048);   // 4 chunks x 512B per wn
#pragma unroll
        for (int c = 0; c < 4; c++) {
            uint32_t bh0, bh1, bh2, bh3, bl0, bl1, bl2, bl3;
            LDSM4(bh0, bh1, bh2, bh3, bbase + c * 512);
            LDSM4(bl0, bl1, bl2, bl3, bbase + 8192 + c * 512);
#pragma unroll
            for (int mi = 0; mi < 2; mi++) {
                float* c0 = acc[mi][2 * c];
                float* c1 = acc[mi][2 * c + 1];
                mma16816(c0, ah[mi][0], ah[mi][1], ah[mi][2], ah[mi][3], bh0, bh2);
                mma16816(c0, ah[mi][0], ah[mi][1], ah[mi][2], ah[mi][3], bl0, bl2);
                mma16816(c0, al[mi][0], al[mi][1], al[mi][2], al[mi][3], bh0, bh2);
                mma16816(c1, ah[mi][0], ah[mi][1], ah[mi][2], ah[mi][3], bh1, bh3);
                mma16816(c1, ah[mi][0], ah[mi][1], ah[mi][2], ah[mi][3], bl1, bl3);
                mma16816(c1, al[mi][0], al[mi][1], al[mi][2], al[mi][3], bh1, bh3);
            }
        }

        if (s == 15) {
            // all warps must finish reading A (slice-15 frags) before overwrite
            __syncthreads();
            // ---- epilogue 1: A := split(relu(D1 + b2)) for this warp's 32x64 tile ----
            const int cb = (l % 4) * 2;
#pragma unroll
            for (int mi = 0; mi < 2; mi++) {
                const int r0 = 32 * wm + 16 * mi + l / 4;
#pragma unroll
                for (int nj = 0; nj < 8; nj++) {
                    const int cn = 64 * wn + 8 * nj + cb;
                    const float bz0 = sb2[cn], bz1 = sb2[cn + 1];
                    float v0 = fmaxf(acc[mi][nj][0] + bz0, 0.f);
                    float v1 = fmaxf(acc[mi][nj][1] + bz1, 0.f);
                    float v2 = fmaxf(acc[mi][nj][2] + bz0, 0.f);
                    float v3 = fmaxf(acc[mi][nj][3] + bz1, 0.f);
                    __nv_bfloat16 h0 = __float2bfloat16(v0), h1 = __float2bfloat16(v1);
                    __nv_bfloat16 h2 = __float2bfloat16(v2), h3 = __float2bfloat16(v3);
                    __nv_bfloat162 hp0 = __halves2bfloat162(h0, h1);
                    __nv_bfloat162 hp1 = __halves2bfloat162(h2, h3);
                    __nv_bfloat162 lp0 = __floats2bfloat162_rn(v0 - __bfloat162float(h0),
                                                               v1 - __bfloat162float(h1));
                    __nv_bfloat162 lp1 = __floats2bfloat162_rn(v2 - __bfloat162float(h2),
                                                               v3 - __bfloat162float(h3));
                    *(uint32_t*)(sm + SM_AHI + r0 * AROW + cn * 2)       = *(uint32_t*)&hp0;
                    *(uint32_t*)(sm + SM_AHI + (r0 + 8) * AROW + cn * 2) = *(uint32_t*)&hp1;
                    *(uint32_t*)(sm + SM_ALO + r0 * AROW + cn * 2)       = *(uint32_t*)&lp0;
                    *(uint32_t*)(sm + SM_ALO + (r0 + 8) * AROW + cn * 2) = *(uint32_t*)&lp1;
                    acc[mi][nj][0] = 0.f; acc[mi][nj][1] = 0.f;
                    acc[mi][nj][2] = 0.f; acc[mi][nj][3] = 0.f;
                }
            }
        }
        __syncthreads();
        if (s + 2 < 32) {
            load_slice(s + 2, sb, t, w2hi, w2lo, w3hi, w3lo);
            CP_COMMIT();
        }
    }

    // ---- epilogue 2: agg[dst] += D2 + b3 ----
    {
        const int cb = (l % 4) * 2;
#pragma unroll
        for (int mi = 0; mi < 2; mi++) {
            const int er = 32 * wm + 16 * mi + l / 4;
            const int d0 = sdst[er], d1 = sdst[er + 8];
            float* a0 = agg + (size_t)d0 * Hh;
            float* a1 = agg + (size_t)d1 * Hh;
#pragma unroll
            for (int nj = 0; nj < 8; nj++) {
                const int cn = 64 * wn + 8 * nj + cb;
                const float bz0 = sb3[cn], bz1 = sb3[cn + 1];
                atomicAdd(a0 + cn,     acc[mi][nj][0] + bz0);
                atomicAdd(a0 + cn + 1, acc[mi][nj][1] + bz1);
                atomicAdd(a1 + cn,     acc[mi][nj][2] + bz0);
                atomicAdd(a1 + cn + 1, acc[mi][nj][3] + bz1);
            }
        }
    }
}

// ---------------- zero ----------------
__global__ void zero_kernel(float* p, int n) {
    int i = blockIdx.x * blockDim.x + threadIdx.x;
    if (i < n) p[i] = 0.f;
}

// ---------------- generic row-tiled fp32 GEMM ----------------
template <int NCOL, int RPB>
__global__ __launch_bounds__(256) void gemm_tiled(
    const float* __restrict__ A, int K,
    const float* __restrict__ W, const float* __restrict__ bias,
    float* __restrict__ C, int M, int do_relu)
{
    __shared__ float As[RPB * 256];
    const int row0 = blockIdx.x * RPB;
    const int tot = RPB * K;
    for (int idx = threadIdx.x; idx < tot; idx += 256) {
        int r = idx / K, k = idx - r * K;
        int gr = row0 + r;
        As[idx] = (gr < M) ? A[gr * K + k] : 0.f;
    }
    __syncthreads();

    const int RG = 256 / NCOL;
    const int RPT = RPB / RG;
    const int col = threadIdx.x % NCOL;
    const int rg = threadIdx.x / NCOL;

    float acc[RPT];
    float bv = bias ? bias[col] : 0.f;
#pragma unroll
    for (int i = 0; i < RPT; i++) acc[i] = bv;

    for (int k = 0; k < K; k += 4) {
        float wv0 = W[(k + 0) * NCOL + col];
        float wv1 = W[(k + 1) * NCOL + col];
        float wv2 = W[(k + 2) * NCOL + col];
        float wv3 = W[(k + 3) * NCOL + col];
#pragma unroll
        for (int i = 0; i < RPT; i++) {
            const float4 a = *(const float4*)&As[(rg + i * RG) * K + k];
            acc[i] = fmaf(a.x, wv0, acc[i]);
            acc[i] = fmaf(a.y, wv1, acc[i]);
            acc[i] = fmaf(a.z, wv2, acc[i]);
            acc[i] = fmaf(a.w, wv3, acc[i]);
        }
    }
#pragma unroll
    for (int i = 0; i < RPT; i++) {
        int gr = row0 + rg + i * RG;
        if (gr < M) {
            float v = acc[i];
            if (do_relu) v = fmaxf(v, 0.f);
            C[gr * NCOL + col] = v;
        }
    }
}

// ---------------- relu + layernorm per node ----------------
__device__ __forceinline__ float warp_sum(float v) {
#pragma unroll
    for (int o = 16; o > 0; o >>= 1) v += __shfl_xor_sync(0xFFFFFFFFu, v, o);
    return v;
}

__global__ __launch_bounds__(256) void relu_ln_kernel(
    const float* __restrict__ agg, const float* __restrict__ g,
    const float* __restrict__ b, float* __restrict__ xout)
{
    const int n = blockIdx.x;
    const int j = threadIdx.x;
    const int lane = j & 31, warp = j >> 5;
    __shared__ float red[8];
    __shared__ float s_mu, s_rstd;

    float v = fmaxf(agg[n * Hh + j], 0.f);
    float t = warp_sum(v);
    if (lane == 0) red[warp] = t;
    __syncthreads();
    if (j == 0) {
        float s = 0.f;
#pragma unroll
        for (int i = 0; i < 8; i++) s += red[i];
        s_mu = s / (float)Hh;
    }
    __syncthreads();
    float d = v - s_mu;
    float t2 = warp_sum(d * d);
    if (lane == 0) red[warp] = t2;
    __syncthreads();
    if (j == 0) {
        float s = 0.f;
#pragma unroll
        for (int i = 0; i < 8; i++) s += red[i];
        s_rstd = rsqrtf(s / (float)Hh + 1e-5f);
    }
    __syncthreads();
    xout[n * Hh + j] = d * s_rstd * g[j] + b[j];
}

// ---------------- assignment ----------------
__global__ __launch_bounds__(256) void assign_kernel(
    const float* __restrict__ t1, const float* __restrict__ aw2,
    const float* __restrict__ ab2, const float* __restrict__ u,
    float* __restrict__ s_out, float* __restrict__ entsum, float* __restrict__ colsum)
{
    __shared__ float rows[8 * Hh];
    __shared__ float blk_col[Ss];
    __shared__ float blk_ent;

    const int lane = threadIdx.x & 31, warp = threadIdx.x >> 5;
    if (threadIdx.x < Ss) blk_col[threadIdx.x] = 0.f;
    if (threadIdx.x == 0) blk_ent = 0.f;
    const int n0 = blockIdx.x * 8;
    for (int idx = threadIdx.x; idx < 8 * Hh; idx += 256)
        rows[idx] = t1[n0 * Hh + idx];
    __syncthreads();

    const int n = n0 + warp;
    float acc = ab2[lane];
    for (int k = 0; k < Hh; k += 4) {
        const float4 a = *(const float4*)&rows[warp * Hh + k];
        acc = fmaf(a.x, aw2[(k + 0) * Ss + lane], acc);
        acc = fmaf(a.y, aw2[(k + 1) * Ss + lane], acc);
        acc = fmaf(a.z, aw2[(k + 2) * Ss + lane], acc);
        acc = fmaf(a.w, aw2[(k + 3) * Ss + lane], acc);
    }
    float uu = u[n * Ss + lane];
    float gmb = -logf(-logf(uu + EPS_F) + EPS_F);
    float z = acc + gmb;
    float m = z;
#pragma unroll
    for (int o = 16; o > 0; o >>= 1) m = fmaxf(m, __shfl_xor_sync(0xFFFFFFFFu, m, o));
    float p = expf(z - m);
    float sum = warp_sum(p);
    float sv = p / sum;
    s_out[n * Ss + lane] = sv;

    float ent = warp_sum(sv * logf(sv + EPS_F));
    if (lane == 0) atomicAdd(&blk_ent, ent);
    atomicAdd(&blk_col[lane], sv);
    __syncthreads();
    if (threadIdx.x == 0) atomicAdd(entsum, blk_ent);
    if (threadIdx.x < Ss) atomicAdd(&colsum[threadIdx.x], blk_col[threadIdx.x]);
}

// ---------------- batch segment starts ----------------
__global__ void bstart_kernel(const int* __restrict__ batch, int* __restrict__ bstart) {
    int b = threadIdx.x;
    if (b > Bb) return;
    if (b == Bb) { bstart[Bb] = Nn; return; }
    int lo = 0, hi = Nn;
    while (lo < hi) {
        int mid = (lo + hi) >> 1;
        if (batch[mid] < b) lo = mid + 1; else hi = mid;
    }
    bstart[b] = lo;
}

// ---------------- pooling ----------------
__global__ __launch_bounds__(256) void pool_kernel(
    const float* __restrict__ x, const float* __restrict__ s_out,
    const int* __restrict__ bstart, float* __restrict__ pooled)
{
    const int b = blockIdx.x;
    const int chunk = blockIdx.y;
    const int NCHUNK = gridDim.y;
    const int lo = bstart[b], hi = bstart[b + 1];
    const int cnt = hi - lo;
    const int c0 = lo + (int)(((long long)cnt * chunk) / NCHUNK);
    const int c1 = lo + (int)(((long long)cnt * (chunk + 1)) / NCHUNK);

    __shared__ float ss[Ss];
    const int t = threadIdx.x;
    float acc[Ss];
#pragma unroll
    for (int sl = 0; sl < Ss; sl++) acc[sl] = 0.f;

    for (int n = c0; n < c1; n++) {
        __syncthreads();
        if (t < Ss) ss[t] = s_out[n * Ss + t];
        __syncthreads();
        float xv = x[n * Hh + t];
#pragma unroll
        for (int sl = 0; sl < Ss; sl++) acc[sl] = fmaf(xv, ss[sl], acc[sl]);
    }
#pragma unroll
    for (int sl = 0; sl < Ss; sl++)
        atomicAdd(&pooled[(b * Ss + sl) * Hh + t], acc[sl]);
}

// ---------------- final scalar loss ----------------
__global__ void finalize_kernel(const float* __restrict__ colsum,
                                const float* __restrict__ entsum,
                                float* __restrict__ out_loss)
{
    int l = threadIdx.x;
    float avg = colsum[l] / (float)Nn;
    float dv = avg * logf(avg + EPS_F);
    dv = warp_sum(dv);
    if (l == 0) {
        float entropy = -(entsum[0] / (float)Nn);
        out_loss[0] = entropy + dv;
    }
}

// ---------------- launch ----------------
extern "C" void kernel_launch(void* const* d_in, const int* in_sizes, int n_in,
                              void* d_out, int out_size)
{
    const float* x    = (const float*)d_in[0];
    const float* u    = (const float*)d_in[1];
    const int* eidx   = (const int*)d_in[2];
    const int* batch  = (const int*)d_in[3];
    const float* g1w1 = (const float*)d_in[4];
    const float* g1b1 = (const float*)d_in[5];
    const float* g1w2 = (const float*)d_in[6];
    const float* g1b2 = (const float*)d_in[7];
    const float* g1w3 = (const float*)d_in[8];
    const float* g1b3 = (const float*)d_in[9];
    const float* ln1g = (const float*)d_in[10];
    const float* ln1b = (const float*)d_in[11];
    const float* g2w1 = (const float*)d_in[12];
    const float* g2b1 = (const float*)d_in[13];
    const float* g2w2 = (const float*)d_in[14];
    const float* g2b2 = (const float*)d_in[15];
    const float* g2w3 = (const float*)d_in[16];
    const float* g2b3 = (const float*)d_in[17];
    const float* ln2g = (const float*)d_in[18];
    const float* ln2b = (const float*)d_in[19];
    const float* aw1  = (const float*)d_in[20];
    const float* ab1  = (const float*)d_in[21];
    const float* aw2  = (const float*)d_in[22];
    const float* ab2  = (const float*)d_in[23];
    const float* ow1  = (const float*)d_in[24];
    const float* ob1  = (const float*)d_in[25];
    const float* ow2  = (const float*)d_in[26];
    const float* ob2  = (const float*)d_in[27];

    const int* src = eidx;
    const int* dst = eidx + Ee;

    float* out = (float*)d_out;
    float* out_latent = out;
    float* out_s = out + Bb * Ss * Ll;
    float* out_loss = out + Bb * Ss * Ll + Nn * Ss;

    float *P, *Q, *agg, *xc, *pooled, *t2, *colsum, *entsum;
    int* bstart;
    __nv_bfloat16* wbf;
    cudaGetSymbolAddress((void**)&P, d_P);
    cudaGetSymbolAddress((void**)&Q, d_Q);
    cudaGetSymbolAddress((void**)&agg, d_agg);
    cudaGetSymbolAddress((void**)&xc, d_x);
    cudaGetSymbolAddress((void**)&pooled, d_pooled);
    cudaGetSymbolAddress((void**)&t2, d_t2);
    cudaGetSymbolAddress((void**)&colsum, d_colsum);
    cudaGetSymbolAddress((void**)&entsum, d_entsum);
    cudaGetSymbolAddress((void**)&bstart, d_bstart);
    cudaGetSymbolAddress((void**)&wbf, d_wbf);

    cudaFuncSetAttribute(edge_mma_kernel, cudaFuncAttributeMaxDynamicSharedMemorySize, SM_TOT);

    const int NH = Nn * Hh;
    const int ZB = 256;
    const int WN = Hh * Hh;   // 65536

    // ---- zero accumulators ----
    zero_kernel<<<(NH + ZB - 1) / ZB, ZB>>>(agg, NH);
    zero_kernel<<<(Bb * Ss * Hh + ZB - 1) / ZB, ZB>>>(pooled, Bb * Ss * Hh);
    zero_kernel<<<1, ZB>>>(colsum, Ss);
    zero_kernel<<<1, ZB>>>(entsum, 1);

    // ---- transpose + split weights to bf16 hi/lo ([n][k] layout) ----
    wsplit_kernel<<<256, 256>>>(g1w2, wbf + 0 * WN, wbf + 1 * WN);
    wsplit_kernel<<<256, 256>>>(g1w3, wbf + 2 * WN, wbf + 3 * WN);
    wsplit_kernel<<<256, 256>>>(g2w2, wbf + 4 * WN, wbf + 5 * WN);
    wsplit_kernel<<<256, 256>>>(g2w3, wbf + 6 * WN, wbf + 7 * WN);

    // ---- GNN layer 1 ----
    gemm_tiled<Hh, 32><<<Nn / 32, 256>>>(x, Ff, g1w1, nullptr, P, Nn, 0);
    gemm_tiled<Hh, 32><<<Nn / 32, 256>>>(x, Ff, g1w1 + Ff * Hh, g1b1, Q, Nn, 0);
    edge_mma_kernel<<<Ee / 128, 512, SM_TOT>>>(src, dst, P, Q,
        wbf + 0 * WN, wbf + 1 * WN, wbf + 2 * WN, wbf + 3 * WN, g1b2, g1b3, agg);
    relu_ln_kernel<<<Nn, 256>>>(agg, ln1g, ln1b, xc);

    // ---- GNN layer 2 ----
    gemm_tiled<Hh, 32><<<Nn / 32, 256>>>(xc, Hh, g2w1, nullptr, P, Nn, 0);
    gemm_tiled<Hh, 32><<<Nn / 32, 256>>>(xc, Hh, g2w1 + Hh * Hh, g2b1, Q, Nn, 0);
    zero_kernel<<<(NH + ZB - 1) / ZB, ZB>>>(agg, NH);
    edge_mma_kernel<<<Ee / 128, 512, SM_TOT>>>(src, dst, P, Q,
        wbf + 4 * WN, wbf + 5 * WN, wbf + 6 * WN, wbf + 7 * WN, g2b2, g2b3, agg);
    relu_ln_kernel<<<Nn, 256>>>(agg, ln2g, ln2b, xc);

    // ---- assignment ----
    gemm_tiled<Hh, 32><<<Nn / 32, 256>>>(xc, Hh, aw1, ab1, P, Nn, 1);
    assign_kernel<<<Nn / 8, 256>>>(P, aw2, ab2, u, out_s, entsum, colsum);

    // ---- pooling ----
    bstart_kernel<<<1, 32>>>(batch, bstart);
    {
        dim3 grid(Bb, 8);
        pool_kernel<<<grid, 256>>>(xc, out_s, bstart, pooled);
    }

    // ---- output MLP ----
    gemm_tiled<Hh, 32><<<(Bb * Ss) / 32, 256>>>(pooled, Hh, ow1, ob1, t2, Bb * Ss, 1);
    gemm_tiled<Ll, 32><<<(Bb * Ss) / 32, 256>>>(t2, Hh, ow2, ob2, out_latent, Bb * Ss, 0);

    // ---- loss scalar ----
    finalize_kernel<<<1, 32>>>(colsum, entsum, out_loss);
}

// round 9
// speedup vs baseline: 2.5263x; 1.2578x over previous
#include <cuda_runtime.h>
#include <cuda_bf16.h>
#include <cuda_fp16.h>
#include <math.h>
#include <stdint.h>

#define Nn 20000
#define Ee 320000
#define Ff 64
#define Hh 256
#define Ss 32
#define Ll 128
#define Bb 16
#define EPS_F 1e-9f

// ---------------- scratch (device globals; no allocation allowed) ----------------
__device__ float d_P[Nn * Hh];
__device__ float d_Q[Nn * Hh];
__device__ float d_agg[Nn * Hh];
__device__ float d_x[Nn * Hh];
__device__ float d_pooled[Bb * Ss * Hh];
__device__ float d_t2[Bb * Ss * Hh];
__device__ float d_colsum[Ss];
__device__ float d_entsum[1];
__device__ int   d_bstart[Bb + 1];
__device__ __align__(256) __half d_wbf[8 * Hh * Hh]; // [w2hi,w2lo,w3hi,w3lo] x 2 layers

// ================= warp-MMA helpers (sm_80-compatible PTX) =================
__device__ __forceinline__ uint32_t smem_u32(const void* p) {
    uint32_t a;
    asm("{ .reg .u64 t; cvta.to.shared.u64 t, %1; cvt.u32.u64 %0, t; }" : "=r"(a) : "l"(p));
    return a;
}
__device__ __forceinline__ void cp16(uint32_t saddr, const void* g) {
    asm volatile("cp.async.cg.shared.global [%0], [%1], 16;" :: "r"(saddr), "l"(g));
}
#define CP_COMMIT() asm volatile("cp.async.commit_group;" ::: "memory")
#define CP_WAIT1()  asm volatile("cp.async.wait_group 1;" ::: "memory")
#define CP_WAIT0()  asm volatile("cp.async.wait_group 0;" ::: "memory")

#define LDSM4(r0, r1, r2, r3, addr) \
    asm volatile("ldmatrix.sync.aligned.m8n8.x4.shared.b16 {%0,%1,%2,%3}, [%4];" \
        : "=r"(r0), "=r"(r1), "=r"(r2), "=r"(r3) : "r"(addr))

__device__ __forceinline__ void mma16816(float* c,
    uint32_t a0, uint32_t a1, uint32_t a2, uint32_t a3, uint32_t b0, uint32_t b1) {
    asm volatile("mma.sync.aligned.m16n8k16.row.col.f32.f16.f16.f32 "
        "{%0,%1,%2,%3}, {%4,%5,%6,%7}, {%8,%9}, {%0,%1,%2,%3};"
        : "+f"(c[0]), "+f"(c[1]), "+f"(c[2]), "+f"(c[3])
        : "r"(a0), "r"(a1), "r"(a2), "r"(a3), "r"(b0), "r"(b1));
}

// ================= SMEM layout for edge kernel (bytes) =================
#define AROW    528                      // 256 fp16 + 16B pad (conflict-free ldmatrix)
#define SM_AHI  0                        // 128 * 528 = 67584
#define SM_BBUF 67584                    // 2 buffers x (8KB hi + 8KB lo) = 32768
#define SM_IDS  100352                   // sdst[128], ssrc[128]
#define SM_B2   101376
#define SM_B3   102400
#define SM_TOT  103424

// ---------------- weight transpose + fp16 split ----------------
__global__ void wsplit_kernel(const float* __restrict__ w,
                              __half* __restrict__ hi, __half* __restrict__ lo) {
    int i = blockIdx.x * 256 + threadIdx.x;   // i = n*256 + k
    int n = i >> 8, k = i & 255;
    float v = w[k * Hh + n];
    __half h = __float2half_rn(v);
    hi[i] = h;
    lo[i] = __float2half_rn(v - __half2float(h));
}

// ---------------- B-slice loader: 16 k-rows x 256 n, hi+lo, xor-swizzled (512 thr) ----------------
__device__ __forceinline__ void load_slice(int s, uint32_t sb, int t,
    const __half* w2hi, const __half* w2lo,
    const __half* w3hi, const __half* w3lo)
{
    const __half* Wh = (s < 16) ? w2hi : w3hi;
    const __half* Wl = (s < 16) ? w2lo : w3lo;
    const int kt = s & 15;
    const uint32_t base = sb + SM_BBUF + (uint32_t)(s & 1) * 16384u;
    const int n = t >> 1;                 // 512 threads -> 256 n-rows, 2 thr each
    const int h = t & 1;                  // 16B half
    const char* gh = (const char*)(Wh + (size_t)n * Hh + kt * 16) + h * 16;
    const char* gl = (const char*)(Wl + (size_t)n * Hh + kt * 16) + h * 16;
    const uint32_t sw4 = (n & 4) ? 16u : 0u;
    const uint32_t doff = base + (uint32_t)n * 32u + (((uint32_t)h * 16u) ^ sw4);
    cp16(doff, gh);
    cp16(doff + 8192u, gl);
}

// ---------------- fused tensor-core edge MLP (16 warps, 32x64 warp tiles, fp16 2-MMA) ----------------
__global__ __launch_bounds__(512, 1) void edge_mma_kernel(
    const int* __restrict__ src, const int* __restrict__ dst,
    const float* __restrict__ P, const float* __restrict__ Q,
    const __half* __restrict__ w2hi, const __half* __restrict__ w2lo,
    const __half* __restrict__ w3hi, const __half* __restrict__ w3lo,
    const float* __restrict__ b2, const float* __restrict__ b3,
    float* __restrict__ agg)
{
    extern __shared__ char sm[];
    const uint32_t sb = smem_u32(sm);
    const int t = threadIdx.x;
    const int w = t >> 5, l = t & 31;
    const int wm = w & 3;        // row quarter: rows [32*wm, 32*wm+32)
    const int wn = w >> 2;       // col quarter: cols [64*wn, 64*wn+64)

    int* sdst = (int*)(sm + SM_IDS);
    int* ssrc = sdst + 128;
    float* sb2 = (float*)(sm + SM_B2);
    float* sb3 = (float*)(sm + SM_B3);

    if (t < 128) {
        sdst[t] = dst[blockIdx.x * 128 + t];
        ssrc[t] = src[blockIdx.x * 128 + t];
    }
    if (t < 256) {
        sb2[t] = b2[t];
        sb3[t] = b3[t];
    }
    __syncthreads();

    // ---- build A = fp16(relu(P[dst] + Q[src])) : 4 threads per edge row ----
    {
        const int e = t & 127, h = t >> 7;        // h in 0..3, 64 cols each
        const int de = sdst[e], se = ssrc[e];
        const float4* Pr = reinterpret_cast<const float4*>(P) + (size_t)de * 64 + h * 16;
        const float4* Qr = reinterpret_cast<const float4*>(Q) + (size_t)se * 64 + h * 16;
        const uint32_t arow = (uint32_t)e * AROW + (uint32_t)h * 128u;
#pragma unroll
        for (int j = 0; j < 8; j++) {
            float4 p0 = Pr[2 * j], q0 = Qr[2 * j];
            float4 p1 = Pr[2 * j + 1], q1 = Qr[2 * j + 1];
            union { uint4 u; __half2 h2[4]; } HI;
            HI.h2[0] = __floats2half2_rn(fmaxf(p0.x + q0.x, 0.f), fmaxf(p0.y + q0.y, 0.f));
            HI.h2[1] = __floats2half2_rn(fmaxf(p0.z + q0.z, 0.f), fmaxf(p0.w + q0.w, 0.f));
            HI.h2[2] = __floats2half2_rn(fmaxf(p1.x + q1.x, 0.f), fmaxf(p1.y + q1.y, 0.f));
            HI.h2[3] = __floats2half2_rn(fmaxf(p1.z + q1.z, 0.f), fmaxf(p1.w + q1.w, 0.f));
            *(uint4*)(sm + SM_AHI + arow + j * 16) = HI.u;
        }
    }

    // ---- accumulators: warp owns 32 rows x 64 cols : acc[mi][nj][4] ----
    float acc[2][8][4];
#pragma unroll
    for (int mi = 0; mi < 2; mi++)
#pragma unroll
        for (int nj = 0; nj < 8; nj++) {
            acc[mi][nj][0] = 0.f; acc[mi][nj][1] = 0.f;
            acc[mi][nj][2] = 0.f; acc[mi][nj][3] = 0.f;
        }

    // per-lane ldmatrix offsets
    const uint32_t a_base = sb + (uint32_t)((32 * wm + (l % 16)) * AROW + (l / 16) * 16);
    const uint32_t b_off = (uint32_t)((l % 16) * 32) +
                           (uint32_t)(((l / 16) * 16) ^ (((l % 16) & 4) ? 16 : 0));

    load_slice(0, sb, t, w2hi, w2lo, w3hi, w3lo); CP_COMMIT();
    load_slice(1, sb, t, w2hi, w2lo, w3hi, w3lo); CP_COMMIT();

#pragma unroll 1
    for (int s = 0; s < 32; s++) {
        if (s < 30) { CP_WAIT1(); } else { CP_WAIT0(); }
        __syncthreads();

        const int kt = s & 15;
        // load A fragments: 2 m-tiles
        uint32_t ah[2][4];
#pragma unroll
        for (int mi = 0; mi < 2; mi++) {
            const uint32_t aa = a_base + (uint32_t)(16 * mi * AROW) + kt * 32;
            LDSM4(ah[mi][0], ah[mi][1], ah[mi][2], ah[mi][3], aa + SM_AHI);
        }

        const uint32_t bbase = sb + SM_BBUF + (uint32_t)(s & 1) * 16384u + b_off
                             + (uint32_t)(wn * 2048);   // 4 chunks x 512B per wn
#pragma unroll
        for (int c = 0; c < 4; c++) {
            uint32_t bh0, bh1, bh2, bh3, bl0, bl1, bl2, bl3;
            LDSM4(bh0, bh1, bh2, bh3, bbase + c * 512);
            LDSM4(bl0, bl1, bl2, bl3, bbase + 8192 + c * 512);
#pragma unroll
            for (int mi = 0; mi < 2; mi++) {
                float* c0 = acc[mi][2 * c];
                float* c1 = acc[mi][2 * c + 1];
                mma16816(c0, ah[mi][0], ah[mi][1], ah[mi][2], ah[mi][3], bh0, bh2);  // A*Whi
                mma16816(c0, ah[mi][0], ah[mi][1], ah[mi][2], ah[mi][3], bl0, bl2);  // A*Wlo
                mma16816(c1, ah[mi][0], ah[mi][1], ah[mi][2], ah[mi][3], bh1, bh3);
                mma16816(c1, ah[mi][0], ah[mi][1], ah[mi][2], ah[mi][3], bl1, bl3);
            }
        }

        if (s == 15) {
            // all warps must finish reading A (slice-15 frags) before overwrite
            __syncthreads();
            // ---- epilogue 1: A := fp16(relu(D1 + b2)) for this warp's 32x64 tile ----
            const int cb = (l % 4) * 2;
#pragma unroll
            for (int mi = 0; mi < 2; mi++) {
                const int r0 = 32 * wm + 16 * mi + l / 4;
#pragma unroll
                for (int nj = 0; nj < 8; nj++) {
                    const int cn = 64 * wn + 8 * nj + cb;
                    const float bz0 = sb2[cn], bz1 = sb2[cn + 1];
                    __half2 hp0 = __floats2half2_rn(fmaxf(acc[mi][nj][0] + bz0, 0.f),
                                                    fmaxf(acc[mi][nj][1] + bz1, 0.f));
                    __half2 hp1 = __floats2half2_rn(fmaxf(acc[mi][nj][2] + bz0, 0.f),
                                                    fmaxf(acc[mi][nj][3] + bz1, 0.f));
                    *(uint32_t*)(sm + SM_AHI + r0 * AROW + cn * 2)       = *(uint32_t*)&hp0;
                    *(uint32_t*)(sm + SM_AHI + (r0 + 8) * AROW + cn * 2) = *(uint32_t*)&hp1;
                    acc[mi][nj][0] = 0.f; acc[mi][nj][1] = 0.f;
                    acc[mi][nj][2] = 0.f; acc[mi][nj][3] = 0.f;
                }
            }
        }
        __syncthreads();
        if (s + 2 < 32) {
            load_slice(s + 2, sb, t, w2hi, w2lo, w3hi, w3lo);
            CP_COMMIT();
        }
    }

    // ---- epilogue 2: agg[dst] += D2 + b3 ----
    {
        const int cb = (l % 4) * 2;
#pragma unroll
        for (int mi = 0; mi < 2; mi++) {
            const int er = 32 * wm + 16 * mi + l / 4;
            const int d0 = sdst[er], d1 = sdst[er + 8];
            float* a0 = agg + (size_t)d0 * Hh;
            float* a1 = agg + (size_t)d1 * Hh;
#pragma unroll
            for (int nj = 0; nj < 8; nj++) {
                const int cn = 64 * wn + 8 * nj + cb;
                const float bz0 = sb3[cn], bz1 = sb3[cn + 1];
                atomicAdd(a0 + cn,     acc[mi][nj][0] + bz0);
                atomicAdd(a0 + cn + 1, acc[mi][nj][1] + bz1);
                atomicAdd(a1 + cn,     acc[mi][nj][2] + bz0);
                atomicAdd(a1 + cn + 1, acc[mi][nj][3] + bz1);
            }
        }
    }
}

// ---------------- zero ----------------
__global__ void zero_kernel(float* p, int n) {
    int i = blockIdx.x * blockDim.x + threadIdx.x;
    if (i < n) p[i] = 0.f;
}

// ---------------- generic row-tiled fp32 GEMM ----------------
template <int NCOL, int RPB>
__global__ __launch_bounds__(256) void gemm_tiled(
    const float* __restrict__ A, int K,
    const float* __restrict__ W, const float* __restrict__ bias,
    float* __restrict__ C, int M, int do_relu)
{
    __shared__ float As[RPB * 256];
    const int row0 = blockIdx.x * RPB;
    const int tot = RPB * K;
    for (int idx = threadIdx.x; idx < tot; idx += 256) {
        int r = idx / K, k = idx - r * K;
        int gr = row0 + r;
        As[idx] = (gr < M) ? A[gr * K + k] : 0.f;
    }
    __syncthreads();

    const int RG = 256 / NCOL;
    const int RPT = RPB / RG;
    const int col = threadIdx.x % NCOL;
    const int rg = threadIdx.x / NCOL;

    float acc[RPT];
    float bv = bias ? bias[col] : 0.f;
#pragma unroll
    for (int i = 0; i < RPT; i++) acc[i] = bv;

    for (int k = 0; k < K; k += 4) {
        float wv0 = W[(k + 0) * NCOL + col];
        float wv1 = W[(k + 1) * NCOL + col];
        float wv2 = W[(k + 2) * NCOL + col];
        float wv3 = W[(k + 3) * NCOL + col];
#pragma unroll
        for (int i = 0; i < RPT; i++) {
            const float4 a = *(const float4*)&As[(rg + i * RG) * K + k];
            acc[i] = fmaf(a.x, wv0, acc[i]);
            acc[i] = fmaf(a.y, wv1, acc[i]);
            acc[i] = fmaf(a.z, wv2, acc[i]);
            acc[i] = fmaf(a.w, wv3, acc[i]);
        }
    }
#pragma unroll
    for (int i = 0; i < RPT; i++) {
        int gr = row0 + rg + i * RG;
        if (gr < M) {
            float v = acc[i];
            if (do_relu) v = fmaxf(v, 0.f);
            C[gr * NCOL + col] = v;
        }
    }
}

// ---------------- relu + layernorm per node ----------------
__device__ __forceinline__ float warp_sum(float v) {
#pragma unroll
    for (int o = 16; o > 0; o >>= 1) v += __shfl_xor_sync(0xFFFFFFFFu, v, o);
    return v;
}

__global__ __launch_bounds__(256) void relu_ln_kernel(
    const float* __restrict__ agg, const float* __restrict__ g,
    const float* __restrict__ b, float* __restrict__ xout)
{
    const int n = blockIdx.x;
    const int j = threadIdx.x;
    const int lane = j & 31, warp = j >> 5;
    __shared__ float red[8];
    __shared__ float s_mu, s_rstd;

    float v = fmaxf(agg[n * Hh + j], 0.f);
    float t = warp_sum(v);
    if (lane == 0) red[warp] = t;
    __syncthreads();
    if (j == 0) {
        float s = 0.f;
#pragma unroll
        for (int i = 0; i < 8; i++) s += red[i];
        s_mu = s / (float)Hh;
    }
    __syncthreads();
    float d = v - s_mu;
    float t2 = warp_sum(d * d);
    if (lane == 0) red[warp] = t2;
    __syncthreads();
    if (j == 0) {
        float s = 0.f;
#pragma unroll
        for (int i = 0; i < 8; i++) s += red[i];
        s_rstd = rsqrtf(s / (float)Hh + 1e-5f);
    }
    __syncthreads();
    xout[n * Hh + j] = d * s_rstd * g[j] + b[j];
}

// ---------------- assignment ----------------
__global__ __launch_bounds__(256) void assign_kernel(
    const float* __restrict__ t1, const float* __restrict__ aw2,
    const float* __restrict__ ab2, const float* __restrict__ u,
    float* __restrict__ s_out, float* __restrict__ entsum, float* __restrict__ colsum)
{
    __shared__ float rows[8 * Hh];
    __shared__ float blk_col[Ss];
    __shared__ float blk_ent;

    const int lane = threadIdx.x & 31, warp = threadIdx.x >> 5;
    if (threadIdx.x < Ss) blk_col[threadIdx.x] = 0.f;
    if (threadIdx.x == 0) blk_ent = 0.f;
    const int n0 = blockIdx.x * 8;
    for (int idx = threadIdx.x; idx < 8 * Hh; idx += 256)
        rows[idx] = t1[n0 * Hh + idx];
    __syncthreads();

    const int n = n0 + warp;
    float acc = ab2[lane];
    for (int k = 0; k < Hh; k += 4) {
        const float4 a = *(const float4*)&rows[warp * Hh + k];
        acc = fmaf(a.x, aw2[(k + 0) * Ss + lane], acc);
        acc = fmaf(a.y, aw2[(k + 1) * Ss + lane], acc);
        acc = fmaf(a.z, aw2[(k + 2) * Ss + lane], acc);
        acc = fmaf(a.w, aw2[(k + 3) * Ss + lane], acc);
    }
    float uu = u[n * Ss + lane];
    float gmb = -logf(-logf(uu + EPS_F) + EPS_F);
    float z = acc + gmb;
    float m = z;
#pragma unroll
    for (int o = 16; o > 0; o >>= 1) m = fmaxf(m, __shfl_xor_sync(0xFFFFFFFFu, m, o));
    float p = expf(z - m);
    float sum = warp_sum(p);
    float sv = p / sum;
    s_out[n * Ss + lane] = sv;

    float ent = warp_sum(sv * logf(sv + EPS_F));
    if (lane == 0) atomicAdd(&blk_ent, ent);
    atomicAdd(&blk_col[lane], sv);
    __syncthreads();
    if (threadIdx.x == 0) atomicAdd(entsum, blk_ent);
    if (threadIdx.x < Ss) atomicAdd(&colsum[threadIdx.x], blk_col[threadIdx.x]);
}

// ---------------- batch segment starts ----------------
__global__ void bstart_kernel(const int* __restrict__ batch, int* __restrict__ bstart) {
    int b = threadIdx.x;
    if (b > Bb) return;
    if (b == Bb) { bstart[Bb] = Nn; return; }
    int lo = 0, hi = Nn;
    while (lo < hi) {
        int mid = (lo + hi) >> 1;
        if (batch[mid] < b) lo = mid + 1; else hi = mid;
    }
    bstart[b] = lo;
}

// ---------------- pooling ----------------
__global__ __launch_bounds__(256) void pool_kernel(
    const float* __restrict__ x, const float* __restrict__ s_out,
    const int* __restrict__ bstart, float* __restrict__ pooled)
{
    const int b = blockIdx.x;
    const int chunk = blockIdx.y;
    const int NCHUNK = gridDim.y;
    const int lo = bstart[b], hi = bstart[b + 1];
    const int cnt = hi - lo;
    const int c0 = lo + (int)(((long long)cnt * chunk) / NCHUNK);
    const int c1 = lo + (int)(((long long)cnt * (chunk + 1)) / NCHUNK);

    __shared__ float ss[Ss];
    const int t = threadIdx.x;
    float acc[Ss];
#pragma unroll
    for (int sl = 0; sl < Ss; sl++) acc[sl] = 0.f;

    for (int n = c0; n < c1; n++) {
        __syncthreads();
        if (t < Ss) ss[t] = s_out[n * Ss + t];
        __syncthreads();
        float xv = x[n * Hh + t];
#pragma unroll
        for (int sl = 0; sl < Ss; sl++) acc[sl] = fmaf(xv, ss[sl], acc[sl]);
    }
#pragma unroll
    for (int sl = 0; sl < Ss; sl++)
        atomicAdd(&pooled[(b * Ss + sl) * Hh + t], acc[sl]);
}

// ---------------- final scalar loss ----------------
__global__ void finalize_kernel(const float* __restrict__ colsum,
                                const float* __restrict__ entsum,
                                float* __restrict__ out_loss)
{
    int l = threadIdx.x;
    float avg = colsum[l] / (float)Nn;
    float dv = avg * logf(avg + EPS_F);
    dv = warp_sum(dv);
    if (l == 0) {
        float entropy = -(entsum[0] / (float)Nn);
        out_loss[0] = entropy + dv;
    }
}

// ---------------- launch ----------------
extern "C" void kernel_launch(void* const* d_in, const int* in_sizes, int n_in,
                              void* d_out, int out_size)
{
    const float* x    = (const float*)d_in[0];
    const float* u    = (const float*)d_in[1];
    const int* eidx   = (const int*)d_in[2];
    const int* batch  = (const int*)d_in[3];
    const float* g1w1 = (const float*)d_in[4];
    const float* g1b1 = (const float*)d_in[5];
    const float* g1w2 = (const float*)d_in[6];
    const float* g1b2 = (const float*)d_in[7];
    const float* g1w3 = (const float*)d_in[8];
    const float* g1b3 = (const float*)d_in[9];
    const float* ln1g = (const float*)d_in[10];
    const float* ln1b = (const float*)d_in[11];
    const float* g2w1 = (const float*)d_in[12];
    const float* g2b1 = (const float*)d_in[13];
    const float* g2w2 = (const float*)d_in[14];
    const float* g2b2 = (const float*)d_in[15];
    const float* g2w3 = (const float*)d_in[16];
    const float* g2b3 = (const float*)d_in[17];
    const float* ln2g = (const float*)d_in[18];
    const float* ln2b = (const float*)d_in[19];
    const float* aw1  = (const float*)d_in[20];
    const float* ab1  = (const float*)d_in[21];
    const float* aw2  = (const float*)d_in[22];
    const float* ab2  = (const float*)d_in[23];
    const float* ow1  = (const float*)d_in[24];
    const float* ob1  = (const float*)d_in[25];
    const float* ow2  = (const float*)d_in[26];
    const float* ob2  = (const float*)d_in[27];

    const int* src = eidx;
    const int* dst = eidx + Ee;

    float* out = (float*)d_out;
    float* out_latent = out;
    float* out_s = out + Bb * Ss * Ll;
    float* out_loss = out + Bb * Ss * Ll + Nn * Ss;

    float *P, *Q, *agg, *xc, *pooled, *t2, *colsum, *entsum;
    int* bstart;
    __half* wbf;
    cudaGetSymbolAddress((void**)&P, d_P);
    cudaGetSymbolAddress((void**)&Q, d_Q);
    cudaGetSymbolAddress((void**)&agg, d_agg);
    cudaGetSymbolAddress((void**)&xc, d_x);
    cudaGetSymbolAddress((void**)&pooled, d_pooled);
    cudaGetSymbolAddress((void**)&t2, d_t2);
    cudaGetSymbolAddress((void**)&colsum, d_colsum);
    cudaGetSymbolAddress((void**)&entsum, d_entsum);
    cudaGetSymbolAddress((void**)&bstart, d_bstart);
    cudaGetSymbolAddress((void**)&wbf, d_wbf);

    cudaFuncSetAttribute(edge_mma_kernel, cudaFuncAttributeMaxDynamicSharedMemorySize, SM_TOT);

    const int NH = Nn * Hh;
    const int ZB = 256;
    const int WN = Hh * Hh;   // 65536

    // ---- zero accumulators ----
    zero_kernel<<<(NH + ZB - 1) / ZB, ZB>>>(agg, NH);
    zero_kernel<<<(Bb * Ss * Hh + ZB - 1) / ZB, ZB>>>(pooled, Bb * Ss * Hh);
    zero_kernel<<<1, ZB>>>(colsum, Ss);
    zero_kernel<<<1, ZB>>>(entsum, 1);

    // ---- transpose + split weights to fp16 hi/lo ([n][k] layout) ----
    wsplit_kernel<<<256, 256>>>(g1w2, wbf + 0 * WN, wbf + 1 * WN);
    wsplit_kernel<<<256, 256>>>(g1w3, wbf + 2 * WN, wbf + 3 * WN);
    wsplit_kernel<<<256, 256>>>(g2w2, wbf + 4 * WN, wbf + 5 * WN);
    wsplit_kernel<<<256, 256>>>(g2w3, wbf + 6 * WN, wbf + 7 * WN);

    // ---- GNN layer 1 ----
    gemm_tiled<Hh, 32><<<Nn / 32, 256>>>(x, Ff, g1w1, nullptr, P, Nn, 0);
    gemm_tiled<Hh, 32><<<Nn / 32, 256>>>(x, Ff, g1w1 + Ff * Hh, g1b1, Q, Nn, 0);
    edge_mma_kernel<<<Ee / 128, 512, SM_TOT>>>(src, dst, P, Q,
        wbf + 0 * WN, wbf + 1 * WN, wbf + 2 * WN, wbf + 3 * WN, g1b2, g1b3, agg);
    relu_ln_kernel<<<Nn, 256>>>(agg, ln1g, ln1b, xc);

    // ---- GNN layer 2 ----
    gemm_tiled<Hh, 32><<<Nn / 32, 256>>>(xc, Hh, g2w1, nullptr, P, Nn, 0);
    gemm_tiled<Hh, 32><<<Nn / 32, 256>>>(xc, Hh, g2w1 + Hh * Hh, g2b1, Q, Nn, 0);
    zero_kernel<<<(NH + ZB - 1) / ZB, ZB>>>(agg, NH);
    edge_mma_kernel<<<Ee / 128, 512, SM_TOT>>>(src, dst, P, Q,
        wbf + 4 * WN, wbf + 5 * WN, wbf + 6 * WN, wbf + 7 * WN, g2b2, g2b3, agg);
    relu_ln_kernel<<<Nn, 256>>>(agg, ln2g, ln2b, xc);

    // ---- assignment ----
    gemm_tiled<Hh, 32><<<Nn / 32, 256>>>(xc, Hh, aw1, ab1, P, Nn, 1);
    assign_kernel<<<Nn / 8, 256>>>(P, aw2, ab2, u, out_s, entsum, colsum);

    // ---- pooling ----
    bstart_kernel<<<1, 32>>>(batch, bstart);
    {
        dim3 grid(Bb, 8);
        pool_kernel<<<grid, 256>>>(xc, out_s, bstart, pooled);
    }

    // ---- output MLP ----
    gemm_tiled<Hh, 32><<<(Bb * Ss) / 32, 256>>>(pooled, Hh, ow1, ob1, t2, Bb * Ss, 1);
    gemm_tiled<Ll, 32><<<(Bb * Ss) / 32, 256>>>(t2, Hh, ow2, ob2, out_latent, Bb * Ss, 0);

    // ---- loss scalar ----
    finalize_kernel<<<1, 32>>>(colsum, entsum, out_loss);
}

// round 10
// speedup vs baseline: 3.1255x; 1.2372x over previous
#include <cuda_runtime.h>
#include <cuda_bf16.h>
#include <cuda_fp16.h>
#include <math.h>
#include <stdint.h>

#define Nn 20000
#define Ee 320000
#define Ff 64
#define Hh 256
#define Ss 32
#define Ll 128
#define Bb 16
#define EPS_F 1e-9f

// ---------------- scratch (device globals; no allocation allowed) ----------------
__device__ float d_P[Nn * Hh];
__device__ float d_Q[Nn * Hh];
__device__ float d_agg[Nn * Hh];
__device__ float d_x[Nn * Hh];
__device__ float d_pooled[Bb * Ss * Hh];
__device__ float d_t2[Bb * Ss * Hh];
__device__ float d_colsum[Ss];
__device__ float d_entsum[1];
__device__ int   d_bstart[Bb + 1];
__device__ __align__(256) __half d_wbf[4 * Hh * Hh]; // [w2,w3] x 2 layers (fp16)

// ================= warp-MMA helpers (sm_80-compatible PTX) =================
__device__ __forceinline__ uint32_t smem_u32(const void* p) {
    uint32_t a;
    asm("{ .reg .u64 t; cvta.to.shared.u64 t, %1; cvt.u32.u64 %0, t; }" : "=r"(a) : "l"(p));
    return a;
}
__device__ __forceinline__ void cp16(uint32_t saddr, const void* g) {
    asm volatile("cp.async.cg.shared.global [%0], [%1], 16;" :: "r"(saddr), "l"(g));
}
#define CP_COMMIT() asm volatile("cp.async.commit_group;" ::: "memory")
#define CP_WAIT1()  asm volatile("cp.async.wait_group 1;" ::: "memory")
#define CP_WAIT0()  asm volatile("cp.async.wait_group 0;" ::: "memory")

#define LDSM4(r0, r1, r2, r3, addr) \
    asm volatile("ldmatrix.sync.aligned.m8n8.x4.shared.b16 {%0,%1,%2,%3}, [%4];" \
        : "=r"(r0), "=r"(r1), "=r"(r2), "=r"(r3) : "r"(addr))

__device__ __forceinline__ void mma16816(float* c,
    uint32_t a0, uint32_t a1, uint32_t a2, uint32_t a3, uint32_t b0, uint32_t b1) {
    asm volatile("mma.sync.aligned.m16n8k16.row.col.f32.f16.f16.f32 "
        "{%0,%1,%2,%3}, {%4,%5,%6,%7}, {%8,%9}, {%0,%1,%2,%3};"
        : "+f"(c[0]), "+f"(c[1]), "+f"(c[2]), "+f"(c[3])
        : "r"(a0), "r"(a1), "r"(a2), "r"(a3), "r"(b0), "r"(b1));
}

// ================= SMEM layout for edge kernel (bytes) =================
#define AROW    528                      // 256 fp16 + 16B pad (conflict-free ldmatrix)
#define SM_AHI  0                        // 128 * 528 = 67584
#define SM_BBUF 67584                    // 2 buffers x 8KB = 16384
#define SM_IDS  83968                    // sdst[128], ssrc[128]
#define SM_B2   84992
#define SM_B3   86016
#define SM_TOT  87040

// ---------------- weight transpose + fp16 convert ----------------
__global__ void wsplit_kernel(const float* __restrict__ w, __half* __restrict__ hi) {
    int i = blockIdx.x * 256 + threadIdx.x;   // i = n*256 + k
    int n = i >> 8, k = i & 255;
    hi[i] = __float2half_rn(w[k * Hh + n]);
}

// ---------------- B-slice loader: 16 k-rows x 256 n, xor-swizzled (512 thr, 1 cp each) --------
__device__ __forceinline__ void load_slice(int s, uint32_t sb, int t,
    const __half* w2, const __half* w3)
{
    const __half* Wh = (s < 16) ? w2 : w3;
    const int kt = s & 15;
    const uint32_t base = sb + SM_BBUF + (uint32_t)(s & 1) * 8192u;
    const int n = t >> 1;                 // 512 threads -> 256 n-rows, 2 thr each
    const int h = t & 1;                  // 16B half
    const char* gh = (const char*)(Wh + (size_t)n * Hh + kt * 16) + h * 16;
    const uint32_t sw4 = (n & 4) ? 16u : 0u;
    const uint32_t doff = base + (uint32_t)n * 32u + (((uint32_t)h * 16u) ^ sw4);
    cp16(doff, gh);
}

// ---------------- fused tensor-core edge MLP (16 warps, 32x64 warp tiles, fp16 1-MMA) ---------
__global__ __launch_bounds__(512, 1) void edge_mma_kernel(
    const int* __restrict__ src, const int* __restrict__ dst,
    const float* __restrict__ P, const float* __restrict__ Q,
    const __half* __restrict__ w2, const __half* __restrict__ w3,
    const float* __restrict__ b2, const float* __restrict__ b3,
    float* __restrict__ agg)
{
    extern __shared__ char sm[];
    const uint32_t sb = smem_u32(sm);
    const int t = threadIdx.x;
    const int w = t >> 5, l = t & 31;
    const int wm = w & 3;        // row quarter: rows [32*wm, 32*wm+32)
    const int wn = w >> 2;       // col quarter: cols [64*wn, 64*wn+64)

    int* sdst = (int*)(sm + SM_IDS);
    int* ssrc = sdst + 128;
    float* sb2 = (float*)(sm + SM_B2);
    float* sb3 = (float*)(sm + SM_B3);

    if (t < 128) {
        sdst[t] = dst[blockIdx.x * 128 + t];
        ssrc[t] = src[blockIdx.x * 128 + t];
    }
    if (t < 256) {
        sb2[t] = b2[t];
        sb3[t] = b3[t];
    }
    __syncthreads();

    // ---- build A = fp16(relu(P[dst] + Q[src])) : 4 threads per edge row ----
    {
        const int e = t & 127, h = t >> 7;        // h in 0..3, 64 cols each
        const int de = sdst[e], se = ssrc[e];
        const float4* Pr = reinterpret_cast<const float4*>(P) + (size_t)de * 64 + h * 16;
        const float4* Qr = reinterpret_cast<const float4*>(Q) + (size_t)se * 64 + h * 16;
        const uint32_t arow = (uint32_t)e * AROW + (uint32_t)h * 128u;
#pragma unroll
        for (int j = 0; j < 8; j++) {
            float4 p0 = Pr[2 * j], q0 = Qr[2 * j];
            float4 p1 = Pr[2 * j + 1], q1 = Qr[2 * j + 1];
            union { uint4 u; __half2 h2[4]; } HI;
            HI.h2[0] = __floats2half2_rn(fmaxf(p0.x + q0.x, 0.f), fmaxf(p0.y + q0.y, 0.f));
            HI.h2[1] = __floats2half2_rn(fmaxf(p0.z + q0.z, 0.f), fmaxf(p0.w + q0.w, 0.f));
            HI.h2[2] = __floats2half2_rn(fmaxf(p1.x + q1.x, 0.f), fmaxf(p1.y + q1.y, 0.f));
            HI.h2[3] = __floats2half2_rn(fmaxf(p1.z + q1.z, 0.f), fmaxf(p1.w + q1.w, 0.f));
            *(uint4*)(sm + SM_AHI + arow + j * 16) = HI.u;
        }
    }

    // ---- accumulators: warp owns 32 rows x 64 cols : acc[mi][nj][4] ----
    float acc[2][8][4];
#pragma unroll
    for (int mi = 0; mi < 2; mi++)
#pragma unroll
        for (int nj = 0; nj < 8; nj++) {
            acc[mi][nj][0] = 0.f; acc[mi][nj][1] = 0.f;
            acc[mi][nj][2] = 0.f; acc[mi][nj][3] = 0.f;
        }

    // per-lane ldmatrix offsets
    const uint32_t a_base = sb + (uint32_t)((32 * wm + (l % 16)) * AROW + (l / 16) * 16);
    const uint32_t b_off = (uint32_t)((l % 16) * 32) +
                           (uint32_t)(((l / 16) * 16) ^ (((l % 16) & 4) ? 16 : 0));

    load_slice(0, sb, t, w2, w3); CP_COMMIT();
    load_slice(1, sb, t, w2, w3); CP_COMMIT();

#pragma unroll 1
    for (int s = 0; s < 32; s++) {
        if (s < 30) { CP_WAIT1(); } else { CP_WAIT0(); }
        __syncthreads();

        const int kt = s & 15;
        // load A fragments: 2 m-tiles
        uint32_t ah[2][4];
#pragma unroll
        for (int mi = 0; mi < 2; mi++) {
            const uint32_t aa = a_base + (uint32_t)(16 * mi * AROW) + kt * 32;
            LDSM4(ah[mi][0], ah[mi][1], ah[mi][2], ah[mi][3], aa + SM_AHI);
        }

        const uint32_t bbase = sb + SM_BBUF + (uint32_t)(s & 1) * 8192u + b_off
                             + (uint32_t)(wn * 2048);   // 4 chunks x 512B per wn
#pragma unroll
        for (int c = 0; c < 4; c++) {
            uint32_t bh0, bh1, bh2, bh3;
            LDSM4(bh0, bh1, bh2, bh3, bbase + c * 512);
#pragma unroll
            for (int mi = 0; mi < 2; mi++) {
                mma16816(acc[mi][2 * c],     ah[mi][0], ah[mi][1], ah[mi][2], ah[mi][3], bh0, bh2);
                mma16816(acc[mi][2 * c + 1], ah[mi][0], ah[mi][1], ah[mi][2], ah[mi][3], bh1, bh3);
            }
        }

        if (s == 15) {
            // all warps must finish reading A (slice-15 frags) before overwrite
            __syncthreads();
            // ---- epilogue 1: A := fp16(relu(D1 + b2)) for this warp's 32x64 tile ----
            const int cb = (l % 4) * 2;
#pragma unroll
            for (int mi = 0; mi < 2; mi++) {
                const int r0 = 32 * wm + 16 * mi + l / 4;
#pragma unroll
                for (int nj = 0; nj < 8; nj++) {
                    const int cn = 64 * wn + 8 * nj + cb;
                    const float bz0 = sb2[cn], bz1 = sb2[cn + 1];
                    __half2 hp0 = __floats2half2_rn(fmaxf(acc[mi][nj][0] + bz0, 0.f),
                                                    fmaxf(acc[mi][nj][1] + bz1, 0.f));
                    __half2 hp1 = __floats2half2_rn(fmaxf(acc[mi][nj][2] + bz0, 0.f),
                                                    fmaxf(acc[mi][nj][3] + bz1, 0.f));
                    *(uint32_t*)(sm + SM_AHI + r0 * AROW + cn * 2)       = *(uint32_t*)&hp0;
                    *(uint32_t*)(sm + SM_AHI + (r0 + 8) * AROW + cn * 2) = *(uint32_t*)&hp1;
                    acc[mi][nj][0] = 0.f; acc[mi][nj][1] = 0.f;
                    acc[mi][nj][2] = 0.f; acc[mi][nj][3] = 0.f;
                }
            }
        }
        __syncthreads();
        if (s + 2 < 32) {
            load_slice(s + 2, sb, t, w2, w3);
            CP_COMMIT();
        }
    }

    // ---- epilogue 2: agg[dst] += D2 + b3 ----
    {
        const int cb = (l % 4) * 2;
#pragma unroll
        for (int mi = 0; mi < 2; mi++) {
            const int er = 32 * wm + 16 * mi + l / 4;
            const int d0 = sdst[er], d1 = sdst[er + 8];
            float* a0 = agg + (size_t)d0 * Hh;
            float* a1 = agg + (size_t)d1 * Hh;
#pragma unroll
            for (int nj = 0; nj < 8; nj++) {
                const int cn = 64 * wn + 8 * nj + cb;
                const float bz0 = sb3[cn], bz1 = sb3[cn + 1];
                atomicAdd(a0 + cn,     acc[mi][nj][0] + bz0);
                atomicAdd(a0 + cn + 1, acc[mi][nj][1] + bz1);
                atomicAdd(a1 + cn,     acc[mi][nj][2] + bz0);
                atomicAdd(a1 + cn + 1, acc[mi][nj][3] + bz1);
            }
        }
    }
}

// ---------------- zero ----------------
__global__ void zero_kernel(float* p, int n) {
    int i = blockIdx.x * blockDim.x + threadIdx.x;
    if (i < n) p[i] = 0.f;
}

// ---------------- generic row-tiled fp32 GEMM ----------------
template <int NCOL, int RPB>
__global__ __launch_bounds__(256) void gemm_tiled(
    const float* __restrict__ A, int K,
    const float* __restrict__ W, const float* __restrict__ bias,
    float* __restrict__ C, int M, int do_relu)
{
    __shared__ float As[RPB * 256];
    const int row0 = blockIdx.x * RPB;
    const int tot = RPB * K;
    for (int idx = threadIdx.x; idx < tot; idx += 256) {
        int r = idx / K, k = idx - r * K;
        int gr = row0 + r;
        As[idx] = (gr < M) ? A[gr * K + k] : 0.f;
    }
    __syncthreads();

    const int RG = 256 / NCOL;
    const int RPT = RPB / RG;
    const int col = threadIdx.x % NCOL;
    const int rg = threadIdx.x / NCOL;

    float acc[RPT];
    float bv = bias ? bias[col] : 0.f;
#pragma unroll
    for (int i = 0; i < RPT; i++) acc[i] = bv;

    for (int k = 0; k < K; k += 4) {
        float wv0 = W[(k + 0) * NCOL + col];
        float wv1 = W[(k + 1) * NCOL + col];
        float wv2 = W[(k + 2) * NCOL + col];
        float wv3 = W[(k + 3) * NCOL + col];
#pragma unroll
        for (int i = 0; i < RPT; i++) {
            const float4 a = *(const float4*)&As[(rg + i * RG) * K + k];
            acc[i] = fmaf(a.x, wv0, acc[i]);
            acc[i] = fmaf(a.y, wv1, acc[i]);
            acc[i] = fmaf(a.z, wv2, acc[i]);
            acc[i] = fmaf(a.w, wv3, acc[i]);
        }
    }
#pragma unroll
    for (int i = 0; i < RPT; i++) {
        int gr = row0 + rg + i * RG;
        if (gr < M) {
            float v = acc[i];
            if (do_relu) v = fmaxf(v, 0.f);
            C[gr * NCOL + col] = v;
        }
    }
}

// ---------------- relu + layernorm per node ----------------
__device__ __forceinline__ float warp_sum(float v) {
#pragma unroll
    for (int o = 16; o > 0; o >>= 1) v += __shfl_xor_sync(0xFFFFFFFFu, v, o);
    return v;
}

__global__ __launch_bounds__(256) void relu_ln_kernel(
    const float* __restrict__ agg, const float* __restrict__ g,
    const float* __restrict__ b, float* __restrict__ xout)
{
    const int n = blockIdx.x;
    const int j = threadIdx.x;
    const int lane = j & 31, warp = j >> 5;
    __shared__ float red[8];
    __shared__ float s_mu, s_rstd;

    float v = fmaxf(agg[n * Hh + j], 0.f);
    float t = warp_sum(v);
    if (lane == 0) red[warp] = t;
    __syncthreads();
    if (j == 0) {
        float s = 0.f;
#pragma unroll
        for (int i = 0; i < 8; i++) s += red[i];
        s_mu = s / (float)Hh;
    }
    __syncthreads();
    float d = v - s_mu;
    float t2 = warp_sum(d * d);
    if (lane == 0) red[warp] = t2;
    __syncthreads();
    if (j == 0) {
        float s = 0.f;
#pragma unroll
        for (int i = 0; i < 8; i++) s += red[i];
        s_rstd = rsqrtf(s / (float)Hh + 1e-5f);
    }
    __syncthreads();
    xout[n * Hh + j] = d * s_rstd * g[j] + b[j];
}

// ---------------- assignment ----------------
__global__ __launch_bounds__(256) void assign_kernel(
    const float* __restrict__ t1, const float* __restrict__ aw2,
    const float* __restrict__ ab2, const float* __restrict__ u,
    float* __restrict__ s_out, float* __restrict__ entsum, float* __restrict__ colsum)
{
    __shared__ float rows[8 * Hh];
    __shared__ float blk_col[Ss];
    __shared__ float blk_ent;

    const int lane = threadIdx.x & 31, warp = threadIdx.x >> 5;
    if (threadIdx.x < Ss) blk_col[threadIdx.x] = 0.f;
    if (threadIdx.x == 0) blk_ent = 0.f;
    const int n0 = blockIdx.x * 8;
    for (int idx = threadIdx.x; idx < 8 * Hh; idx += 256)
        rows[idx] = t1[n0 * Hh + idx];
    __syncthreads();

    const int n = n0 + warp;
    float acc = ab2[lane];
    for (int k = 0; k < Hh; k += 4) {
        const float4 a = *(const float4*)&rows[warp * Hh + k];
        acc = fmaf(a.x, aw2[(k + 0) * Ss + lane], acc);
        acc = fmaf(a.y, aw2[(k + 1) * Ss + lane], acc);
        acc = fmaf(a.z, aw2[(k + 2) * Ss + lane], acc);
        acc = fmaf(a.w, aw2[(k + 3) * Ss + lane], acc);
    }
    float uu = u[n * Ss + lane];
    float gmb = -logf(-logf(uu + EPS_F) + EPS_F);
    float z = acc + gmb;
    float m = z;
#pragma unroll
    for (int o = 16; o > 0; o >>= 1) m = fmaxf(m, __shfl_xor_sync(0xFFFFFFFFu, m, o));
    float p = expf(z - m);
    float sum = warp_sum(p);
    float sv = p / sum;
    s_out[n * Ss + lane] = sv;

    float ent = warp_sum(sv * logf(sv + EPS_F));
    if (lane == 0) atomicAdd(&blk_ent, ent);
    atomicAdd(&blk_col[lane], sv);
    __syncthreads();
    if (threadIdx.x == 0) atomicAdd(entsum, blk_ent);
    if (threadIdx.x < Ss) atomicAdd(&colsum[threadIdx.x], blk_col[threadIdx.x]);
}

// ---------------- batch segment starts ----------------
__global__ void bstart_kernel(const int* __restrict__ batch, int* __restrict__ bstart) {
    int b = threadIdx.x;
    if (b > Bb) return;
    if (b == Bb) { bstart[Bb] = Nn; return; }
    int lo = 0, hi = Nn;
    while (lo < hi) {
        int mid = (lo + hi) >> 1;
        if (batch[mid] < b) lo = mid + 1; else hi = mid;
    }
    bstart[b] = lo;
}

// ---------------- pooling ----------------
__global__ __launch_bounds__(256) void pool_kernel(
    const float* __restrict__ x, const float* __restrict__ s_out,
    const int* __restrict__ bstart, float* __restrict__ pooled)
{
    const int b = blockIdx.x;
    const int chunk = blockIdx.y;
    const int NCHUNK = gridDim.y;
    const int lo = bstart[b], hi = bstart[b + 1];
    const int cnt = hi - lo;
    const int c0 = lo + (int)(((long long)cnt * chunk) / NCHUNK);
    const int c1 = lo + (int)(((long long)cnt * (chunk + 1)) / NCHUNK);

    __shared__ float ss[Ss];
    const int t = threadIdx.x;
    float acc[Ss];
#pragma unroll
    for (int sl = 0; sl < Ss; sl++) acc[sl] = 0.f;

    for (int n = c0; n < c1; n++) {
        __syncthreads();
        if (t < Ss) ss[t] = s_out[n * Ss + t];
        __syncthreads();
        float xv = x[n * Hh + t];
#pragma unroll
        for (int sl = 0; sl < Ss; sl++) acc[sl] = fmaf(xv, ss[sl], acc[sl]);
    }
#pragma unroll
    for (int sl = 0; sl < Ss; sl++)
        atomicAdd(&pooled[(b * Ss + sl) * Hh + t], acc[sl]);
}

// ---------------- final scalar loss ----------------
__global__ void finalize_kernel(const float* __restrict__ colsum,
                                const float* __restrict__ entsum,
                                float* __restrict__ out_loss)
{
    int l = threadIdx.x;
    float avg = colsum[l] / (float)Nn;
    float dv = avg * logf(avg + EPS_F);
    dv = warp_sum(dv);
    if (l == 0) {
        float entropy = -(entsum[0] / (float)Nn);
        out_loss[0] = entropy + dv;
    }
}

// ---------------- launch ----------------
extern "C" void kernel_launch(void* const* d_in, const int* in_sizes, int n_in,
                              void* d_out, int out_size)
{
    const float* x    = (const float*)d_in[0];
    const float* u    = (const float*)d_in[1];
    const int* eidx   = (const int*)d_in[2];
    const int* batch  = (const int*)d_in[3];
    const float* g1w1 = (const float*)d_in[4];
    const float* g1b1 = (const float*)d_in[5];
    const float* g1w2 = (const float*)d_in[6];
    const float* g1b2 = (const float*)d_in[7];
    const float* g1w3 = (const float*)d_in[8];
    const float* g1b3 = (const float*)d_in[9];
    const float* ln1g = (const float*)d_in[10];
    const float* ln1b = (const float*)d_in[11];
    const float* g2w1 = (const float*)d_in[12];
    const float* g2b1 = (const float*)d_in[13];
    const float* g2w2 = (const float*)d_in[14];
    const float* g2b2 = (const float*)d_in[15];
    const float* g2w3 = (const float*)d_in[16];
    const float* g2b3 = (const float*)d_in[17];
    const float* ln2g = (const float*)d_in[18];
    const float* ln2b = (const float*)d_in[19];
    const float* aw1  = (const float*)d_in[20];
    const float* ab1  = (const float*)d_in[21];
    const float* aw2  = (const float*)d_in[22];
    const float* ab2  = (const float*)d_in[23];
    const float* ow1  = (const float*)d_in[24];
    const float* ob1  = (const float*)d_in[25];
    const float* ow2  = (const float*)d_in[26];
    const float* ob2  = (const float*)d_in[27];

    const int* src = eidx;
    const int* dst = eidx + Ee;

    float* out = (float*)d_out;
    float* out_latent = out;
    float* out_s = out + Bb * Ss * Ll;
    float* out_loss = out + Bb * Ss * Ll + Nn * Ss;

    float *P, *Q, *agg, *xc, *pooled, *t2, *colsum, *entsum;
    int* bstart;
    __half* wbf;
    cudaGetSymbolAddress((void**)&P, d_P);
    cudaGetSymbolAddress((void**)&Q, d_Q);
    cudaGetSymbolAddress((void**)&agg, d_agg);
    cudaGetSymbolAddress((void**)&xc, d_x);
    cudaGetSymbolAddress((void**)&pooled, d_pooled);
    cudaGetSymbolAddress((void**)&t2, d_t2);
    cudaGetSymbolAddress((void**)&colsum, d_colsum);
    cudaGetSymbolAddress((void**)&entsum, d_entsum);
    cudaGetSymbolAddress((void**)&bstart, d_bstart);
    cudaGetSymbolAddress((void**)&wbf, d_wbf);

    cudaFuncSetAttribute(edge_mma_kernel, cudaFuncAttributeMaxDynamicSharedMemorySize, SM_TOT);

    const int NH = Nn * Hh;
    const int ZB = 256;
    const int WN = Hh * Hh;   // 65536

    // ---- zero accumulators ----
    zero_kernel<<<(NH + ZB - 1) / ZB, ZB>>>(agg, NH);
    zero_kernel<<<(Bb * Ss * Hh + ZB - 1) / ZB, ZB>>>(pooled, Bb * Ss * Hh);
    zero_kernel<<<1, ZB>>>(colsum, Ss);
    zero_kernel<<<1, ZB>>>(entsum, 1);

    // ---- transpose + convert weights to fp16 ([n][k] layout) ----
    wsplit_kernel<<<256, 256>>>(g1w2, wbf + 0 * WN);
    wsplit_kernel<<<256, 256>>>(g1w3, wbf + 1 * WN);
    wsplit_kernel<<<256, 256>>>(g2w2, wbf + 2 * WN);
    wsplit_kernel<<<256, 256>>>(g2w3, wbf + 3 * WN);

    // ---- GNN layer 1 ----
    gemm_tiled<Hh, 32><<<Nn / 32, 256>>>(x, Ff, g1w1, nullptr, P, Nn, 0);
    gemm_tiled<Hh, 32><<<Nn / 32, 256>>>(x, Ff, g1w1 + Ff * Hh, g1b1, Q, Nn, 0);
    edge_mma_kernel<<<Ee / 128, 512, SM_TOT>>>(src, dst, P, Q,
        wbf + 0 * WN, wbf + 1 * WN, g1b2, g1b3, agg);
    relu_ln_kernel<<<Nn, 256>>>(agg, ln1g, ln1b, xc);

    // ---- GNN layer 2 ----
    gemm_tiled<Hh, 32><<<Nn / 32, 256>>>(xc, Hh, g2w1, nullptr, P, Nn, 0);
    gemm_tiled<Hh, 32><<<Nn / 32, 256>>>(xc, Hh, g2w1 + Hh * Hh, g2b1, Q, Nn, 0);
    zero_kernel<<<(NH + ZB - 1) / ZB, ZB>>>(agg, NH);
    edge_mma_kernel<<<Ee / 128, 512, SM_TOT>>>(src, dst, P, Q,
        wbf + 2 * WN, wbf + 3 * WN, g2b2, g2b3, agg);
    relu_ln_kernel<<<Nn, 256>>>(agg, ln2g, ln2b, xc);

    // ---- assignment ----
    gemm_tiled<Hh, 32><<<Nn / 32, 256>>>(xc, Hh, aw1, ab1, P, Nn, 1);
    assign_kernel<<<Nn / 8, 256>>>(P, aw2, ab2, u, out_s, entsum, colsum);

    // ---- pooling ----
    bstart_kernel<<<1, 32>>>(batch, bstart);
    {
        dim3 grid(Bb, 8);
        pool_kernel<<<grid, 256>>>(xc, out_s, bstart, pooled);
    }

    // ---- output MLP ----
    gemm_tiled<Hh, 32><<<(Bb * Ss) / 32, 256>>>(pooled, Hh, ow1, ob1, t2, Bb * Ss, 1);
    gemm_tiled<Ll, 32><<<(Bb * Ss) / 32, 256>>>(t2, Hh, ow2, ob2, out_latent, Bb * Ss, 0);

    // ---- loss scalar ----
    finalize_kernel<<<1, 32>>>(colsum, entsum, out_loss);
}

// round 11
// speedup vs baseline: 3.4948x; 1.1182x over previous
#include <cuda_runtime.h>
#include <cuda_fp16.h>
#include <math.h>
#include <stdint.h>

#define Nn 20000
#define Ee 320000
#define Ff 64
#define Hh 256
#define Ss 32
#define Ll 128
#define Bb 16
#define EPS_F 1e-9f

// ---------------- scratch (device globals; no allocation allowed) ----------------
__device__ float d_P[Nn * Hh];
__device__ float d_Q[Nn * Hh];
__device__ float d_agg[Nn * Hh];
__device__ float d_x[Nn * Hh];
__device__ float d_pooled[Bb * Ss * Hh];
__device__ float d_t2[Bb * Ss * Hh];
__device__ float d_colsum[Ss];
__device__ float d_entsum[1];
__device__ int   d_bstart[Bb + 1];
__device__ __align__(256) __half d_wbf[4 * Hh * Hh];    // edge weights [w2,w3] x 2 layers (fp16)
__device__ __align__(256) __half d_wnode[458752];       // node weights hi/lo splits

// ================= warp-MMA helpers (sm_80-compatible PTX) =================
__device__ __forceinline__ uint32_t smem_u32(const void* p) {
    uint32_t a;
    asm("{ .reg .u64 t; cvta.to.shared.u64 t, %1; cvt.u32.u64 %0, t; }" : "=r"(a) : "l"(p));
    return a;
}
__device__ __forceinline__ void cp16(uint32_t saddr, const void* g) {
    asm volatile("cp.async.cg.shared.global [%0], [%1], 16;" :: "r"(saddr), "l"(g));
}
#define CP_COMMIT() asm volatile("cp.async.commit_group;" ::: "memory")
#define CP_WAIT1()  asm volatile("cp.async.wait_group 1;" ::: "memory")
#define CP_WAIT0()  asm volatile("cp.async.wait_group 0;" ::: "memory")

#define LDSM4(r0, r1, r2, r3, addr) \
    asm volatile("ldmatrix.sync.aligned.m8n8.x4.shared.b16 {%0,%1,%2,%3}, [%4];" \
        : "=r"(r0), "=r"(r1), "=r"(r2), "=r"(r3) : "r"(addr))

__device__ __forceinline__ void mma16816(float* c,
    uint32_t a0, uint32_t a1, uint32_t a2, uint32_t a3, uint32_t b0, uint32_t b1) {
    asm volatile("mma.sync.aligned.m16n8k16.row.col.f32.f16.f16.f32 "
        "{%0,%1,%2,%3}, {%4,%5,%6,%7}, {%8,%9}, {%0,%1,%2,%3};"
        : "+f"(c[0]), "+f"(c[1]), "+f"(c[2]), "+f"(c[3])
        : "r"(a0), "r"(a1), "r"(a2), "r"(a3), "r"(b0), "r"(b1));
}

// ================= SMEM layout for edge kernel (bytes) =================
#define AROW    528                      // 256 fp16 + 16B pad (conflict-free ldmatrix)
#define SM_AHI  0                        // 128 * 528 = 67584
#define SM_BBUF 67584                    // 2 buffers x 8KB = 16384
#define SM_IDS  83968                    // sdst[128], ssrc[128]
#define SM_B2   84992
#define SM_B3   86016
#define SM_TOT  87040

// ---------------- edge weight transpose + fp16 convert ----------------
__global__ void wsplit_kernel(const float* __restrict__ w, __half* __restrict__ hi) {
    int i = blockIdx.x * 256 + threadIdx.x;   // i = n*256 + k
    int n = i >> 8, k = i & 255;
    hi[i] = __float2half_rn(w[k * Hh + n]);
}

// ---------------- node weight transpose + fp16 hi/lo split ----------------
__global__ void wsplit_node(const float* __restrict__ w, int K,
                            __half* __restrict__ hi, __half* __restrict__ lo) {
    int i = blockIdx.x * 256 + threadIdx.x;   // i = n*K + k
    int n = i / K, k = i - n * K;
    float v = w[k * Hh + n];
    __half h = __float2half_rn(v);
    hi[i] = h;
    lo[i] = __float2half_rn(v - __half2float(h));
}

// ---------------- edge B-slice loader ----------------
__device__ __forceinline__ void load_slice(int s, uint32_t sb, int t,
    const __half* w2, const __half* w3)
{
    const __half* Wh = (s < 16) ? w2 : w3;
    const int kt = s & 15;
    const uint32_t base = sb + SM_BBUF + (uint32_t)(s & 1) * 8192u;
    const int n = t >> 1;
    const int h = t & 1;
    const char* gh = (const char*)(Wh + (size_t)n * Hh + kt * 16) + h * 16;
    const uint32_t sw4 = (n & 4) ? 16u : 0u;
    const uint32_t doff = base + (uint32_t)n * 32u + (((uint32_t)h * 16u) ^ sw4);
    cp16(doff, gh);
}

// ---------------- fused tensor-core edge MLP (16 warps, 32x64 warp tiles, fp16 1-MMA) ---------
__global__ __launch_bounds__(512, 1) void edge_mma_kernel(
    const int* __restrict__ src, const int* __restrict__ dst,
    const float* __restrict__ P, const float* __restrict__ Q,
    const __half* __restrict__ w2, const __half* __restrict__ w3,
    const float* __restrict__ b2, const float* __restrict__ b3,
    float* __restrict__ agg)
{
    extern __shared__ char sm[];
    const uint32_t sb = smem_u32(sm);
    const int t = threadIdx.x;
    const int w = t >> 5, l = t & 31;
    const int wm = w & 3;
    const int wn = w >> 2;

    int* sdst = (int*)(sm + SM_IDS);
    int* ssrc = sdst + 128;
    float* sb2 = (float*)(sm + SM_B2);
    float* sb3 = (float*)(sm + SM_B3);

    if (t < 128) {
        sdst[t] = dst[blockIdx.x * 128 + t];
        ssrc[t] = src[blockIdx.x * 128 + t];
    }
    if (t < 256) {
        sb2[t] = b2[t];
        sb3[t] = b3[t];
    }
    __syncthreads();

    // ---- build A = fp16(relu(P[dst] + Q[src])) ----
    {
        const int e = t & 127, h = t >> 7;
        const int de = sdst[e], se = ssrc[e];
        const float4* Pr = reinterpret_cast<const float4*>(P) + (size_t)de * 64 + h * 16;
        const float4* Qr = reinterpret_cast<const float4*>(Q) + (size_t)se * 64 + h * 16;
        const uint32_t arow = (uint32_t)e * AROW + (uint32_t)h * 128u;
#pragma unroll
        for (int j = 0; j < 8; j++) {
            float4 p0 = Pr[2 * j], q0 = Qr[2 * j];
            float4 p1 = Pr[2 * j + 1], q1 = Qr[2 * j + 1];
            union { uint4 u; __half2 h2[4]; } HI;
            HI.h2[0] = __floats2half2_rn(fmaxf(p0.x + q0.x, 0.f), fmaxf(p0.y + q0.y, 0.f));
            HI.h2[1] = __floats2half2_rn(fmaxf(p0.z + q0.z, 0.f), fmaxf(p0.w + q0.w, 0.f));
            HI.h2[2] = __floats2half2_rn(fmaxf(p1.x + q1.x, 0.f), fmaxf(p1.y + q1.y, 0.f));
            HI.h2[3] = __floats2half2_rn(fmaxf(p1.z + q1.z, 0.f), fmaxf(p1.w + q1.w, 0.f));
            *(uint4*)(sm + SM_AHI + arow + j * 16) = HI.u;
        }
    }

    float acc[2][8][4];
#pragma unroll
    for (int mi = 0; mi < 2; mi++)
#pragma unroll
        for (int nj = 0; nj < 8; nj++) {
            acc[mi][nj][0] = 0.f; acc[mi][nj][1] = 0.f;
            acc[mi][nj][2] = 0.f; acc[mi][nj][3] = 0.f;
        }

    const uint32_t a_base = sb + (uint32_t)((32 * wm + (l % 16)) * AROW + (l / 16) * 16);
    const uint32_t b_off = (uint32_t)((l % 16) * 32) +
                           (uint32_t)(((l / 16) * 16) ^ (((l % 16) & 4) ? 16 : 0));

    load_slice(0, sb, t, w2, w3); CP_COMMIT();
    load_slice(1, sb, t, w2, w3); CP_COMMIT();

#pragma unroll 1
    for (int s = 0; s < 32; s++) {
        if (s < 30) { CP_WAIT1(); } else { CP_WAIT0(); }
        __syncthreads();

        const int kt = s & 15;
        uint32_t ah[2][4];
#pragma unroll
        for (int mi = 0; mi < 2; mi++) {
            const uint32_t aa = a_base + (uint32_t)(16 * mi * AROW) + kt * 32;
            LDSM4(ah[mi][0], ah[mi][1], ah[mi][2], ah[mi][3], aa + SM_AHI);
        }

        const uint32_t bbase = sb + SM_BBUF + (uint32_t)(s & 1) * 8192u + b_off
                             + (uint32_t)(wn * 2048);
#pragma unroll
        for (int c = 0; c < 4; c++) {
            uint32_t bh0, bh1, bh2, bh3;
            LDSM4(bh0, bh1, bh2, bh3, bbase + c * 512);
#pragma unroll
            for (int mi = 0; mi < 2; mi++) {
                mma16816(acc[mi][2 * c],     ah[mi][0], ah[mi][1], ah[mi][2], ah[mi][3], bh0, bh2);
                mma16816(acc[mi][2 * c + 1], ah[mi][0], ah[mi][1], ah[mi][2], ah[mi][3], bh1, bh3);
            }
        }

        if (s == 15) {
            __syncthreads();
            const int cb = (l % 4) * 2;
#pragma unroll
            for (int mi = 0; mi < 2; mi++) {
                const int r0 = 32 * wm + 16 * mi + l / 4;
#pragma unroll
                for (int nj = 0; nj < 8; nj++) {
                    const int cn = 64 * wn + 8 * nj + cb;
                    const float bz0 = sb2[cn], bz1 = sb2[cn + 1];
                    __half2 hp0 = __floats2half2_rn(fmaxf(acc[mi][nj][0] + bz0, 0.f),
                                                    fmaxf(acc[mi][nj][1] + bz1, 0.f));
                    __half2 hp1 = __floats2half2_rn(fmaxf(acc[mi][nj][2] + bz0, 0.f),
                                                    fmaxf(acc[mi][nj][3] + bz1, 0.f));
                    *(uint32_t*)(sm + SM_AHI + r0 * AROW + cn * 2)       = *(uint32_t*)&hp0;
                    *(uint32_t*)(sm + SM_AHI + (r0 + 8) * AROW + cn * 2) = *(uint32_t*)&hp1;
                    acc[mi][nj][0] = 0.f; acc[mi][nj][1] = 0.f;
                    acc[mi][nj][2] = 0.f; acc[mi][nj][3] = 0.f;
                }
            }
        }
        __syncthreads();
        if (s + 2 < 32) {
            load_slice(s + 2, sb, t, w2, w3);
            CP_COMMIT();
        }
    }

    // ---- epilogue 2: agg[dst] += D2 + b3 ----
    {
        const int cb = (l % 4) * 2;
#pragma unroll
        for (int mi = 0; mi < 2; mi++) {
            const int er = 32 * wm + 16 * mi + l / 4;
            const int d0 = sdst[er], d1 = sdst[er + 8];
            float* a0 = agg + (size_t)d0 * Hh;
            float* a1 = agg + (size_t)d1 * Hh;
#pragma unroll
            for (int nj = 0; nj < 8; nj++) {
                const int cn = 64 * wn + 8 * nj + cb;
                const float bz0 = sb3[cn], bz1 = sb3[cn + 1];
                atomicAdd(a0 + cn,     acc[mi][nj][0] + bz0);
                atomicAdd(a0 + cn + 1, acc[mi][nj][1] + bz1);
                atomicAdd(a1 + cn,     acc[mi][nj][2] + bz0);
                atomicAdd(a1 + cn + 1, acc[mi][nj][3] + bz1);
            }
        }
    }
}

// ---------------- tensor-core node GEMM: C[M,256] = act(A[M,K] @ W + bias) ----------------
// W pre-split fp16 hi/lo, [n][k] layout. 3-product: Ahi*Whi + Ahi*Wlo + Alo*Whi.
template <int K, bool RELU>
__global__ __launch_bounds__(512, 1) void gemm_mma(
    const float* __restrict__ A,
    const __half* __restrict__ Whi, const __half* __restrict__ Wlo,
    const float* __restrict__ bias, float* __restrict__ C, int M)
{
    constexpr int AROWK = K * 2 + 16;
    constexpr int SA_HI = 0;
    constexpr int SA_LO = 128 * AROWK;
    constexpr int S_BB  = 2 * 128 * AROWK;
    constexpr int S_BIAS = S_BB + 32768;
    constexpr int NS = K / 16;

    extern __shared__ char sm[];
    const uint32_t sb = smem_u32(sm);
    const int t = threadIdx.x;
    const int w = t >> 5, l = t & 31;
    const int wm = w & 3;
    const int wn = w >> 2;

    float* sbias = (float*)(sm + S_BIAS);
    if (t < 256) sbias[t] = bias ? bias[t] : 0.f;

    // ---- load + split A rows into hi/lo fp16 ----
    {
        const int e = t & 127, h = t >> 7;
        const int grow = blockIdx.x * 128 + e;
        constexpr int cpt = K / 4;                  // cols per thread
        const uint32_t arow = (uint32_t)e * AROWK + (uint32_t)h * (cpt * 2);
        if (grow < M) {
            const float4* Ar = reinterpret_cast<const float4*>(A + (size_t)grow * K) + h * (cpt / 4);
#pragma unroll
            for (int j = 0; j < cpt / 8; j++) {
                float4 a0 = Ar[2 * j], a1 = Ar[2 * j + 1];
                float v[8] = { a0.x, a0.y, a0.z, a0.w, a1.x, a1.y, a1.z, a1.w };
                union { uint4 u; __half2 h2[4]; } HI, LO;
#pragma unroll
                for (int p = 0; p < 4; p++) {
                    float v0 = v[2 * p], v1 = v[2 * p + 1];
                    __half h0 = __float2half_rn(v0), h1 = __float2half_rn(v1);
                    HI.h2[p] = __halves2half2(h0, h1);
                    LO.h2[p] = __floats2half2_rn(v0 - __half2float(h0),
                                                 v1 - __half2float(h1));
                }
                *(uint4*)(sm + SA_HI + arow + j * 16) = HI.u;
                *(uint4*)(sm + SA_LO + arow + j * 16) = LO.u;
            }
        } else {
            const uint4 z = make_uint4(0, 0, 0, 0);
#pragma unroll
            for (int j = 0; j < cpt / 8; j++) {
                *(uint4*)(sm + SA_HI + arow + j * 16) = z;
                *(uint4*)(sm + SA_LO + arow + j * 16) = z;
            }
        }
    }

    float acc[2][8][4];
#pragma unroll
    for (int mi = 0; mi < 2; mi++)
#pragma unroll
        for (int nj = 0; nj < 8; nj++) {
            acc[mi][nj][0] = 0.f; acc[mi][nj][1] = 0.f;
            acc[mi][nj][2] = 0.f; acc[mi][nj][3] = 0.f;
        }

    const uint32_t a_base = sb + (uint32_t)((32 * wm + (l % 16)) * AROWK + (l / 16) * 16);
    const uint32_t b_off = (uint32_t)((l % 16) * 32) +
                           (uint32_t)(((l / 16) * 16) ^ (((l % 16) & 4) ? 16 : 0));

    // B slice loader (hi + lo)
    auto load_b = [&](int s) {
        const uint32_t base = sb + S_BB + (uint32_t)(s & 1) * 16384u;
        const int n = t >> 1;
        const int h = t & 1;
        const char* gh = (const char*)(Whi + (size_t)n * K + s * 16) + h * 16;
        const char* gl = (const char*)(Wlo + (size_t)n * K + s * 16) + h * 16;
        const uint32_t sw4 = (n & 4) ? 16u : 0u;
        const uint32_t doff = base + (uint32_t)n * 32u + (((uint32_t)h * 16u) ^ sw4);
        cp16(doff, gh);
        cp16(doff + 8192u, gl);
    };

    load_b(0); CP_COMMIT();
    load_b(1); CP_COMMIT();

#pragma unroll 1
    for (int s = 0; s < NS; s++) {
        if (s < NS - 2) { CP_WAIT1(); } else { CP_WAIT0(); }
        __syncthreads();

        uint32_t ah[2][4], al[2][4];
#pragma unroll
        for (int mi = 0; mi < 2; mi++) {
            const uint32_t aa = a_base + (uint32_t)(16 * mi * AROWK) + s * 32;
            LDSM4(ah[mi][0], ah[mi][1], ah[mi][2], ah[mi][3], aa + SA_HI);
            LDSM4(al[mi][0], al[mi][1], al[mi][2], al[mi][3], aa + SA_LO);
        }

        const uint32_t bbase = sb + S_BB + (uint32_t)(s & 1) * 16384u + b_off
                             + (uint32_t)(wn * 2048);
#pragma unroll
        for (int c = 0; c < 4; c++) {
            uint32_t bh0, bh1, bh2, bh3, bl0, bl1, bl2, bl3;
            LDSM4(bh0, bh1, bh2, bh3, bbase + c * 512);
            LDSM4(bl0, bl1, bl2, bl3, bbase + 8192 + c * 512);
#pragma unroll
            for (int mi = 0; mi < 2; mi++) {
                float* c0 = acc[mi][2 * c];
                float* c1 = acc[mi][2 * c + 1];
                mma16816(c0, ah[mi][0], ah[mi][1], ah[mi][2], ah[mi][3], bh0, bh2);
                mma16816(c0, ah[mi][0], ah[mi][1], ah[mi][2], ah[mi][3], bl0, bl2);
                mma16816(c0, al[mi][0], al[mi][1], al[mi][2], al[mi][3], bh0, bh2);
                mma16816(c1, ah[mi][0], ah[mi][1], ah[mi][2], ah[mi][3], bh1, bh3);
                mma16816(c1, ah[mi][0], ah[mi][1], ah[mi][2], ah[mi][3], bl1, bl3);
                mma16816(c1, al[mi][0], al[mi][1], al[mi][2], al[mi][3], bh1, bh3);
            }
        }
        __syncthreads();
        if (s + 2 < NS) {
            load_b(s + 2);
            CP_COMMIT();
        }
    }

    // ---- epilogue: bias (+relu) -> C ----
    {
        const int cb = (l % 4) * 2;
#pragma unroll
        for (int mi = 0; mi < 2; mi++) {
            const int r0 = 32 * wm + 16 * mi + l / 4;
            const int g0 = blockIdx.x * 128 + r0;
            const int g1 = g0 + 8;
#pragma unroll
            for (int nj = 0; nj < 8; nj++) {
                const int cn = 64 * wn + 8 * nj + cb;
                const float bz0 = sbias[cn], bz1 = sbias[cn + 1];
                float v0 = acc[mi][nj][0] + bz0, v1 = acc[mi][nj][1] + bz1;
                float v2 = acc[mi][nj][2] + bz0, v3 = acc[mi][nj][3] + bz1;
                if (RELU) {
                    v0 = fmaxf(v0, 0.f); v1 = fmaxf(v1, 0.f);
                    v2 = fmaxf(v2, 0.f); v3 = fmaxf(v3, 0.f);
                }
                if (g0 < M) { float2 o = make_float2(v0, v1); *(float2*)(C + (size_t)g0 * Hh + cn) = o; }
                if (g1 < M) { float2 o = make_float2(v2, v3); *(float2*)(C + (size_t)g1 * Hh + cn) = o; }
            }
        }
    }
}

// ---------------- zero ----------------
__global__ void zero_kernel(float* p, int n) {
    int i = blockIdx.x * blockDim.x + threadIdx.x;
    if (i < n) p[i] = 0.f;
}

// ---------------- generic row-tiled fp32 GEMM (small outputs only) ----------------
template <int NCOL, int RPB>
__global__ __launch_bounds__(256) void gemm_tiled(
    const float* __restrict__ A, int K,
    const float* __restrict__ W, const float* __restrict__ bias,
    float* __restrict__ C, int M, int do_relu)
{
    __shared__ float As[RPB * 256];
    const int row0 = blockIdx.x * RPB;
    const int tot = RPB * K;
    for (int idx = threadIdx.x; idx < tot; idx += 256) {
        int r = idx / K, k = idx - r * K;
        int gr = row0 + r;
        As[idx] = (gr < M) ? A[gr * K + k] : 0.f;
    }
    __syncthreads();

    const int RG = 256 / NCOL;
    const int RPT = RPB / RG;
    const int col = threadIdx.x % NCOL;
    const int rg = threadIdx.x / NCOL;

    float acc[RPT];
    float bv = bias ? bias[col] : 0.f;
#pragma unroll
    for (int i = 0; i < RPT; i++) acc[i] = bv;

    for (int k = 0; k < K; k += 4) {
        float wv0 = W[(k + 0) * NCOL + col];
        float wv1 = W[(k + 1) * NCOL + col];
        float wv2 = W[(k + 2) * NCOL + col];
        float wv3 = W[(k + 3) * NCOL + col];
#pragma unroll
        for (int i = 0; i < RPT; i++) {
            const float4 a = *(const float4*)&As[(rg + i * RG) * K + k];
            acc[i] = fmaf(a.x, wv0, acc[i]);
            acc[i] = fmaf(a.y, wv1, acc[i]);
            acc[i] = fmaf(a.z, wv2, acc[i]);
            acc[i] = fmaf(a.w, wv3, acc[i]);
        }
    }
#pragma unroll
    for (int i = 0; i < RPT; i++) {
        int gr = row0 + rg + i * RG;
        if (gr < M) {
            float v = acc[i];
            if (do_relu) v = fmaxf(v, 0.f);
            C[gr * NCOL + col] = v;
        }
    }
}

// ---------------- relu + layernorm per node ----------------
__device__ __forceinline__ float warp_sum(float v) {
#pragma unroll
    for (int o = 16; o > 0; o >>= 1) v += __shfl_xor_sync(0xFFFFFFFFu, v, o);
    return v;
}

__global__ __launch_bounds__(256) void relu_ln_kernel(
    const float* __restrict__ agg, const float* __restrict__ g,
    const float* __restrict__ b, float* __restrict__ xout)
{
    const int n = blockIdx.x;
    const int j = threadIdx.x;
    const int lane = j & 31, warp = j >> 5;
    __shared__ float red[8];
    __shared__ float s_mu, s_rstd;

    float v = fmaxf(agg[n * Hh + j], 0.f);
    float t = warp_sum(v);
    if (lane == 0) red[warp] = t;
    __syncthreads();
    if (j == 0) {
        float s = 0.f;
#pragma unroll
        for (int i = 0; i < 8; i++) s += red[i];
        s_mu = s / (float)Hh;
    }
    __syncthreads();
    float d = v - s_mu;
    float t2 = warp_sum(d * d);
    if (lane == 0) red[warp] = t2;
    __syncthreads();
    if (j == 0) {
        float s = 0.f;
#pragma unroll
        for (int i = 0; i < 8; i++) s += red[i];
        s_rstd = rsqrtf(s / (float)Hh + 1e-5f);
    }
    __syncthreads();
    xout[n * Hh + j] = d * s_rstd * g[j] + b[j];
}

// ---------------- assignment ----------------
__global__ __launch_bounds__(256) void assign_kernel(
    const float* __restrict__ t1, const float* __restrict__ aw2,
    const float* __restrict__ ab2, const float* __restrict__ u,
    float* __restrict__ s_out, float* __restrict__ entsum, float* __restrict__ colsum)
{
    __shared__ float rows[8 * Hh];
    __shared__ float blk_col[Ss];
    __shared__ float blk_ent;

    const int lane = threadIdx.x & 31, warp = threadIdx.x >> 5;
    if (threadIdx.x < Ss) blk_col[threadIdx.x] = 0.f;
    if (threadIdx.x == 0) blk_ent = 0.f;
    const int n0 = blockIdx.x * 8;
    for (int idx = threadIdx.x; idx < 8 * Hh; idx += 256)
        rows[idx] = t1[n0 * Hh + idx];
    __syncthreads();

    const int n = n0 + warp;
    float acc = ab2[lane];
    for (int k = 0; k < Hh; k += 4) {
        const float4 a = *(const float4*)&rows[warp * Hh + k];
        acc = fmaf(a.x, aw2[(k + 0) * Ss + lane], acc);
        acc = fmaf(a.y, aw2[(k + 1) * Ss + lane], acc);
        acc = fmaf(a.z, aw2[(k + 2) * Ss + lane], acc);
        acc = fmaf(a.w, aw2[(k + 3) * Ss + lane], acc);
    }
    float uu = u[n * Ss + lane];
    float gmb = -logf(-logf(uu + EPS_F) + EPS_F);
    float z = acc + gmb;
    float m = z;
#pragma unroll
    for (int o = 16; o > 0; o >>= 1) m = fmaxf(m, __shfl_xor_sync(0xFFFFFFFFu, m, o));
    float p = expf(z - m);
    float sum = warp_sum(p);
    float sv = p / sum;
    s_out[n * Ss + lane] = sv;

    float ent = warp_sum(sv * logf(sv + EPS_F));
    if (lane == 0) atomicAdd(&blk_ent, ent);
    atomicAdd(&blk_col[lane], sv);
    __syncthreads();
    if (threadIdx.x == 0) atomicAdd(entsum, blk_ent);
    if (threadIdx.x < Ss) atomicAdd(&colsum[threadIdx.x], blk_col[threadIdx.x]);
}

// ---------------- batch segment starts ----------------
__global__ void bstart_kernel(const int* __restrict__ batch, int* __restrict__ bstart) {
    int b = threadIdx.x;
    if (b > Bb) return;
    if (b == Bb) { bstart[Bb] = Nn; return; }
    int lo = 0, hi = Nn;
    while (lo < hi) {
        int mid = (lo + hi) >> 1;
        if (batch[mid] < b) lo = mid + 1; else hi = mid;
    }
    bstart[b] = lo;
}

// ---------------- pooling ----------------
__global__ __launch_bounds__(256) void pool_kernel(
    const float* __restrict__ x, const float* __restrict__ s_out,
    const int* __restrict__ bstart, float* __restrict__ pooled)
{
    const int b = blockIdx.x;
    const int chunk = blockIdx.y;
    const int NCHUNK = gridDim.y;
    const int lo = bstart[b], hi = bstart[b + 1];
    const int cnt = hi - lo;
    const int c0 = lo + (int)(((long long)cnt * chunk) / NCHUNK);
    const int c1 = lo + (int)(((long long)cnt * (chunk + 1)) / NCHUNK);

    __shared__ float ss[Ss];
    const int t = threadIdx.x;
    float acc[Ss];
#pragma unroll
    for (int sl = 0; sl < Ss; sl++) acc[sl] = 0.f;

    for (int n = c0; n < c1; n++) {
        __syncthreads();
        if (t < Ss) ss[t] = s_out[n * Ss + t];
        __syncthreads();
        float xv = x[n * Hh + t];
#pragma unroll
        for (int sl = 0; sl < Ss; sl++) acc[sl] = fmaf(xv, ss[sl], acc[sl]);
    }
#pragma unroll
    for (int sl = 0; sl < Ss; sl++)
        atomicAdd(&pooled[(b * Ss + sl) * Hh + t], acc[sl]);
}

// ---------------- final scalar loss ----------------
__global__ void finalize_kernel(const float* __restrict__ colsum,
                                const float* __restrict__ entsum,
                                float* __restrict__ out_loss)
{
    int l = threadIdx.x;
    float avg = colsum[l] / (float)Nn;
    float dv = avg * logf(avg + EPS_F);
    dv = warp_sum(dv);
    if (l == 0) {
        float entropy = -(entsum[0] / (float)Nn);
        out_loss[0] = entropy + dv;
    }
}

// ---------------- launch ----------------
extern "C" void kernel_launch(void* const* d_in, const int* in_sizes, int n_in,
                              void* d_out, int out_size)
{
    const float* x    = (const float*)d_in[0];
    const float* u    = (const float*)d_in[1];
    const int* eidx   = (const int*)d_in[2];
    const int* batch  = (const int*)d_in[3];
    const float* g1w1 = (const float*)d_in[4];
    const float* g1b1 = (const float*)d_in[5];
    const float* g1w2 = (const float*)d_in[6];
    const float* g1b2 = (const float*)d_in[7];
    const float* g1w3 = (const float*)d_in[8];
    const float* g1b3 = (const float*)d_in[9];
    const float* ln1g = (const float*)d_in[10];
    const float* ln1b = (const float*)d_in[11];
    const float* g2w1 = (const float*)d_in[12];
    const float* g2b1 = (const float*)d_in[13];
    const float* g2w2 = (const float*)d_in[14];
    const float* g2b2 = (const float*)d_in[15];
    const float* g2w3 = (const float*)d_in[16];
    const float* g2b3 = (const float*)d_in[17];
    const float* ln2g = (const float*)d_in[18];
    const float* ln2b = (const float*)d_in[19];
    const float* aw1  = (const float*)d_in[20];
    const float* ab1  = (const float*)d_in[21];
    const float* aw2  = (const float*)d_in[22];
    const float* ab2  = (const float*)d_in[23];
    const float* ow1  = (const float*)d_in[24];
    const float* ob1  = (const float*)d_in[25];
    const float* ow2  = (const float*)d_in[26];
    const float* ob2  = (const float*)d_in[27];

    const int* src = eidx;
    const int* dst = eidx + Ee;

    float* out = (float*)d_out;
    float* out_latent = out;
    float* out_s = out + Bb * Ss * Ll;
    float* out_loss = out + Bb * Ss * Ll + Nn * Ss;

    float *P, *Q, *agg, *xc, *pooled, *t2, *colsum, *entsum;
    int* bstart;
    __half *wbf, *wn;
    cudaGetSymbolAddress((void**)&P, d_P);
    cudaGetSymbolAddress((void**)&Q, d_Q);
    cudaGetSymbolAddress((void**)&agg, d_agg);
    cudaGetSymbolAddress((void**)&xc, d_x);
    cudaGetSymbolAddress((void**)&pooled, d_pooled);
    cudaGetSymbolAddress((void**)&t2, d_t2);
    cudaGetSymbolAddress((void**)&colsum, d_colsum);
    cudaGetSymbolAddress((void**)&entsum, d_entsum);
    cudaGetSymbolAddress((void**)&bstart, d_bstart);
    cudaGetSymbolAddress((void**)&wbf, d_wbf);
    cudaGetSymbolAddress((void**)&wn, d_wnode);

    cudaFuncSetAttribute(edge_mma_kernel, cudaFuncAttributeMaxDynamicSharedMemorySize, SM_TOT);
    // gemm_mma smem: K=64 -> 2*128*144 + 32768 + 1024 = 70656 ; K=256 -> 2*128*528 + 32768 + 1024 = 168960
    cudaFuncSetAttribute(gemm_mma<64, false>,  cudaFuncAttributeMaxDynamicSharedMemorySize, 70656);
    cudaFuncSetAttribute(gemm_mma<256, false>, cudaFuncAttributeMaxDynamicSharedMemorySize, 168960);
    cudaFuncSetAttribute(gemm_mma<256, true>,  cudaFuncAttributeMaxDynamicSharedMemorySize, 168960);

    const int NH = Nn * Hh;
    const int ZB = 256;
    const int WN = Hh * Hh;   // 65536
    const int GB = (Nn + 127) / 128;   // 157

    // node weight split offsets (halfs)
    __half* g1Ph = wn + 0;       __half* g1Pl = wn + 16384;
    __half* g1Qh = wn + 32768;   __half* g1Ql = wn + 49152;
    __half* g2Ph = wn + 65536;   __half* g2Pl = wn + 131072;
    __half* g2Qh = wn + 196608;  __half* g2Ql = wn + 262144;
    __half* awh  = wn + 327680;  __half* awl  = wn + 393216;

    // ---- zero accumulators ----
    zero_kernel<<<(NH + ZB - 1) / ZB, ZB>>>(agg, NH);
    zero_kernel<<<(Bb * Ss * Hh + ZB - 1) / ZB, ZB>>>(pooled, Bb * Ss * Hh);
    zero_kernel<<<1, ZB>>>(colsum, Ss);
    zero_kernel<<<1, ZB>>>(entsum, 1);

    // ---- edge weights: transpose + fp16 ----
    wsplit_kernel<<<256, 256>>>(g1w2, wbf + 0 * WN);
    wsplit_kernel<<<256, 256>>>(g1w3, wbf + 1 * WN);
    wsplit_kernel<<<256, 256>>>(g2w2, wbf + 2 * WN);
    wsplit_kernel<<<256, 256>>>(g2w3, wbf + 3 * WN);

    // ---- node weights: transpose + fp16 hi/lo split ----
    wsplit_node<<<64, 256>>>(g1w1,            64,  g1Ph, g1Pl);
    wsplit_node<<<64, 256>>>(g1w1 + 64 * Hh,  64,  g1Qh, g1Ql);
    wsplit_node<<<256, 256>>>(g2w1,           256, g2Ph, g2Pl);
    wsplit_node<<<256, 256>>>(g2w1 + Hh * Hh, 256, g2Qh, g2Ql);
    wsplit_node<<<256, 256>>>(aw1,            256, awh,  awl);

    // ---- GNN layer 1 ----
    gemm_mma<64, false><<<GB, 512, 70656>>>(x, g1Ph, g1Pl, nullptr, P, Nn);
    gemm_mma<64, false><<<GB, 512, 70656>>>(x, g1Qh, g1Ql, g1b1, Q, Nn);
    edge_mma_kernel<<<Ee / 128, 512, SM_TOT>>>(src, dst, P, Q,
        wbf + 0 * WN, wbf + 1 * WN, g1b2, g1b3, agg);
    relu_ln_kernel<<<Nn, 256>>>(agg, ln1g, ln1b, xc);

    // ---- GNN layer 2 ----
    gemm_mma<256, false><<<GB, 512, 168960>>>(xc, g2Ph, g2Pl, nullptr, P, Nn);
    gemm_mma<256, false><<<GB, 512, 168960>>>(xc, g2Qh, g2Ql, g2b1, Q, Nn);
    zero_kernel<<<(NH + ZB - 1) / ZB, ZB>>>(agg, NH);
    edge_mma_kernel<<<Ee / 128, 512, SM_TOT>>>(src, dst, P, Q,
        wbf + 2 * WN, wbf + 3 * WN, g2b2, g2b3, agg);
    relu_ln_kernel<<<Nn, 256>>>(agg, ln2g, ln2b, xc);

    // ---- assignment ----
    gemm_mma<256, true><<<GB, 512, 168960>>>(xc, awh, awl, ab1, P, Nn);
    assign_kernel<<<Nn / 8, 256>>>(P, aw2, ab2, u, out_s, entsum, colsum);

    // ---- pooling ----
    bstart_kernel<<<1, 32>>>(batch, bstart);
    {
        dim3 grid(Bb, 8);
        pool_kernel<<<grid, 256>>>(xc, out_s, bstart, pooled);
    }

    // ---- output MLP ----
    gemm_tiled<Hh, 32><<<(Bb * Ss) / 32, 256>>>(pooled, Hh, ow1, ob1, t2, Bb * Ss, 1);
    gemm_tiled<Ll, 32><<<(Bb * Ss) / 32, 256>>>(t2, Hh, ow2, ob2, out_latent, Bb * Ss, 0);

    // ---- loss scalar ----
    finalize_kernel<<<1, 32>>>(colsum, entsum, out_loss);
}

// round 12
// speedup vs baseline: 3.8328x; 1.0967x over previous
#include <cuda_runtime.h>
#include <cuda_fp16.h>
#include <math.h>
#include <stdint.h>

#define Nn 20000
#define Ee 320000
#define Ff 64
#define Hh 256
#define Ss 32
#define Ll 128
#define Bb 16
#define EPS_F 1e-9f

// ---------------- scratch (device globals; no allocation allowed) ----------------
__device__ float d_P[Nn * Hh];          // fp32 (assign t1)
__device__ __half d_Ph[Nn * Hh];        // fp16 P for edge layers
__device__ __half d_Qh[Nn * Hh];        // fp16 Q for edge layers
__device__ float d_agg[Nn * Hh];
__device__ float d_x[Nn * Hh];
__device__ float d_pooled[Bb * Ss * Hh];
__device__ float d_t2[Bb * Ss * Hh];
__device__ float d_colsum[Ss];
__device__ float d_entsum[1];
__device__ int   d_bstart[Bb + 1];
__device__ __align__(256) __half d_wbf[4 * Hh * Hh];    // edge weights [w2,w3] x 2 layers (fp16)
__device__ __align__(256) __half d_wnode[458752];       // node weights hi/lo splits

// ================= warp-MMA helpers (sm_80-compatible PTX) =================
__device__ __forceinline__ uint32_t smem_u32(const void* p) {
    uint32_t a;
    asm("{ .reg .u64 t; cvta.to.shared.u64 t, %1; cvt.u32.u64 %0, t; }" : "=r"(a) : "l"(p));
    return a;
}
__device__ __forceinline__ void cp16(uint32_t saddr, const void* g) {
    asm volatile("cp.async.cg.shared.global [%0], [%1], 16;" :: "r"(saddr), "l"(g));
}
#define CP_COMMIT() asm volatile("cp.async.commit_group;" ::: "memory")
#define CP_WAIT1()  asm volatile("cp.async.wait_group 1;" ::: "memory")
#define CP_WAIT0()  asm volatile("cp.async.wait_group 0;" ::: "memory")

#define LDSM4(r0, r1, r2, r3, addr) \
    asm volatile("ldmatrix.sync.aligned.m8n8.x4.shared.b16 {%0,%1,%2,%3}, [%4];" \
        : "=r"(r0), "=r"(r1), "=r"(r2), "=r"(r3) : "r"(addr))

__device__ __forceinline__ void mma16816(float* c,
    uint32_t a0, uint32_t a1, uint32_t a2, uint32_t a3, uint32_t b0, uint32_t b1) {
    asm volatile("mma.sync.aligned.m16n8k16.row.col.f32.f16.f16.f32 "
        "{%0,%1,%2,%3}, {%4,%5,%6,%7}, {%8,%9}, {%0,%1,%2,%3};"
        : "+f"(c[0]), "+f"(c[1]), "+f"(c[2]), "+f"(c[3])
        : "r"(a0), "r"(a1), "r"(a2), "r"(a3), "r"(b0), "r"(b1));
}

// ================= SMEM layout for edge kernel (bytes) =================
#define AROW    528                      // 256 fp16 + 16B pad (conflict-free ldmatrix)
#define SM_AHI  0                        // 128 * 528 = 67584
#define SM_BBUF 67584                    // 2 buffers x 8KB = 16384
#define SM_IDS  83968                    // sdst[128], ssrc[128]
#define SM_B2   84992
#define SM_B3   86016
#define SM_TOT  87040

// ---------------- edge weight transpose + fp16 convert ----------------
__global__ void wsplit_kernel(const float* __restrict__ w, __half* __restrict__ hi) {
    int i = blockIdx.x * 256 + threadIdx.x;   // i = n*256 + k
    int n = i >> 8, k = i & 255;
    hi[i] = __float2half_rn(w[k * Hh + n]);
}

// ---------------- node weight transpose + fp16 hi/lo split ----------------
__global__ void wsplit_node(const float* __restrict__ w, int K,
                            __half* __restrict__ hi, __half* __restrict__ lo) {
    int i = blockIdx.x * 256 + threadIdx.x;   // i = n*K + k
    int n = i / K, k = i - n * K;
    float v = w[k * Hh + n];
    __half h = __float2half_rn(v);
    hi[i] = h;
    lo[i] = __float2half_rn(v - __half2float(h));
}

// ---------------- edge B-slice loader ----------------
__device__ __forceinline__ void load_slice(int s, uint32_t sb, int t,
    const __half* w2, const __half* w3)
{
    const __half* Wh = (s < 16) ? w2 : w3;
    const int kt = s & 15;
    const uint32_t base = sb + SM_BBUF + (uint32_t)(s & 1) * 8192u;
    const int n = t >> 1;
    const int h = t & 1;
    const char* gh = (const char*)(Wh + (size_t)n * Hh + kt * 16) + h * 16;
    const uint32_t sw4 = (n & 4) ? 16u : 0u;
    const uint32_t doff = base + (uint32_t)n * 32u + (((uint32_t)h * 16u) ^ sw4);
    cp16(doff, gh);
}

// ---------------- fused tensor-core edge MLP (16 warps, 32x64 warp tiles, fp16 1-MMA) ---------
__global__ __launch_bounds__(512, 1) void edge_mma_kernel(
    const int* __restrict__ src, const int* __restrict__ dst,
    const __half* __restrict__ P, const __half* __restrict__ Q,
    const __half* __restrict__ w2, const __half* __restrict__ w3,
    const float* __restrict__ b2, const float* __restrict__ b3,
    float* __restrict__ agg)
{
    extern __shared__ char sm[];
    const uint32_t sb = smem_u32(sm);
    const int t = threadIdx.x;
    const int w = t >> 5, l = t & 31;
    const int wm = w & 3;
    const int wn = w >> 2;

    int* sdst = (int*)(sm + SM_IDS);
    int* ssrc = sdst + 128;
    float* sb2 = (float*)(sm + SM_B2);
    float* sb3 = (float*)(sm + SM_B3);

    if (t < 128) {
        sdst[t] = dst[blockIdx.x * 128 + t];
        ssrc[t] = src[blockIdx.x * 128 + t];
    }
    if (t < 256) {
        sb2[t] = b2[t];
        sb3[t] = b3[t];
    }
    __syncthreads();

    // ---- build A = relu(P[dst] + Q[src]) in fp16 (half2 math) ----
    {
        const int e = t & 127, h = t >> 7;        // h in 0..3, 64 cols each
        const int de = sdst[e], se = ssrc[e];
        const uint4* Pr = reinterpret_cast<const uint4*>(P + (size_t)de * Hh + h * 64);
        const uint4* Qr = reinterpret_cast<const uint4*>(Q + (size_t)se * Hh + h * 64);
        const uint32_t arow = (uint32_t)e * AROW + (uint32_t)h * 128u;
        const __half2 z2 = __float2half2_rn(0.f);
#pragma unroll
        for (int j = 0; j < 8; j++) {
            union { uint4 u; __half2 h2[4]; } A_, B_, C_;
            A_.u = Pr[j];
            B_.u = Qr[j];
#pragma unroll
            for (int p = 0; p < 4; p++)
                C_.h2[p] = __hmax2(__hadd2(A_.h2[p], B_.h2[p]), z2);
            *(uint4*)(sm + SM_AHI + arow + j * 16) = C_.u;
        }
    }

    float acc[2][8][4];
#pragma unroll
    for (int mi = 0; mi < 2; mi++)
#pragma unroll
        for (int nj = 0; nj < 8; nj++) {
            acc[mi][nj][0] = 0.f; acc[mi][nj][1] = 0.f;
            acc[mi][nj][2] = 0.f; acc[mi][nj][3] = 0.f;
        }

    const uint32_t a_base = sb + (uint32_t)((32 * wm + (l % 16)) * AROW + (l / 16) * 16);
    const uint32_t b_off = (uint32_t)((l % 16) * 32) +
                           (uint32_t)(((l / 16) * 16) ^ (((l % 16) & 4) ? 16 : 0));

    load_slice(0, sb, t, w2, w3); CP_COMMIT();
    load_slice(1, sb, t, w2, w3); CP_COMMIT();

#pragma unroll 1
    for (int s = 0; s < 32; s++) {
        if (s < 30) { CP_WAIT1(); } else { CP_WAIT0(); }
        __syncthreads();

        const int kt = s & 15;
        uint32_t ah[2][4];
#pragma unroll
        for (int mi = 0; mi < 2; mi++) {
            const uint32_t aa = a_base + (uint32_t)(16 * mi * AROW) + kt * 32;
            LDSM4(ah[mi][0], ah[mi][1], ah[mi][2], ah[mi][3], aa + SM_AHI);
        }

        const uint32_t bbase = sb + SM_BBUF + (uint32_t)(s & 1) * 8192u + b_off
                             + (uint32_t)(wn * 2048);
#pragma unroll
        for (int c = 0; c < 4; c++) {
            uint32_t bh0, bh1, bh2, bh3;
            LDSM4(bh0, bh1, bh2, bh3, bbase + c * 512);
#pragma unroll
            for (int mi = 0; mi < 2; mi++) {
                mma16816(acc[mi][2 * c],     ah[mi][0], ah[mi][1], ah[mi][2], ah[mi][3], bh0, bh2);
                mma16816(acc[mi][2 * c + 1], ah[mi][0], ah[mi][1], ah[mi][2], ah[mi][3], bh1, bh3);
            }
        }

        if (s == 15) {
            __syncthreads();
            const int cb = (l % 4) * 2;
#pragma unroll
            for (int mi = 0; mi < 2; mi++) {
                const int r0 = 32 * wm + 16 * mi + l / 4;
#pragma unroll
                for (int nj = 0; nj < 8; nj++) {
                    const int cn = 64 * wn + 8 * nj + cb;
                    const float bz0 = sb2[cn], bz1 = sb2[cn + 1];
                    __half2 hp0 = __floats2half2_rn(fmaxf(acc[mi][nj][0] + bz0, 0.f),
                                                    fmaxf(acc[mi][nj][1] + bz1, 0.f));
                    __half2 hp1 = __floats2half2_rn(fmaxf(acc[mi][nj][2] + bz0, 0.f),
                                                    fmaxf(acc[mi][nj][3] + bz1, 0.f));
                    *(uint32_t*)(sm + SM_AHI + r0 * AROW + cn * 2)       = *(uint32_t*)&hp0;
                    *(uint32_t*)(sm + SM_AHI + (r0 + 8) * AROW + cn * 2) = *(uint32_t*)&hp1;
                    acc[mi][nj][0] = 0.f; acc[mi][nj][1] = 0.f;
                    acc[mi][nj][2] = 0.f; acc[mi][nj][3] = 0.f;
                }
            }
        }
        __syncthreads();
        if (s + 2 < 32) {
            load_slice(s + 2, sb, t, w2, w3);
            CP_COMMIT();
        }
    }

    // ---- epilogue 2: agg[dst] += D2 + b3 ----
    {
        const int cb = (l % 4) * 2;
#pragma unroll
        for (int mi = 0; mi < 2; mi++) {
            const int er = 32 * wm + 16 * mi + l / 4;
            const int d0 = sdst[er], d1 = sdst[er + 8];
            float* a0 = agg + (size_t)d0 * Hh;
            float* a1 = agg + (size_t)d1 * Hh;
#pragma unroll
            for (int nj = 0; nj < 8; nj++) {
                const int cn = 64 * wn + 8 * nj + cb;
                const float bz0 = sb3[cn], bz1 = sb3[cn + 1];
                atomicAdd(a0 + cn,     acc[mi][nj][0] + bz0);
                atomicAdd(a0 + cn + 1, acc[mi][nj][1] + bz1);
                atomicAdd(a1 + cn,     acc[mi][nj][2] + bz0);
                atomicAdd(a1 + cn + 1, acc[mi][nj][3] + bz1);
            }
        }
    }
}

// ---------------- fused node GEMM pair: P = A@Wp ; Q = A@Wq + bq ; fp16 outputs ----------------
// W pre-split fp16 hi/lo, [n][k] layout. 3-product per GEMM.
template <int K>
__global__ __launch_bounds__(512, 1) void gemm_mma_pq(
    const float* __restrict__ A,
    const __half* __restrict__ Wph, const __half* __restrict__ Wpl,
    const __half* __restrict__ Wqh, const __half* __restrict__ Wql,
    const float* __restrict__ biasq,
    __half* __restrict__ Pout, __half* __restrict__ Qout, int M)
{
    constexpr int AROWK = K * 2 + 16;
    constexpr int SA_HI = 0;
    constexpr int SA_LO = 128 * AROWK;
    constexpr int S_BB  = 2 * 128 * AROWK;
    constexpr int S_BIAS = S_BB + 32768;
    constexpr int NS = K / 16;
    constexpr int TOT = 2 * NS;

    extern __shared__ char sm[];
    const uint32_t sb = smem_u32(sm);
    const int t = threadIdx.x;
    const int w = t >> 5, l = t & 31;
    const int wm = w & 3;
    const int wn = w >> 2;

    float* sbias = (float*)(sm + S_BIAS);
    if (t < 256) sbias[t] = biasq[t];

    // ---- load + split A rows into hi/lo fp16 ----
    {
        const int e = t & 127, h = t >> 7;
        const int grow = blockIdx.x * 128 + e;
        constexpr int cpt = K / 4;
        const uint32_t arow = (uint32_t)e * AROWK + (uint32_t)h * (cpt * 2);
        if (grow < M) {
            const float4* Ar = reinterpret_cast<const float4*>(A + (size_t)grow * K) + h * (cpt / 4);
#pragma unroll
            for (int j = 0; j < cpt / 8; j++) {
                float4 a0 = Ar[2 * j], a1 = Ar[2 * j + 1];
                float v[8] = { a0.x, a0.y, a0.z, a0.w, a1.x, a1.y, a1.z, a1.w };
                union { uint4 u; __half2 h2[4]; } HI, LO;
#pragma unroll
                for (int p = 0; p < 4; p++) {
                    float v0 = v[2 * p], v1 = v[2 * p + 1];
                    __half h0 = __float2half_rn(v0), h1 = __float2half_rn(v1);
                    HI.h2[p] = __halves2half2(h0, h1);
                    LO.h2[p] = __floats2half2_rn(v0 - __half2float(h0),
                                                 v1 - __half2float(h1));
                }
                *(uint4*)(sm + SA_HI + arow + j * 16) = HI.u;
                *(uint4*)(sm + SA_LO + arow + j * 16) = LO.u;
            }
        } else {
            const uint4 z = make_uint4(0, 0, 0, 0);
#pragma unroll
            for (int j = 0; j < cpt / 8; j++) {
                *(uint4*)(sm + SA_HI + arow + j * 16) = z;
                *(uint4*)(sm + SA_LO + arow + j * 16) = z;
            }
        }
    }

    float acc[2][8][4];
#pragma unroll
    for (int mi = 0; mi < 2; mi++)
#pragma unroll
        for (int nj = 0; nj < 8; nj++) {
            acc[mi][nj][0] = 0.f; acc[mi][nj][1] = 0.f;
            acc[mi][nj][2] = 0.f; acc[mi][nj][3] = 0.f;
        }

    const uint32_t a_base = sb + (uint32_t)((32 * wm + (l % 16)) * AROWK + (l / 16) * 16);
    const uint32_t b_off = (uint32_t)((l % 16) * 32) +
                           (uint32_t)(((l / 16) * 16) ^ (((l % 16) & 4) ? 16 : 0));

    auto load_b = [&](int s) {
        const __half* Bh = (s < NS) ? Wph : Wqh;
        const __half* Bl = (s < NS) ? Wpl : Wql;
        const int kt = s & (NS - 1);
        const uint32_t base = sb + S_BB + (uint32_t)(s & 1) * 16384u;
        const int n = t >> 1;
        const int h = t & 1;
        const char* gh = (const char*)(Bh + (size_t)n * K + kt * 16) + h * 16;
        const char* gl = (const char*)(Bl + (size_t)n * K + kt * 16) + h * 16;
        const uint32_t sw4 = (n & 4) ? 16u : 0u;
        const uint32_t doff = base + (uint32_t)n * 32u + (((uint32_t)h * 16u) ^ sw4);
        cp16(doff, gh);
        cp16(doff + 8192u, gl);
    };

    load_b(0); CP_COMMIT();
    load_b(1); CP_COMMIT();

    const int e_r0base = blockIdx.x * 128;

#pragma unroll 1
    for (int s = 0; s < TOT; s++) {
        if (s < TOT - 2) { CP_WAIT1(); } else { CP_WAIT0(); }
        __syncthreads();

        const int kt = s & (NS - 1);
        uint32_t ah[2][4], al[2][4];
#pragma unroll
        for (int mi = 0; mi < 2; mi++) {
            const uint32_t aa = a_base + (uint32_t)(16 * mi * AROWK) + kt * 32;
            LDSM4(ah[mi][0], ah[mi][1], ah[mi][2], ah[mi][3], aa + SA_HI);
            LDSM4(al[mi][0], al[mi][1], al[mi][2], al[mi][3], aa + SA_LO);
        }

        const uint32_t bbase = sb + S_BB + (uint32_t)(s & 1) * 16384u + b_off
                             + (uint32_t)(wn * 2048);
#pragma unroll
        for (int c = 0; c < 4; c++) {
            uint32_t bh0, bh1, bh2, bh3, bl0, bl1, bl2, bl3;
            LDSM4(bh0, bh1, bh2, bh3, bbase + c * 512);
            LDSM4(bl0, bl1, bl2, bl3, bbase + 8192 + c * 512);
#pragma unroll
            for (int mi = 0; mi < 2; mi++) {
                float* c0 = acc[mi][2 * c];
                float* c1 = acc[mi][2 * c + 1];
                mma16816(c0, ah[mi][0], ah[mi][1], ah[mi][2], ah[mi][3], bh0, bh2);
                mma16816(c0, ah[mi][0], ah[mi][1], ah[mi][2], ah[mi][3], bl0, bl2);
                mma16816(c0, al[mi][0], al[mi][1], al[mi][2], al[mi][3], bh0, bh2);
                mma16816(c1, ah[mi][0], ah[mi][1], ah[mi][2], ah[mi][3], bh1, bh3);
                mma16816(c1, ah[mi][0], ah[mi][1], ah[mi][2], ah[mi][3], bl1, bl3);
                mma16816(c1, al[mi][0], al[mi][1], al[mi][2], al[mi][3], bh1, bh3);
            }
        }

        if (s == NS - 1) {
            // ---- write P (no bias), reset acc ----
            const int cb = (l % 4) * 2;
#pragma unroll
            for (int mi = 0; mi < 2; mi++) {
                const int r0 = 32 * wm + 16 * mi + l / 4;
                const int g0 = e_r0base + r0;
                const int g1 = g0 + 8;
#pragma unroll
                for (int nj = 0; nj < 8; nj++) {
                    const int cn = 64 * wn + 8 * nj + cb;
                    __half2 hp0 = __floats2half2_rn(acc[mi][nj][0], acc[mi][nj][1]);
                    __half2 hp1 = __floats2half2_rn(acc[mi][nj][2], acc[mi][nj][3]);
                    if (g0 < M) *(uint32_t*)(Pout + (size_t)g0 * Hh + cn) = *(uint32_t*)&hp0;
                    if (g1 < M) *(uint32_t*)(Pout + (size_t)g1 * Hh + cn) = *(uint32_t*)&hp1;
                    acc[mi][nj][0] = 0.f; acc[mi][nj][1] = 0.f;
                    acc[mi][nj][2] = 0.f; acc[mi][nj][3] = 0.f;
                }
            }
        }
        __syncthreads();
        if (s + 2 < TOT) {
            load_b(s + 2);
            CP_COMMIT();
        }
    }

    // ---- write Q (+ biasq) ----
    {
        const int cb = (l % 4) * 2;
#pragma unroll
        for (int mi = 0; mi < 2; mi++) {
            const int r0 = 32 * wm + 16 * mi + l / 4;
            const int g0 = e_r0base + r0;
            const int g1 = g0 + 8;
#pragma unroll
            for (int nj = 0; nj < 8; nj++) {
                const int cn = 64 * wn + 8 * nj + cb;
                const float bz0 = sbias[cn], bz1 = sbias[cn + 1];
                __half2 hp0 = __floats2half2_rn(acc[mi][nj][0] + bz0, acc[mi][nj][1] + bz1);
                __half2 hp1 = __floats2half2_rn(acc[mi][nj][2] + bz0, acc[mi][nj][3] + bz1);
                if (g0 < M) *(uint32_t*)(Qout + (size_t)g0 * Hh + cn) = *(uint32_t*)&hp0;
                if (g1 < M) *(uint32_t*)(Qout + (size_t)g1 * Hh + cn) = *(uint32_t*)&hp1;
            }
        }
    }
}

// ---------------- tensor-core node GEMM (fp32 out, for assign hidden) ----------------
template <int K, bool RELU>
__global__ __launch_bounds__(512, 1) void gemm_mma(
    const float* __restrict__ A,
    const __half* __restrict__ Whi, const __half* __restrict__ Wlo,
    const float* __restrict__ bias, float* __restrict__ C, int M)
{
    constexpr int AROWK = K * 2 + 16;
    constexpr int SA_HI = 0;
    constexpr int SA_LO = 128 * AROWK;
    constexpr int S_BB  = 2 * 128 * AROWK;
    constexpr int S_BIAS = S_BB + 32768;
    constexpr int NS = K / 16;

    extern __shared__ char sm[];
    const uint32_t sb = smem_u32(sm);
    const int t = threadIdx.x;
    const int w = t >> 5, l = t & 31;
    const int wm = w & 3;
    const int wn = w >> 2;

    float* sbias = (float*)(sm + S_BIAS);
    if (t < 256) sbias[t] = bias ? bias[t] : 0.f;

    {
        const int e = t & 127, h = t >> 7;
        const int grow = blockIdx.x * 128 + e;
        constexpr int cpt = K / 4;
        const uint32_t arow = (uint32_t)e * AROWK + (uint32_t)h * (cpt * 2);
        if (grow < M) {
            const float4* Ar = reinterpret_cast<const float4*>(A + (size_t)grow * K) + h * (cpt / 4);
#pragma unroll
            for (int j = 0; j < cpt / 8; j++) {
                float4 a0 = Ar[2 * j], a1 = Ar[2 * j + 1];
                float v[8] = { a0.x, a0.y, a0.z, a0.w, a1.x, a1.y, a1.z, a1.w };
                union { uint4 u; __half2 h2[4]; } HI, LO;
#pragma unroll
                for (int p = 0; p < 4; p++) {
                    float v0 = v[2 * p], v1 = v[2 * p + 1];
                    __half h0 = __float2half_rn(v0), h1 = __float2half_rn(v1);
                    HI.h2[p] = __halves2half2(h0, h1);
                    LO.h2[p] = __floats2half2_rn(v0 - __half2float(h0),
                                                 v1 - __half2float(h1));
                }
                *(uint4*)(sm + SA_HI + arow + j * 16) = HI.u;
                *(uint4*)(sm + SA_LO + arow + j * 16) = LO.u;
            }
        } else {
            const uint4 z = make_uint4(0, 0, 0, 0);
#pragma unroll
            for (int j = 0; j < cpt / 8; j++) {
                *(uint4*)(sm + SA_HI + arow + j * 16) = z;
                *(uint4*)(sm + SA_LO + arow + j * 16) = z;
            }
        }
    }

    float acc[2][8][4];
#pragma unroll
    for (int mi = 0; mi < 2; mi++)
#pragma unroll
        for (int nj = 0; nj < 8; nj++) {
            acc[mi][nj][0] = 0.f; acc[mi][nj][1] = 0.f;
            acc[mi][nj][2] = 0.f; acc[mi][nj][3] = 0.f;
        }

    const uint32_t a_base = sb + (uint32_t)((32 * wm + (l % 16)) * AROWK + (l / 16) * 16);
    const uint32_t b_off = (uint32_t)((l % 16) * 32) +
                           (uint32_t)(((l / 16) * 16) ^ (((l % 16) & 4) ? 16 : 0));

    auto load_b = [&](int s) {
        const uint32_t base = sb + S_BB + (uint32_t)(s & 1) * 16384u;
        const int n = t >> 1;
        const int h = t & 1;
        const char* gh = (const char*)(Whi + (size_t)n * K + s * 16) + h * 16;
        const char* gl = (const char*)(Wlo + (size_t)n * K + s * 16) + h * 16;
        const uint32_t sw4 = (n & 4) ? 16u : 0u;
        const uint32_t doff = base + (uint32_t)n * 32u + (((uint32_t)h * 16u) ^ sw4);
        cp16(doff, gh);
        cp16(doff + 8192u, gl);
    };

    load_b(0); CP_COMMIT();
    load_b(1); CP_COMMIT();

#pragma unroll 1
    for (int s = 0; s < NS; s++) {
        if (s < NS - 2) { CP_WAIT1(); } else { CP_WAIT0(); }
        __syncthreads();

        uint32_t ah[2][4], al[2][4];
#pragma unroll
        for (int mi = 0; mi < 2; mi++) {
            const uint32_t aa = a_base + (uint32_t)(16 * mi * AROWK) + s * 32;
            LDSM4(ah[mi][0], ah[mi][1], ah[mi][2], ah[mi][3], aa + SA_HI);
            LDSM4(al[mi][0], al[mi][1], al[mi][2], al[mi][3], aa + SA_LO);
        }

        const uint32_t bbase = sb + S_BB + (uint32_t)(s & 1) * 16384u + b_off
                             + (uint32_t)(wn * 2048);
#pragma unroll
        for (int c = 0; c < 4; c++) {
            uint32_t bh0, bh1, bh2, bh3, bl0, bl1, bl2, bl3;
            LDSM4(bh0, bh1, bh2, bh3, bbase + c * 512);
            LDSM4(bl0, bl1, bl2, bl3, bbase + 8192 + c * 512);
#pragma unroll
            for (int mi = 0; mi < 2; mi++) {
                float* c0 = acc[mi][2 * c];
                float* c1 = acc[mi][2 * c + 1];
                mma16816(c0, ah[mi][0], ah[mi][1], ah[mi][2], ah[mi][3], bh0, bh2);
                mma16816(c0, ah[mi][0], ah[mi][1], ah[mi][2], ah[mi][3], bl0, bl2);
                mma16816(c0, al[mi][0], al[mi][1], al[mi][2], al[mi][3], bh0, bh2);
                mma16816(c1, ah[mi][0], ah[mi][1], ah[mi][2], ah[mi][3], bh1, bh3);
                mma16816(c1, ah[mi][0], ah[mi][1], ah[mi][2], ah[mi][3], bl1, bl3);
                mma16816(c1, al[mi][0], al[mi][1], al[mi][2], al[mi][3], bh1, bh3);
            }
        }
        __syncthreads();
        if (s + 2 < NS) {
            load_b(s + 2);
            CP_COMMIT();
        }
    }

    {
        const int cb = (l % 4) * 2;
#pragma unroll
        for (int mi = 0; mi < 2; mi++) {
            const int r0 = 32 * wm + 16 * mi + l / 4;
            const int g0 = blockIdx.x * 128 + r0;
            const int g1 = g0 + 8;
#pragma unroll
            for (int nj = 0; nj < 8; nj++) {
                const int cn = 64 * wn + 8 * nj + cb;
                const float bz0 = sbias[cn], bz1 = sbias[cn + 1];
                float v0 = acc[mi][nj][0] + bz0, v1 = acc[mi][nj][1] + bz1;
                float v2 = acc[mi][nj][2] + bz0, v3 = acc[mi][nj][3] + bz1;
                if (RELU) {
                    v0 = fmaxf(v0, 0.f); v1 = fmaxf(v1, 0.f);
                    v2 = fmaxf(v2, 0.f); v3 = fmaxf(v3, 0.f);
                }
                if (g0 < M) { float2 o = make_float2(v0, v1); *(float2*)(C + (size_t)g0 * Hh + cn) = o; }
                if (g1 < M) { float2 o = make_float2(v2, v3); *(float2*)(C + (size_t)g1 * Hh + cn) = o; }
            }
        }
    }
}

// ---------------- zero ----------------
__global__ void zero_kernel(float* p, int n) {
    int i = blockIdx.x * blockDim.x + threadIdx.x;
    if (i < n) p[i] = 0.f;
}

// ---------------- generic row-tiled fp32 GEMM (small outputs only) ----------------
template <int NCOL, int RPB>
__global__ __launch_bounds__(256) void gemm_tiled(
    const float* __restrict__ A, int K,
    const float* __restrict__ W, const float* __restrict__ bias,
    float* __restrict__ C, int M, int do_relu)
{
    __shared__ float As[RPB * 256];
    const int row0 = blockIdx.x * RPB;
    const int tot = RPB * K;
    for (int idx = threadIdx.x; idx < tot; idx += 256) {
        int r = idx / K, k = idx - r * K;
        int gr = row0 + r;
        As[idx] = (gr < M) ? A[gr * K + k] : 0.f;
    }
    __syncthreads();

    const int RG = 256 / NCOL;
    const int RPT = RPB / RG;
    const int col = threadIdx.x % NCOL;
    const int rg = threadIdx.x / NCOL;

    float acc[RPT];
    float bv = bias ? bias[col] : 0.f;
#pragma unroll
    for (int i = 0; i < RPT; i++) acc[i] = bv;

    for (int k = 0; k < K; k += 4) {
        float wv0 = W[(k + 0) * NCOL + col];
        float wv1 = W[(k + 1) * NCOL + col];
        float wv2 = W[(k + 2) * NCOL + col];
        float wv3 = W[(k + 3) * NCOL + col];
#pragma unroll
        for (int i = 0; i < RPT; i++) {
            const float4 a = *(const float4*)&As[(rg + i * RG) * K + k];
            acc[i] = fmaf(a.x, wv0, acc[i]);
            acc[i] = fmaf(a.y, wv1, acc[i]);
            acc[i] = fmaf(a.z, wv2, acc[i]);
            acc[i] = fmaf(a.w, wv3, acc[i]);
        }
    }
#pragma unroll
    for (int i = 0; i < RPT; i++) {
        int gr = row0 + rg + i * RG;
        if (gr < M) {
            float v = acc[i];
            if (do_relu) v = fmaxf(v, 0.f);
            C[gr * NCOL + col] = v;
        }
    }
}

// ---------------- relu + layernorm per node ----------------
__device__ __forceinline__ float warp_sum(float v) {
#pragma unroll
    for (int o = 16; o > 0; o >>= 1) v += __shfl_xor_sync(0xFFFFFFFFu, v, o);
    return v;
}

__global__ __launch_bounds__(256) void relu_ln_kernel(
    const float* __restrict__ agg, const float* __restrict__ g,
    const float* __restrict__ b, float* __restrict__ xout)
{
    const int n = blockIdx.x;
    const int j = threadIdx.x;
    const int lane = j & 31, warp = j >> 5;
    __shared__ float red[8];
    __shared__ float s_mu, s_rstd;

    float v = fmaxf(agg[n * Hh + j], 0.f);
    float t = warp_sum(v);
    if (lane == 0) red[warp] = t;
    __syncthreads();
    if (j == 0) {
        float s = 0.f;
#pragma unroll
        for (int i = 0; i < 8; i++) s += red[i];
        s_mu = s / (float)Hh;
    }
    __syncthreads();
    float d = v - s_mu;
    float t2 = warp_sum(d * d);
    if (lane == 0) red[warp] = t2;
    __syncthreads();
    if (j == 0) {
        float s = 0.f;
#pragma unroll
        for (int i = 0; i < 8; i++) s += red[i];
        s_rstd = rsqrtf(s / (float)Hh + 1e-5f);
    }
    __syncthreads();
    xout[n * Hh + j] = d * s_rstd * g[j] + b[j];
}

// ---------------- assignment ----------------
__global__ __launch_bounds__(256) void assign_kernel(
    const float* __restrict__ t1, const float* __restrict__ aw2,
    const float* __restrict__ ab2, const float* __restrict__ u,
    float* __restrict__ s_out, float* __restrict__ entsum, float* __restrict__ colsum)
{
    __shared__ float rows[8 * Hh];
    __shared__ float blk_col[Ss];
    __shared__ float blk_ent;

    const int lane = threadIdx.x & 31, warp = threadIdx.x >> 5;
    if (threadIdx.x < Ss) blk_col[threadIdx.x] = 0.f;
    if (threadIdx.x == 0) blk_ent = 0.f;
    const int n0 = blockIdx.x * 8;
    for (int idx = threadIdx.x; idx < 8 * Hh; idx += 256)
        rows[idx] = t1[n0 * Hh + idx];
    __syncthreads();

    const int n = n0 + warp;
    float acc = ab2[lane];
    for (int k = 0; k < Hh; k += 4) {
        const float4 a = *(const float4*)&rows[warp * Hh + k];
        acc = fmaf(a.x, aw2[(k + 0) * Ss + lane], acc);
        acc = fmaf(a.y, aw2[(k + 1) * Ss + lane], acc);
        acc = fmaf(a.z, aw2[(k + 2) * Ss + lane], acc);
        acc = fmaf(a.w, aw2[(k + 3) * Ss + lane], acc);
    }
    float uu = u[n * Ss + lane];
    float gmb = -logf(-logf(uu + EPS_F) + EPS_F);
    float z = acc + gmb;
    float m = z;
#pragma unroll
    for (int o = 16; o > 0; o >>= 1) m = fmaxf(m, __shfl_xor_sync(0xFFFFFFFFu, m, o));
    float p = expf(z - m);
    float sum = warp_sum(p);
    float sv = p / sum;
    s_out[n * Ss + lane] = sv;

    float ent = warp_sum(sv * logf(sv + EPS_F));
    if (lane == 0) atomicAdd(&blk_ent, ent);
    atomicAdd(&blk_col[lane], sv);
    __syncthreads();
    if (threadIdx.x == 0) atomicAdd(entsum, blk_ent);
    if (threadIdx.x < Ss) atomicAdd(&colsum[threadIdx.x], blk_col[threadIdx.x]);
}

// ---------------- batch segment starts ----------------
__global__ void bstart_kernel(const int* __restrict__ batch, int* __restrict__ bstart) {
    int b = threadIdx.x;
    if (b > Bb) return;
    if (b == Bb) { bstart[Bb] = Nn; return; }
    int lo = 0, hi = Nn;
    while (lo < hi) {
        int mid = (lo + hi) >> 1;
        if (batch[mid] < b) lo = mid + 1; else hi = mid;
    }
    bstart[b] = lo;
}

// ---------------- pooling ----------------
__global__ __launch_bounds__(256) void pool_kernel(
    const float* __restrict__ x, const float* __restrict__ s_out,
    const int* __restrict__ bstart, float* __restrict__ pooled)
{
    const int b = blockIdx.x;
    const int chunk = blockIdx.y;
    const int NCHUNK = gridDim.y;
    const int lo = bstart[b], hi = bstart[b + 1];
    const int cnt = hi - lo;
    const int c0 = lo + (int)(((long long)cnt * chunk) / NCHUNK);
    const int c1 = lo + (int)(((long long)cnt * (chunk + 1)) / NCHUNK);

    __shared__ float ss[Ss];
    const int t = threadIdx.x;
    float acc[Ss];
#pragma unroll
    for (int sl = 0; sl < Ss; sl++) acc[sl] = 0.f;

    for (int n = c0; n < c1; n++) {
        __syncthreads();
        if (t < Ss) ss[t] = s_out[n * Ss + t];
        __syncthreads();
        float xv = x[n * Hh + t];
#pragma unroll
        for (int sl = 0; sl < Ss; sl++) acc[sl] = fmaf(xv, ss[sl], acc[sl]);
    }
#pragma unroll
    for (int sl = 0; sl < Ss; sl++)
        atomicAdd(&pooled[(b * Ss + sl) * Hh + t], acc[sl]);
}

// ---------------- final scalar loss ----------------
__global__ void finalize_kernel(const float* __restrict__ colsum,
                                const float* __restrict__ entsum,
                                float* __restrict__ out_loss)
{
    int l = threadIdx.x;
    float avg = colsum[l] / (float)Nn;
    float dv = avg * logf(avg + EPS_F);
    dv = warp_sum(dv);
    if (l == 0) {
        float entropy = -(entsum[0] / (float)Nn);
        out_loss[0] = entropy + dv;
    }
}

// ---------------- launch ----------------
extern "C" void kernel_launch(void* const* d_in, const int* in_sizes, int n_in,
                              void* d_out, int out_size)
{
    const float* x    = (const float*)d_in[0];
    const float* u    = (const float*)d_in[1];
    const int* eidx   = (const int*)d_in[2];
    const int* batch  = (const int*)d_in[3];
    const float* g1w1 = (const float*)d_in[4];
    const float* g1b1 = (const float*)d_in[5];
    const float* g1w2 = (const float*)d_in[6];
    const float* g1b2 = (const float*)d_in[7];
    const float* g1w3 = (const float*)d_in[8];
    const float* g1b3 = (const float*)d_in[9];
    const float* ln1g = (const float*)d_in[10];
    const float* ln1b = (const float*)d_in[11];
    const float* g2w1 = (const float*)d_in[12];
    const float* g2b1 = (const float*)d_in[13];
    const float* g2w2 = (const float*)d_in[14];
    const float* g2b2 = (const float*)d_in[15];
    const float* g2w3 = (const float*)d_in[16];
    const float* g2b3 = (const float*)d_in[17];
    const float* ln2g = (const float*)d_in[18];
    const float* ln2b = (const float*)d_in[19];
    const float* aw1  = (const float*)d_in[20];
    const float* ab1  = (const float*)d_in[21];
    const float* aw2  = (const float*)d_in[22];
    const float* ab2  = (const float*)d_in[23];
    const float* ow1  = (const float*)d_in[24];
    const float* ob1  = (const float*)d_in[25];
    const float* ow2  = (const float*)d_in[26];
    const float* ob2  = (const float*)d_in[27];

    const int* src = eidx;
    const int* dst = eidx + Ee;

    float* out = (float*)d_out;
    float* out_latent = out;
    float* out_s = out + Bb * Ss * Ll;
    float* out_loss = out + Bb * Ss * Ll + Nn * Ss;

    float *P, *agg, *xc, *pooled, *t2, *colsum, *entsum;
    __half *Ph, *Qh;
    int* bstart;
    __half *wbf, *wn;
    cudaGetSymbolAddress((void**)&P, d_P);
    cudaGetSymbolAddress((void**)&Ph, d_Ph);
    cudaGetSymbolAddress((void**)&Qh, d_Qh);
    cudaGetSymbolAddress((void**)&agg, d_agg);
    cudaGetSymbolAddress((void**)&xc, d_x);
    cudaGetSymbolAddress((void**)&pooled, d_pooled);
    cudaGetSymbolAddress((void**)&t2, d_t2);
    cudaGetSymbolAddress((void**)&colsum, d_colsum);
    cudaGetSymbolAddress((void**)&entsum, d_entsum);
    cudaGetSymbolAddress((void**)&bstart, d_bstart);
    cudaGetSymbolAddress((void**)&wbf, d_wbf);
    cudaGetSymbolAddress((void**)&wn, d_wnode);

    cudaFuncSetAttribute(edge_mma_kernel, cudaFuncAttributeMaxDynamicSharedMemorySize, SM_TOT);
    cudaFuncSetAttribute(gemm_mma_pq<64>,  cudaFuncAttributeMaxDynamicSharedMemorySize, 70656);
    cudaFuncSetAttribute(gemm_mma_pq<256>, cudaFuncAttributeMaxDynamicSharedMemorySize, 168960);
    cudaFuncSetAttribute(gemm_mma<256, true>, cudaFuncAttributeMaxDynamicSharedMemorySize, 168960);

    const int NH = Nn * Hh;
    const int ZB = 256;
    const int WN = Hh * Hh;   // 65536
    const int GB = (Nn + 127) / 128;   // 157

    // node weight split offsets (halfs)
    __half* g1Ph = wn + 0;       __half* g1Pl = wn + 16384;
    __half* g1Qh = wn + 32768;   __half* g1Ql = wn + 49152;
    __half* g2Ph = wn + 65536;   __half* g2Pl = wn + 131072;
    __half* g2Qh = wn + 196608;  __half* g2Ql = wn + 262144;
    __half* awh  = wn + 327680;  __half* awl  = wn + 393216;

    // ---- zero accumulators ----
    zero_kernel<<<(NH + ZB - 1) / ZB, ZB>>>(agg, NH);
    zero_kernel<<<(Bb * Ss * Hh + ZB - 1) / ZB, ZB>>>(pooled, Bb * Ss * Hh);
    zero_kernel<<<1, ZB>>>(colsum, Ss);
    zero_kernel<<<1, ZB>>>(entsum, 1);

    // ---- edge weights: transpose + fp16 ----
    wsplit_kernel<<<256, 256>>>(g1w2, wbf + 0 * WN);
    wsplit_kernel<<<256, 256>>>(g1w3, wbf + 1 * WN);
    wsplit_kernel<<<256, 256>>>(g2w2, wbf + 2 * WN);
    wsplit_kernel<<<256, 256>>>(g2w3, wbf + 3 * WN);

    // ---- node weights: transpose + fp16 hi/lo split ----
    wsplit_node<<<64, 256>>>(g1w1,            64,  g1Ph, g1Pl);
    wsplit_node<<<64, 256>>>(g1w1 + 64 * Hh,  64,  g1Qh, g1Ql);
    wsplit_node<<<256, 256>>>(g2w1,           256, g2Ph, g2Pl);
    wsplit_node<<<256, 256>>>(g2w1 + Hh * Hh, 256, g2Qh, g2Ql);
    wsplit_node<<<256, 256>>>(aw1,            256, awh,  awl);

    // ---- GNN layer 1 ----
    gemm_mma_pq<64><<<GB, 512, 70656>>>(x, g1Ph, g1Pl, g1Qh, g1Ql, g1b1, Ph, Qh, Nn);
    edge_mma_kernel<<<Ee / 128, 512, SM_TOT>>>(src, dst, Ph, Qh,
        wbf + 0 * WN, wbf + 1 * WN, g1b2, g1b3, agg);
    relu_ln_kernel<<<Nn, 256>>>(agg, ln1g, ln1b, xc);

    // ---- GNN layer 2 ----
    gemm_mma_pq<256><<<GB, 512, 168960>>>(xc, g2Ph, g2Pl, g2Qh, g2Ql, g2b1, Ph, Qh, Nn);
    zero_kernel<<<(NH + ZB - 1) / ZB, ZB>>>(agg, NH);
    edge_mma_kernel<<<Ee / 128, 512, SM_TOT>>>(src, dst, Ph, Qh,
        wbf + 2 * WN, wbf + 3 * WN, g2b2, g2b3, agg);
    relu_ln_kernel<<<Nn, 256>>>(agg, ln2g, ln2b, xc);

    // ---- assignment ----
    gemm_mma<256, true><<<GB, 512, 168960>>>(xc, awh, awl, ab1, P, Nn);
    assign_kernel<<<Nn / 8, 256>>>(P, aw2, ab2, u, out_s, entsum, colsum);

    // ---- pooling ----
    bstart_kernel<<<1, 32>>>(batch, bstart);
    {
        dim3 grid(Bb, 8);
        pool_kernel<<<grid, 256>>>(xc, out_s, bstart, pooled);
    }

    // ---- output MLP ----
    gemm_tiled<Hh, 32><<<(Bb * Ss) / 32, 256>>>(pooled, Hh, ow1, ob1, t2, Bb * Ss, 1);
    gemm_tiled<Ll, 32><<<(Bb * Ss) / 32, 256>>>(t2, Hh, ow2, ob2, out_latent, Bb * Ss, 0);

    // ---- loss scalar ----
    finalize_kernel<<<1, 32>>>(colsum, entsum, out_loss);
}

// round 15
// speedup vs baseline: 4.1769x; 1.0898x over previous
#include <cuda_runtime.h>
#include <cuda_fp16.h>
#include <math.h>
#include <stdint.h>

#define Nn 20000
#define Ee 320000
#define Ff 64
#define Hh 256
#define Ss 32
#define Ll 128
#define Bb 16
#define EPS_F 1e-9f

// ---------------- scratch (device globals; no allocation allowed) ----------------
__device__ float d_P[Nn * Hh];          // fp32 (assign t1)
__device__ __half d_Ph[Nn * Hh];        // fp16 P for edge layers
__device__ __half d_Qh[Nn * Hh];        // fp16 Q for edge layers
__device__ float d_agg[Nn * Hh];
__device__ float d_x[Nn * Hh];
__device__ float d_pooled[Bb * Ss * Hh];
__device__ float d_t2[Bb * Ss * Hh];
__device__ float d_colsum[Ss];
__device__ float d_entsum[1];
__device__ int   d_bstart[Bb + 1];
__device__ __align__(256) __half d_wbf[4 * Hh * Hh];    // edge weights [w2,w3] x 2 layers (fp16)
__device__ __align__(256) __half d_wnode[458752];       // node weights hi/lo splits

// ================= warp-MMA helpers (sm_80-compatible PTX) =================
__device__ __forceinline__ uint32_t smem_u32(const void* p) {
    uint32_t a;
    asm("{ .reg .u64 t; cvta.to.shared.u64 t, %1; cvt.u32.u64 %0, t; }" : "=r"(a) : "l"(p));
    return a;
}
__device__ __forceinline__ void cp16(uint32_t saddr, const void* g) {
    asm volatile("cp.async.cg.shared.global [%0], [%1], 16;" :: "r"(saddr), "l"(g));
}
#define CP_COMMIT() asm volatile("cp.async.commit_group;" ::: "memory")
#define CP_WAIT2()  asm volatile("cp.async.wait_group 2;" ::: "memory")
#define CP_WAIT1()  asm volatile("cp.async.wait_group 1;" ::: "memory")
#define CP_WAIT0()  asm volatile("cp.async.wait_group 0;" ::: "memory")

#define LDSM4(r0, r1, r2, r3, addr) \
    asm volatile("ldmatrix.sync.aligned.m8n8.x4.shared.b16 {%0,%1,%2,%3}, [%4];" \
        : "=r"(r0), "=r"(r1), "=r"(r2), "=r"(r3) : "r"(addr))

__device__ __forceinline__ void mma16816(float* c,
    uint32_t a0, uint32_t a1, uint32_t a2, uint32_t a3, uint32_t b0, uint32_t b1) {
    asm volatile("mma.sync.aligned.m16n8k16.row.col.f32.f16.f16.f32 "
        "{%0,%1,%2,%3}, {%4,%5,%6,%7}, {%8,%9}, {%0,%1,%2,%3};"
        : "+f"(c[0]), "+f"(c[1]), "+f"(c[2]), "+f"(c[3])
        : "r"(a0), "r"(a1), "r"(a2), "r"(a3), "r"(b0), "r"(b1));
}

// ================= SMEM layout for edge kernel (bytes) =================
#define AROW    528                      // 256 fp16 + 16B pad (conflict-free ldmatrix)
#define SM_AHI  0                        // 128 * 528 = 67584
#define SM_BBUF 67584                    // 4 buffers x 8KB = 32768
#define SM_IDS  100352                   // sdst[128], ssrc[128]
#define SM_B2   101376
#define SM_B3   102400
#define SM_TOT  103424

// ---------------- edge weight transpose + fp16 convert ----------------
__global__ void wsplit_kernel(const float* __restrict__ w, __half* __restrict__ hi) {
    int i = blockIdx.x * 256 + threadIdx.x;   // i = n*256 + k
    int n = i >> 8, k = i & 255;
    hi[i] = __float2half_rn(w[k * Hh + n]);
}

// ---------------- node weight transpose + fp16 hi/lo split ----------------
__global__ void wsplit_node(const float* __restrict__ w, int K,
                            __half* __restrict__ hi, __half* __restrict__ lo) {
    int i = blockIdx.x * 256 + threadIdx.x;   // i = n*K + k
    int n = i / K, k = i - n * K;
    float v = w[k * Hh + n];
    __half h = __float2half_rn(v);
    hi[i] = h;
    lo[i] = __float2half_rn(v - __half2float(h));
}

// ---------------- edge B-slice loader (4-slot ring) ----------------
__device__ __forceinline__ void load_slice(int s, uint32_t sb, int t,
    const __half* w2, const __half* w3)
{
    const __half* Wh = (s < 16) ? w2 : w3;
    const int kt = s & 15;
    const uint32_t base = sb + SM_BBUF + (uint32_t)(s & 3) * 8192u;
    const int n = t >> 1;
    const int h = t & 1;
    const char* gh = (const char*)(Wh + (size_t)n * Hh + kt * 16) + h * 16;
    const uint32_t sw4 = (n & 4) ? 16u : 0u;
    const uint32_t doff = base + (uint32_t)n * 32u + (((uint32_t)h * 16u) ^ sw4);
    cp16(doff, gh);
}

// ---------------- fused tensor-core edge MLP (16 warps, 32x64 warp tiles, fp16 1-MMA) ---------
__global__ __launch_bounds__(512, 1) void edge_mma_kernel(
    const int* __restrict__ src, const int* __restrict__ dst,
    const __half* __restrict__ P, const __half* __restrict__ Q,
    const __half* __restrict__ w2, const __half* __restrict__ w3,
    const float* __restrict__ b2, const float* __restrict__ b3,
    float* __restrict__ agg)
{
    extern __shared__ char sm[];
    const uint32_t sb = smem_u32(sm);
    const int t = threadIdx.x;
    const int w = t >> 5, l = t & 31;
    const int wm = w & 3;
    const int wn = w >> 2;

    int* sdst = (int*)(sm + SM_IDS);
    int* ssrc = sdst + 128;
    float* sb2 = (float*)(sm + SM_B2);
    float* sb3 = (float*)(sm + SM_B3);

    if (t < 128) {
        sdst[t] = dst[blockIdx.x * 128 + t];
        ssrc[t] = src[blockIdx.x * 128 + t];
    }
    if (t < 256) {
        sb2[t] = b2[t];
        sb3[t] = b3[t];
    }
    // kick off B prefetch before A-build
    load_slice(0, sb, t, w2, w3); CP_COMMIT();
    load_slice(1, sb, t, w2, w3); CP_COMMIT();
    __syncthreads();

    // ---- build A = relu(P[dst] + Q[src]) in fp16 (half2 math) ----
    {
        const int e = t & 127, h = t >> 7;        // h in 0..3, 64 cols each
        const int de = sdst[e], se = ssrc[e];
        const uint4* Pr = reinterpret_cast<const uint4*>(P + (size_t)de * Hh + h * 64);
        const uint4* Qr = reinterpret_cast<const uint4*>(Q + (size_t)se * Hh + h * 64);
        const uint32_t arow = (uint32_t)e * AROW + (uint32_t)h * 128u;
        const __half2 z2 = __float2half2_rn(0.f);
#pragma unroll
        for (int j = 0; j < 8; j++) {
            union { uint4 u; __half2 h2[4]; } A_, B_, C_;
            A_.u = Pr[j];
            B_.u = Qr[j];
#pragma unroll
            for (int p = 0; p < 4; p++)
                C_.h2[p] = __hmax2(__hadd2(A_.h2[p], B_.h2[p]), z2);
            *(uint4*)(sm + SM_AHI + arow + j * 16) = C_.u;
        }
    }

    float acc[2][8][4];
#pragma unroll
    for (int mi = 0; mi < 2; mi++)
#pragma unroll
        for (int nj = 0; nj < 8; nj++) {
            acc[mi][nj][0] = 0.f; acc[mi][nj][1] = 0.f;
            acc[mi][nj][2] = 0.f; acc[mi][nj][3] = 0.f;
        }

    const uint32_t a_base = sb + (uint32_t)((32 * wm + (l % 16)) * AROW + (l / 16) * 16);
    const uint32_t b_off = (uint32_t)((l % 16) * 32) +
                           (uint32_t)(((l / 16) * 16) ^ (((l % 16) & 4) ? 16 : 0));

#pragma unroll 1
    for (int s = 0; s < 32; s++) {
        // load slice s+2 into ring slot (s+2)&3. Safe: that slot's previous
        // content (slice s-2) was consumed at iter s-2, and every warp passed
        // iter (s-1)'s barrier after that consume.
        if (s + 2 < 32) { load_slice(s + 2, sb, t, w2, w3); CP_COMMIT(); CP_WAIT2(); }
        else if (s + 2 == 32) { CP_WAIT1(); }
        else { CP_WAIT0(); }
        __syncthreads();   // slice s visible to all; ring slot reuse fence

        const int kt = s & 15;
        uint32_t ah[2][4];
#pragma unroll
        for (int mi = 0; mi < 2; mi++) {
            const uint32_t aa = a_base + (uint32_t)(16 * mi * AROW) + kt * 32;
            LDSM4(ah[mi][0], ah[mi][1], ah[mi][2], ah[mi][3], aa + SM_AHI);
        }

        const uint32_t bbase = sb + SM_BBUF + (uint32_t)(s & 3) * 8192u + b_off
                             + (uint32_t)(wn * 2048);
#pragma unroll
        for (int c = 0; c < 4; c++) {
            uint32_t bh0, bh1, bh2, bh3;
            LDSM4(bh0, bh1, bh2, bh3, bbase + c * 512);
#pragma unroll
            for (int mi = 0; mi < 2; mi++) {
                mma16816(acc[mi][2 * c],     ah[mi][0], ah[mi][1], ah[mi][2], ah[mi][3], bh0, bh2);
                mma16816(acc[mi][2 * c + 1], ah[mi][0], ah[mi][1], ah[mi][2], ah[mi][3], bh1, bh3);
            }
        }

        if (s == 15) {
            // all warps must finish reading A slice-15 frags before overwrite
            __syncthreads();
            // ---- epilogue 1: A := fp16(relu(D1 + b2)) for this warp's 32x64 tile ----
            const int cb = (l % 4) * 2;
#pragma unroll
            for (int mi = 0; mi < 2; mi++) {
                const int r0 = 32 * wm + 16 * mi + l / 4;
#pragma unroll
                for (int nj = 0; nj < 8; nj++) {
                    const int cn = 64 * wn + 8 * nj + cb;
                    const float bz0 = sb2[cn], bz1 = sb2[cn + 1];
                    __half2 hp0 = __floats2half2_rn(fmaxf(acc[mi][nj][0] + bz0, 0.f),
                                                    fmaxf(acc[mi][nj][1] + bz1, 0.f));
                    __half2 hp1 = __floats2half2_rn(fmaxf(acc[mi][nj][2] + bz0, 0.f),
                                                    fmaxf(acc[mi][nj][3] + bz1, 0.f));
                    *(uint32_t*)(sm + SM_AHI + r0 * AROW + cn * 2)       = *(uint32_t*)&hp0;
                    *(uint32_t*)(sm + SM_AHI + (r0 + 8) * AROW + cn * 2) = *(uint32_t*)&hp1;
                    acc[mi][nj][0] = 0.f; acc[mi][nj][1] = 0.f;
                    acc[mi][nj][2] = 0.f; acc[mi][nj][3] = 0.f;
                }
            }
            // iter-16's barrier orders these writes before the next A reads
        }
    }

    // ---- epilogue 2: agg[dst] += D2 + b3 ----
    {
        const int cb = (l % 4) * 2;
#pragma unroll
        for (int mi = 0; mi < 2; mi++) {
            const int er = 32 * wm + 16 * mi + l / 4;
            const int d0 = sdst[er], d1 = sdst[er + 8];
            float* a0 = agg + (size_t)d0 * Hh;
            float* a1 = agg + (size_t)d1 * Hh;
#pragma unroll
            for (int nj = 0; nj < 8; nj++) {
                const int cn = 64 * wn + 8 * nj + cb;
                const float bz0 = sb3[cn], bz1 = sb3[cn + 1];
                atomicAdd(a0 + cn,     acc[mi][nj][0] + bz0);
                atomicAdd(a0 + cn + 1, acc[mi][nj][1] + bz1);
                atomicAdd(a1 + cn,     acc[mi][nj][2] + bz0);
                atomicAdd(a1 + cn + 1, acc[mi][nj][3] + bz1);
            }
        }
    }
}

// ---------------- fused node GEMM pair: P = A@Wp ; Q = A@Wq + bq ; fp16 outputs ----------------
// A as single fp16; W pre-split fp16 hi/lo -> 2 MMAs per product (A*Whi + A*Wlo).
template <int K>
__global__ __launch_bounds__(512, 1) void gemm_mma_pq(
    const float* __restrict__ A,
    const __half* __restrict__ Wph, const __half* __restrict__ Wpl,
    const __half* __restrict__ Wqh, const __half* __restrict__ Wql,
    const float* __restrict__ biasq,
    __half* __restrict__ Pout, __half* __restrict__ Qout, int M)
{
    constexpr int AROWK = K * 2 + 16;
    constexpr int SA_HI = 0;
    constexpr int S_BB  = 128 * AROWK;
    constexpr int S_BIAS = S_BB + 32768;
    constexpr int NS = K / 16;
    constexpr int TOT = 2 * NS;

    extern __shared__ char sm[];
    const uint32_t sb = smem_u32(sm);
    const int t = threadIdx.x;
    const int w = t >> 5, l = t & 31;
    const int wm = w & 3;
    const int wn = w >> 2;

    float* sbias = (float*)(sm + S_BIAS);
    if (t < 256) sbias[t] = biasq[t];

    // ---- load A rows as fp16 ----
    {
        const int e = t & 127, h = t >> 7;
        const int grow = blockIdx.x * 128 + e;
        constexpr int cpt = K / 4;
        const uint32_t arow = (uint32_t)e * AROWK + (uint32_t)h * (cpt * 2);
        if (grow < M) {
            const float4* Ar = reinterpret_cast<const float4*>(A + (size_t)grow * K) + h * (cpt / 4);
#pragma unroll
            for (int j = 0; j < cpt / 8; j++) {
                float4 a0 = Ar[2 * j], a1 = Ar[2 * j + 1];
                union { uint4 u; __half2 h2[4]; } HI;
                HI.h2[0] = __floats2half2_rn(a0.x, a0.y);
                HI.h2[1] = __floats2half2_rn(a0.z, a0.w);
                HI.h2[2] = __floats2half2_rn(a1.x, a1.y);
                HI.h2[3] = __floats2half2_rn(a1.z, a1.w);
                *(uint4*)(sm + SA_HI + arow + j * 16) = HI.u;
            }
        } else {
            const uint4 z = make_uint4(0, 0, 0, 0);
#pragma unroll
            for (int j = 0; j < cpt / 8; j++)
                *(uint4*)(sm + SA_HI + arow + j * 16) = z;
        }
    }

    float acc[2][8][4];
#pragma unroll
    for (int mi = 0; mi < 2; mi++)
#pragma unroll
        for (int nj = 0; nj < 8; nj++) {
            acc[mi][nj][0] = 0.f; acc[mi][nj][1] = 0.f;
            acc[mi][nj][2] = 0.f; acc[mi][nj][3] = 0.f;
        }

    const uint32_t a_base = sb + (uint32_t)((32 * wm + (l % 16)) * AROWK + (l / 16) * 16);
    const uint32_t b_off = (uint32_t)((l % 16) * 32) +
                           (uint32_t)(((l / 16) * 16) ^ (((l % 16) & 4) ? 16 : 0));

    auto load_b = [&](int s) {
        const __half* Bh = (s < NS) ? Wph : Wqh;
        const __half* Bl = (s < NS) ? Wpl : Wql;
        const int kt = s & (NS - 1);
        const uint32_t base = sb + S_BB + (uint32_t)(s & 1) * 16384u;
        const int n = t >> 1;
        const int h = t & 1;
        const char* gh = (const char*)(Bh + (size_t)n * K + kt * 16) + h * 16;
        const char* gl = (const char*)(Bl + (size_t)n * K + kt * 16) + h * 16;
        const uint32_t sw4 = (n & 4) ? 16u : 0u;
        const uint32_t doff = base + (uint32_t)n * 32u + (((uint32_t)h * 16u) ^ sw4);
        cp16(doff, gh);
        cp16(doff + 8192u, gl);
    };

    load_b(0); CP_COMMIT();
    load_b(1); CP_COMMIT();

    const int e_r0base = blockIdx.x * 128;

#pragma unroll 1
    for (int s = 0; s < TOT; s++) {
        if (s < TOT - 2) { CP_WAIT1(); } else { CP_WAIT0(); }
        __syncthreads();

        const int kt = s & (NS - 1);
        uint32_t ah[2][4];
#pragma unroll
        for (int mi = 0; mi < 2; mi++) {
            const uint32_t aa = a_base + (uint32_t)(16 * mi * AROWK) + kt * 32;
            LDSM4(ah[mi][0], ah[mi][1], ah[mi][2], ah[mi][3], aa + SA_HI);
        }

        const uint32_t bbase = sb + S_BB + (uint32_t)(s & 1) * 16384u + b_off
                             + (uint32_t)(wn * 2048);
#pragma unroll
        for (int c = 0; c < 4; c++) {
            uint32_t bh0, bh1, bh2, bh3, bl0, bl1, bl2, bl3;
            LDSM4(bh0, bh1, bh2, bh3, bbase + c * 512);
            LDSM4(bl0, bl1, bl2, bl3, bbase + 8192 + c * 512);
#pragma unroll
            for (int mi = 0; mi < 2; mi++) {
                float* c0 = acc[mi][2 * c];
                float* c1 = acc[mi][2 * c + 1];
                mma16816(c0, ah[mi][0], ah[mi][1], ah[mi][2], ah[mi][3], bh0, bh2);
                mma16816(c0, ah[mi][0], ah[mi][1], ah[mi][2], ah[mi][3], bl0, bl2);
                mma16816(c1, ah[mi][0], ah[mi][1], ah[mi][2], ah[mi][3], bh1, bh3);
                mma16816(c1, ah[mi][0], ah[mi][1], ah[mi][2], ah[mi][3], bl1, bl3);
            }
        }

        if (s == NS - 1) {
            // ---- write P (no bias), reset acc ----
            const int cb = (l % 4) * 2;
#pragma unroll
            for (int mi = 0; mi < 2; mi++) {
                const int r0 = 32 * wm + 16 * mi + l / 4;
                const int g0 = e_r0base + r0;
                const int g1 = g0 + 8;
#pragma unroll
                for (int nj = 0; nj < 8; nj++) {
                    const int cn = 64 * wn + 8 * nj + cb;
                    __half2 hp0 = __floats2half2_rn(acc[mi][nj][0], acc[mi][nj][1]);
                    __half2 hp1 = __floats2half2_rn(acc[mi][nj][2], acc[mi][nj][3]);
                    if (g0 < M) *(uint32_t*)(Pout + (size_t)g0 * Hh + cn) = *(uint32_t*)&hp0;
                    if (g1 < M) *(uint32_t*)(Pout + (size_t)g1 * Hh + cn) = *(uint32_t*)&hp1;
                    acc[mi][nj][0] = 0.f; acc[mi][nj][1] = 0.f;
                    acc[mi][nj][2] = 0.f; acc[mi][nj][3] = 0.f;
                }
            }
        }
        __syncthreads();
        if (s + 2 < TOT) {
            load_b(s + 2);
            CP_COMMIT();
        }
    }

    // ---- write Q (+ biasq) ----
    {
        const int cb = (l % 4) * 2;
#pragma unroll
        for (int mi = 0; mi < 2; mi++) {
            const int r0 = 32 * wm + 16 * mi + l / 4;
            const int g0 = e_r0base + r0;
            const int g1 = g0 + 8;
#pragma unroll
            for (int nj = 0; nj < 8; nj++) {
                const int cn = 64 * wn + 8 * nj + cb;
                const float bz0 = sbias[cn], bz1 = sbias[cn + 1];
                __half2 hp0 = __floats2half2_rn(acc[mi][nj][0] + bz0, acc[mi][nj][1] + bz1);
                __half2 hp1 = __floats2half2_rn(acc[mi][nj][2] + bz0, acc[mi][nj][3] + bz1);
                if (g0 < M) *(uint32_t*)(Qout + (size_t)g0 * Hh + cn) = *(uint32_t*)&hp0;
                if (g1 < M) *(uint32_t*)(Qout + (size_t)g1 * Hh + cn) = *(uint32_t*)&hp1;
            }
        }
    }
}

// ---------------- tensor-core node GEMM (fp32 out, for assign hidden; A fp16, W hi/lo) -------
template <int K, bool RELU>
__global__ __launch_bounds__(512, 1) void gemm_mma(
    const float* __restrict__ A,
    const __half* __restrict__ Whi, const __half* __restrict__ Wlo,
    const float* __restrict__ bias, float* __restrict__ C, int M)
{
    constexpr int AROWK = K * 2 + 16;
    constexpr int SA_HI = 0;
    constexpr int S_BB  = 128 * AROWK;
    constexpr int S_BIAS = S_BB + 32768;
    constexpr int NS = K / 16;

    extern __shared__ char sm[];
    const uint32_t sb = smem_u32(sm);
    const int t = threadIdx.x;
    const int w = t >> 5, l = t & 31;
    const int wm = w & 3;
    const int wn = w >> 2;

    float* sbias = (float*)(sm + S_BIAS);
    if (t < 256) sbias[t] = bias ? bias[t] : 0.f;

    {
        const int e = t & 127, h = t >> 7;
        const int grow = blockIdx.x * 128 + e;
        constexpr int cpt = K / 4;
        const uint32_t arow = (uint32_t)e * AROWK + (uint32_t)h * (cpt * 2);
        if (grow < M) {
            const float4* Ar = reinterpret_cast<const float4*>(A + (size_t)grow * K) + h * (cpt / 4);
#pragma unroll
            for (int j = 0; j < cpt / 8; j++) {
                float4 a0 = Ar[2 * j], a1 = Ar[2 * j + 1];
                union { uint4 u; __half2 h2[4]; } HI;
                HI.h2[0] = __floats2half2_rn(a0.x, a0.y);
                HI.h2[1] = __floats2half2_rn(a0.z, a0.w);
                HI.h2[2] = __floats2half2_rn(a1.x, a1.y);
                HI.h2[3] = __floats2half2_rn(a1.z, a1.w);
                *(uint4*)(sm + SA_HI + arow + j * 16) = HI.u;
            }
        } else {
            const uint4 z = make_uint4(0, 0, 0, 0);
#pragma unroll
            for (int j = 0; j < cpt / 8; j++)
                *(uint4*)(sm + SA_HI + arow + j * 16) = z;
        }
    }

    float acc[2][8][4];
#pragma unroll
    for (int mi = 0; mi < 2; mi++)
#pragma unroll
        for (int nj = 0; nj < 8; nj++) {
            acc[mi][nj][0] = 0.f; acc[mi][nj][1] = 0.f;
            acc[mi][nj][2] = 0.f; acc[mi][nj][3] = 0.f;
        }

    const uint32_t a_base = sb + (uint32_t)((32 * wm + (l % 16)) * AROWK + (l / 16) * 16);
    const uint32_t b_off = (uint32_t)((l % 16) * 32) +
                           (uint32_t)(((l / 16) * 16) ^ (((l % 16) & 4) ? 16 : 0));

    auto load_b = [&](int s) {
        const uint32_t base = sb + S_BB + (uint32_t)(s & 1) * 16384u;
        const int n = t >> 1;
        const int h = t & 1;
        const char* gh = (const char*)(Whi + (size_t)n * K + s * 16) + h * 16;
        const char* gl = (const char*)(Wlo + (size_t)n * K + s * 16) + h * 16;
        const uint32_t sw4 = (n & 4) ? 16u : 0u;
        const uint32_t doff = base + (uint32_t)n * 32u + (((uint32_t)h * 16u) ^ sw4);
        cp16(doff, gh);
        cp16(doff + 8192u, gl);
    };

    load_b(0); CP_COMMIT();
    load_b(1); CP_COMMIT();

#pragma unroll 1
    for (int s = 0; s < NS; s++) {
        if (s < NS - 2) { CP_WAIT1(); } else { CP_WAIT0(); }
        __syncthreads();

        uint32_t ah[2][4];
#pragma unroll
        for (int mi = 0; mi < 2; mi++) {
            const uint32_t aa = a_base + (uint32_t)(16 * mi * AROWK) + s * 32;
            LDSM4(ah[mi][0], ah[mi][1], ah[mi][2], ah[mi][3], aa + SA_HI);
        }

        const uint32_t bbase = sb + S_BB + (uint32_t)(s & 1) * 16384u + b_off
                             + (uint32_t)(wn * 2048);
#pragma unroll
        for (int c = 0; c < 4; c++) {
            uint32_t bh0, bh1, bh2, bh3, bl0, bl1, bl2, bl3;
            LDSM4(bh0, bh1, bh2, bh3, bbase + c * 512);
            LDSM4(bl0, bl1, bl2, bl3, bbase + 8192 + c * 512);
#pragma unroll
            for (int mi = 0; mi < 2; mi++) {
                float* c0 = acc[mi][2 * c];
                float* c1 = acc[mi][2 * c + 1];
                mma16816(c0, ah[mi][0], ah[mi][1], ah[mi][2], ah[mi][3], bh0, bh2);
                mma16816(c0, ah[mi][0], ah[mi][1], ah[mi][2], ah[mi][3], bl0, bl2);
                mma16816(c1, ah[mi][0], ah[mi][1], ah[mi][2], ah[mi][3], bh1, bh3);
                mma16816(c1, ah[mi][0], ah[mi][1], ah[mi][2], ah[mi][3], bl1, bl3);
            }
        }
        __syncthreads();
        if (s + 2 < NS) {
            load_b(s + 2);
            CP_COMMIT();
        }
    }

    {
        const int cb = (l % 4) * 2;
#pragma unroll
        for (int mi = 0; mi < 2; mi++) {
            const int r0 = 32 * wm + 16 * mi + l / 4;
            const int g0 = blockIdx.x * 128 + r0;
            const int g1 = g0 + 8;
#pragma unroll
            for (int nj = 0; nj < 8; nj++) {
                const int cn = 64 * wn + 8 * nj + cb;
                const float bz0 = sbias[cn], bz1 = sbias[cn + 1];
                float v0 = acc[mi][nj][0] + bz0, v1 = acc[mi][nj][1] + bz1;
                float v2 = acc[mi][nj][2] + bz0, v3 = acc[mi][nj][3] + bz1;
                if (RELU) {
                    v0 = fmaxf(v0, 0.f); v1 = fmaxf(v1, 0.f);
                    v2 = fmaxf(v2, 0.f); v3 = fmaxf(v3, 0.f);
                }
                if (g0 < M) { float2 o = make_float2(v0, v1); *(float2*)(C + (size_t)g0 * Hh + cn) = o; }
                if (g1 < M) { float2 o = make_float2(v2, v3); *(float2*)(C + (size_t)g1 * Hh + cn) = o; }
            }
        }
    }
}

// ---------------- zero ----------------
__global__ void zero_kernel(float* p, int n) {
    int i = blockIdx.x * blockDim.x + threadIdx.x;
    if (i < n) p[i] = 0.f;
}

// ---------------- generic row-tiled fp32 GEMM (small outputs only) ----------------
template <int NCOL, int RPB>
__global__ __launch_bounds__(256) void gemm_tiled(
    const float* __restrict__ A, int K,
    const float* __restrict__ W, const float* __restrict__ bias,
    float* __restrict__ C, int M, int do_relu)
{
    __shared__ float As[RPB * 256];
    const int row0 = blockIdx.x * RPB;
    const int tot = RPB * K;
    for (int idx = threadIdx.x; idx < tot; idx += 256) {
        int r = idx / K, k = idx - r * K;
        int gr = row0 + r;
        As[idx] = (gr < M) ? A[gr * K + k] : 0.f;
    }
    __syncthreads();

    const int RG = 256 / NCOL;
    const int RPT = RPB / RG;
    const int col = threadIdx.x % NCOL;
    const int rg = threadIdx.x / NCOL;

    float acc[RPT];
    float bv = bias ? bias[col] : 0.f;
#pragma unroll
    for (int i = 0; i < RPT; i++) acc[i] = bv;

    for (int k = 0; k < K; k += 4) {
        float wv0 = W[(k + 0) * NCOL + col];
        float wv1 = W[(k + 1) * NCOL + col];
        float wv2 = W[(k + 2) * NCOL + col];
        float wv3 = W[(k + 3) * NCOL + col];
#pragma unroll
        for (int i = 0; i < RPT; i++) {
            const float4 a = *(const float4*)&As[(rg + i * RG) * K + k];
            acc[i] = fmaf(a.x, wv0, acc[i]);
            acc[i] = fmaf(a.y, wv1, acc[i]);
            acc[i] = fmaf(a.z, wv2, acc[i]);
            acc[i] = fmaf(a.w, wv3, acc[i]);
        }
    }
#pragma unroll
    for (int i = 0; i < RPT; i++) {
        int gr = row0 + rg + i * RG;
        if (gr < M) {
            float v = acc[i];
            if (do_relu) v = fmaxf(v, 0.f);
            C[gr * NCOL + col] = v;
        }
    }
}

// ---------------- relu + layernorm per node (also re-zeroes agg for next layer) --------------
__device__ __forceinline__ float warp_sum(float v) {
#pragma unroll
    for (int o = 16; o > 0; o >>= 1) v += __shfl_xor_sync(0xFFFFFFFFu, v, o);
    return v;
}

__global__ __launch_bounds__(256) void relu_ln_kernel(
    float* __restrict__ agg, const float* __restrict__ g,
    const float* __restrict__ b, float* __restrict__ xout)
{
    const int n = blockIdx.x;
    const int j = threadIdx.x;
    const int lane = j & 31, warp = j >> 5;
    __shared__ float red[8];
    __shared__ float s_mu, s_rstd;

    float v = fmaxf(agg[n * Hh + j], 0.f);
    agg[n * Hh + j] = 0.f;             // reset accumulator for the next edge layer
    float t = warp_sum(v);
    if (lane == 0) red[warp] = t;
    __syncthreads();
    if (j == 0) {
        float s = 0.f;
#pragma unroll
        for (int i = 0; i < 8; i++) s += red[i];
        s_mu = s / (float)Hh;
    }
    __syncthreads();
    float d = v - s_mu;
    float t2 = warp_sum(d * d);
    if (lane == 0) red[warp] = t2;
    __syncthreads();
    if (j == 0) {
        float s = 0.f;
#pragma unroll
        for (int i = 0; i < 8; i++) s += red[i];
        s_rstd = rsqrtf(s / (float)Hh + 1e-5f);
    }
    __syncthreads();
    xout[n * Hh + j] = d * s_rstd * g[j] + b[j];
}

// ---------------- assignment ----------------
__global__ __launch_bounds__(256) void assign_kernel(
    const float* __restrict__ t1, const float* __restrict__ aw2,
    const float* __restrict__ ab2, const float* __restrict__ u,
    float* __restrict__ s_out, float* __restrict__ entsum, float* __restrict__ colsum)
{
    __shared__ float rows[8 * Hh];
    __shared__ float blk_col[Ss];
    __shared__ float blk_ent;

    const int lane = threadIdx.x & 31, warp = threadIdx.x >> 5;
    if (threadIdx.x < Ss) blk_col[threadIdx.x] = 0.f;
    if (threadIdx.x == 0) blk_ent = 0.f;
    const int n0 = blockIdx.x * 8;
    for (int idx = threadIdx.x; idx < 8 * Hh; idx += 256)
        rows[idx] = t1[n0 * Hh + idx];
    __syncthreads();

    const int n = n0 + warp;
    float acc = ab2[lane];
    for (int k = 0; k < Hh; k += 4) {
        const float4 a = *(const float4*)&rows[warp * Hh + k];
        acc = fmaf(a.x, aw2[(k + 0) * Ss + lane], acc);
        acc = fmaf(a.y, aw2[(k + 1) * Ss + lane], acc);
        acc = fmaf(a.z, aw2[(k + 2) * Ss + lane], acc);
        acc = fmaf(a.w, aw2[(k + 3) * Ss + lane], acc);
    }
    float uu = u[n * Ss + lane];
    float gmb = -logf(-logf(uu + EPS_F) + EPS_F);
    float z = acc + gmb;
    float m = z;
#pragma unroll
    for (int o = 16; o > 0; o >>= 1) m = fmaxf(m, __shfl_xor_sync(0xFFFFFFFFu, m, o));
    float p = expf(z - m);
    float sum = warp_sum(p);
    float sv = p / sum;
    s_out[n * Ss + lane] = sv;

    float ent = warp_sum(sv * logf(sv + EPS_F));
    if (lane == 0) atomicAdd(&blk_ent, ent);
    atomicAdd(&blk_col[lane], sv);
    __syncthreads();
    if (threadIdx.x == 0) atomicAdd(entsum, blk_ent);
    if (threadIdx.x < Ss) atomicAdd(&colsum[threadIdx.x], blk_col[threadIdx.x]);
}

// ---------------- batch segment starts ----------------
__global__ void bstart_kernel(const int* __restrict__ batch, int* __restrict__ bstart) {
    int b = threadIdx.x;
    if (b > Bb) return;
    if (b == Bb) { bstart[Bb] = Nn; return; }
    int lo = 0, hi = Nn;
    while (lo < hi) {
        int mid = (lo + hi) >> 1;
        if (batch[mid] < b) lo = mid + 1; else hi = mid;
    }
    bstart[b] = lo;
}

// ---------------- pooling ----------------
__global__ __launch_bounds__(256) void pool_kernel(
    const float* __restrict__ x, const float* __restrict__ s_out,
    const int* __restrict__ bstart, float* __restrict__ pooled)
{
    const int b = blockIdx.x;
    const int chunk = blockIdx.y;
    const int NCHUNK = gridDim.y;
    const int lo = bstart[b], hi = bstart[b + 1];
    const int cnt = hi - lo;
    const int c0 = lo + (int)(((long long)cnt * chunk) / NCHUNK);
    const int c1 = lo + (int)(((long long)cnt * (chunk + 1)) / NCHUNK);

    __shared__ float ss[Ss];
    const int t = threadIdx.x;
    float acc[Ss];
#pragma unroll
    for (int sl = 0; sl < Ss; sl++) acc[sl] = 0.f;

    for (int n = c0; n < c1; n++) {
        __syncthreads();
        if (t < Ss) ss[t] = s_out[n * Ss + t];
        __syncthreads();
        float xv = x[n * Hh + t];
#pragma unroll
        for (int sl = 0; sl < Ss; sl++) acc[sl] = fmaf(xv, ss[sl], acc[sl]);
    }
#pragma unroll
    for (int sl = 0; sl < Ss; sl++)
        atomicAdd(&pooled[(b * Ss + sl) * Hh + t], acc[sl]);
}

// ---------------- final scalar loss ----------------
__global__ void finalize_kernel(const float* __restrict__ colsum,
                                const float* __restrict__ entsum,
                                float* __restrict__ out_loss)
{
    int l = threadIdx.x;
    float avg = colsum[l] / (float)Nn;
    float dv = avg * logf(avg + EPS_F);
    dv = warp_sum(dv);
    if (l == 0) {
        float entropy = -(entsum[0] / (float)Nn);
        out_loss[0] = entropy + dv;
    }
}

// ---------------- launch ----------------
extern "C" void kernel_launch(void* const* d_in, const int* in_sizes, int n_in,
                              void* d_out, int out_size)
{
    const float* x    = (const float*)d_in[0];
    const float* u    = (const float*)d_in[1];
    const int* eidx   = (const int*)d_in[2];
    const int* batch  = (const int*)d_in[3];
    const float* g1w1 = (const float*)d_in[4];
    const float* g1b1 = (const float*)d_in[5];
    const float* g1w2 = (const float*)d_in[6];
    const float* g1b2 = (const float*)d_in[7];
    const float* g1w3 = (const float*)d_in[8];
    const float* g1b3 = (const float*)d_in[9];
    const float* ln1g = (const float*)d_in[10];
    const float* ln1b = (const float*)d_in[11];
    const float* g2w1 = (const float*)d_in[12];
    const float* g2b1 = (const float*)d_in[13];
    const float* g2w2 = (const float*)d_in[14];
    const float* g2b2 = (const float*)d_in[15];
    const float* g2w3 = (const float*)d_in[16];
    const float* g2b3 = (const float*)d_in[17];
    const float* ln2g = (const float*)d_in[18];
    const float* ln2b = (const float*)d_in[19];
    const float* aw1  = (const float*)d_in[20];
    const float* ab1  = (const float*)d_in[21];
    const float* aw2  = (const float*)d_in[22];
    const float* ab2  = (const float*)d_in[23];
    const float* ow1  = (const float*)d_in[24];
    const float* ob1  = (const float*)d_in[25];
    const float* ow2  = (const float*)d_in[26];
    const float* ob2  = (const float*)d_in[27];

    const int* src = eidx;
    const int* dst = eidx + Ee;

    float* out = (float*)d_out;
    float* out_latent = out;
    float* out_s = out + Bb * Ss * Ll;
    float* out_loss = out + Bb * Ss * Ll + Nn * Ss;

    float *P, *agg, *xc, *pooled, *t2, *colsum, *entsum;
    __half *Ph, *Qh;
    int* bstart;
    __half *wbf, *wn;
    cudaGetSymbolAddress((void**)&P, d_P);
    cudaGetSymbolAddress((void**)&Ph, d_Ph);
    cudaGetSymbolAddress((void**)&Qh, d_Qh);
    cudaGetSymbolAddress((void**)&agg, d_agg);
    cudaGetSymbolAddress((void**)&xc, d_x);
    cudaGetSymbolAddress((void**)&pooled, d_pooled);
    cudaGetSymbolAddress((void**)&t2, d_t2);
    cudaGetSymbolAddress((void**)&colsum, d_colsum);
    cudaGetSymbolAddress((void**)&entsum, d_entsum);
    cudaGetSymbolAddress((void**)&bstart, d_bstart);
    cudaGetSymbolAddress((void**)&wbf, d_wbf);
    cudaGetSymbolAddress((void**)&wn, d_wnode);

    cudaFuncSetAttribute(edge_mma_kernel, cudaFuncAttributeMaxDynamicSharedMemorySize, SM_TOT);
    cudaFuncSetAttribute(gemm_mma_pq<64>,  cudaFuncAttributeMaxDynamicSharedMemorySize, 52224);
    cudaFuncSetAttribute(gemm_mma_pq<256>, cudaFuncAttributeMaxDynamicSharedMemorySize, 101376);
    cudaFuncSetAttribute(gemm_mma<256, true>, cudaFuncAttributeMaxDynamicSharedMemorySize, 101376);

    const int NH = Nn * Hh;
    const int ZB = 256;
    const int WN = Hh * Hh;   // 65536
    const int GB = (Nn + 127) / 128;   // 157

    // node weight split offsets (halfs)
    __half* g1Ph = wn + 0;       __half* g1Pl = wn + 16384;
    __half* g1Qh = wn + 32768;   __half* g1Ql = wn + 49152;
    __half* g2Ph = wn + 65536;   __half* g2Pl = wn + 131072;
    __half* g2Qh = wn + 196608;  __half* g2Ql = wn + 262144;
    __half* awh  = wn + 327680;  __half* awl  = wn + 393216;

    // ---- zero accumulators ----
    zero_kernel<<<(NH + ZB - 1) / ZB, ZB>>>(agg, NH);
    zero_kernel<<<(Bb * Ss * Hh + ZB - 1) / ZB, ZB>>>(pooled, Bb * Ss * Hh);
    zero_kernel<<<1, ZB>>>(colsum, Ss);
    zero_kernel<<<1, ZB>>>(entsum, 1);

    // ---- edge weights: transpose + fp16 ----
    wsplit_kernel<<<256, 256>>>(g1w2, wbf + 0 * WN);
    wsplit_kernel<<<256, 256>>>(g1w3, wbf + 1 * WN);
    wsplit_kernel<<<256, 256>>>(g2w2, wbf + 2 * WN);
    wsplit_kernel<<<256, 256>>>(g2w3, wbf + 3 * WN);

    // ---- node weights: transpose + fp16 hi/lo split ----
    wsplit_node<<<64, 256>>>(g1w1,            64,  g1Ph, g1Pl);
    wsplit_node<<<64, 256>>>(g1w1 + 64 * Hh,  64,  g1Qh, g1Ql);
    wsplit_node<<<256, 256>>>(g2w1,           256, g2Ph, g2Pl);
    wsplit_node<<<256, 256>>>(g2w1 + Hh * Hh, 256, g2Qh, g2Ql);
    wsplit_node<<<256, 256>>>(aw1,            256, awh,  awl);

    // ---- GNN layer 1 ----
    gemm_mma_pq<64><<<GB, 512, 52224>>>(x, g1Ph, g1Pl, g1Qh, g1Ql, g1b1, Ph, Qh, Nn);
    edge_mma_kernel<<<Ee / 128, 512, SM_TOT>>>(src, dst, Ph, Qh,
        wbf + 0 * WN, wbf + 1 * WN, g1b2, g1b3, agg);
    relu_ln_kernel<<<Nn, 256>>>(agg, ln1g, ln1b, xc);   // also re-zeroes agg

    // ---- GNN layer 2 ----
    gemm_mma_pq<256><<<GB, 512, 101376>>>(xc, g2Ph, g2Pl, g2Qh, g2Ql, g2b1, Ph, Qh, Nn);
    edge_mma_kernel<<<Ee / 128, 512, SM_TOT>>>(src, dst, Ph, Qh,
        wbf + 2 * WN, wbf + 3 * WN, g2b2, g2b3, agg);
    relu_ln_kernel<<<Nn, 256>>>(agg, ln2g, ln2b, xc);

    // ---- assignment ----
    gemm_mma<256, true><<<GB, 512, 101376>>>(xc, awh, awl, ab1, P, Nn);
    assign_kernel<<<Nn / 8, 256>>>(P, aw2, ab2, u, out_s, entsum, colsum);

    // ---- pooling ----
    bstart_kernel<<<1, 32>>>(batch, bstart);
    {
        dim3 grid(Bb, 8);
        pool_kernel<<<grid, 256>>>(xc, out_s, bstart, pooled);
    }

    // ---- output MLP ----
    gemm_tiled<Hh, 32><<<(Bb * Ss) / 32, 256>>>(pooled, Hh, ow1, ob1, t2, Bb * Ss, 1);
    gemm_tiled<Ll, 32><<<(Bb * Ss) / 32, 256>>>(t2, Hh, ow2, ob2, out_latent, Bb * Ss, 0);

    // ---- loss scalar ----
    finalize_kernel<<<1, 32>>>(colsum, entsum, out_loss);
}

// round 16
// speedup vs baseline: 4.2159x; 1.0094x over previous
#include <cuda_runtime.h>
#include <cuda_fp16.h>
#include <math.h>
#include <stdint.h>

#define Nn 20000
#define Ee 320000
#define Ff 64
#define Hh 256
#define Ss 32
#define Ll 128
#define Bb 16
#define EPS_F 1e-9f

// ---------------- scratch (device globals; no allocation allowed) ----------------
__device__ float d_P[Nn * Hh];          // fp32 (assign t1)
__device__ __half d_Ph[Nn * Hh];        // fp16 P for edge layers
__device__ __half d_Qh[Nn * Hh];        // fp16 Q for edge layers
__device__ float d_agg[Nn * Hh];
__device__ float d_x[Nn * Hh];          // fp32 LN output (pooling)
__device__ __half d_xh[Nn * Hh];        // fp16 LN output (node GEMM A operand)
__device__ float d_pooled[Bb * Ss * Hh];
__device__ float d_t2[Bb * Ss * Hh];
__device__ float d_colsum[Ss];
__device__ float d_entsum[1];
__device__ int   d_bstart[Bb + 1];
__device__ __align__(256) __half d_wbf[4 * Hh * Hh];    // edge weights [w2,w3] x 2 layers (fp16)
__device__ __align__(256) __half d_wnode[458752];       // node weights hi/lo splits

// ================= warp-MMA helpers (sm_80-compatible PTX) =================
__device__ __forceinline__ uint32_t smem_u32(const void* p) {
    uint32_t a;
    asm("{ .reg .u64 t; cvta.to.shared.u64 t, %1; cvt.u32.u64 %0, t; }" : "=r"(a) : "l"(p));
    return a;
}
__device__ __forceinline__ void cp16(uint32_t saddr, const void* g) {
    asm volatile("cp.async.cg.shared.global [%0], [%1], 16;" :: "r"(saddr), "l"(g));
}
#define CP_COMMIT() asm volatile("cp.async.commit_group;" ::: "memory")
#define CP_WAIT2()  asm volatile("cp.async.wait_group 2;" ::: "memory")
#define CP_WAIT1()  asm volatile("cp.async.wait_group 1;" ::: "memory")
#define CP_WAIT0()  asm volatile("cp.async.wait_group 0;" ::: "memory")

#define LDSM4(r0, r1, r2, r3, addr) \
    asm volatile("ldmatrix.sync.aligned.m8n8.x4.shared.b16 {%0,%1,%2,%3}, [%4];" \
        : "=r"(r0), "=r"(r1), "=r"(r2), "=r"(r3) : "r"(addr))

__device__ __forceinline__ void mma16816(float* c,
    uint32_t a0, uint32_t a1, uint32_t a2, uint32_t a3, uint32_t b0, uint32_t b1) {
    asm volatile("mma.sync.aligned.m16n8k16.row.col.f32.f16.f16.f32 "
        "{%0,%1,%2,%3}, {%4,%5,%6,%7}, {%8,%9}, {%0,%1,%2,%3};"
        : "+f"(c[0]), "+f"(c[1]), "+f"(c[2]), "+f"(c[3])
        : "r"(a0), "r"(a1), "r"(a2), "r"(a3), "r"(b0), "r"(b1));
}

// no-return vectorized global reduction (sm_90+ base PTX)
__device__ __forceinline__ void red_add_v2(float* addr, float v0, float v1) {
    asm volatile("red.global.add.v2.f32 [%0], {%1, %2};"
        :: "l"(addr), "f"(v0), "f"(v1) : "memory");
}

// ================= SMEM layout for edge kernel (bytes) =================
#define AROW    528                      // 256 fp16 + 16B pad (conflict-free ldmatrix)
#define SM_AHI  0                        // 128 * 528 = 67584
#define SM_BBUF 67584                    // 4 buffers x 8KB = 32768
#define SM_IDS  100352                   // sdst[128], ssrc[128]
#define SM_B2   101376
#define SM_B3   102400
#define SM_TOT  103424

// ---------------- edge weight transpose + fp16 convert ----------------
__global__ void wsplit_kernel(const float* __restrict__ w, __half* __restrict__ hi) {
    int i = blockIdx.x * 256 + threadIdx.x;   // i = n*256 + k
    int n = i >> 8, k = i & 255;
    hi[i] = __float2half_rn(w[k * Hh + n]);
}

// ---------------- node weight transpose + fp16 hi/lo split ----------------
__global__ void wsplit_node(const float* __restrict__ w, int K,
                            __half* __restrict__ hi, __half* __restrict__ lo) {
    int i = blockIdx.x * 256 + threadIdx.x;   // i = n*K + k
    int n = i / K, k = i - n * K;
    float v = w[k * Hh + n];
    __half h = __float2half_rn(v);
    hi[i] = h;
    lo[i] = __float2half_rn(v - __half2float(h));
}

// ---------------- edge B-slice loader (4-slot ring) ----------------
__device__ __forceinline__ void load_slice(int s, uint32_t sb, int t,
    const __half* w2, const __half* w3)
{
    const __half* Wh = (s < 16) ? w2 : w3;
    const int kt = s & 15;
    const uint32_t base = sb + SM_BBUF + (uint32_t)(s & 3) * 8192u;
    const int n = t >> 1;
    const int h = t & 1;
    const char* gh = (const char*)(Wh + (size_t)n * Hh + kt * 16) + h * 16;
    const uint32_t sw4 = (n & 4) ? 16u : 0u;
    const uint32_t doff = base + (uint32_t)n * 32u + (((uint32_t)h * 16u) ^ sw4);
    cp16(doff, gh);
}

// ---------------- fused tensor-core edge MLP (16 warps, 32x64 warp tiles, fp16 1-MMA) ---------
__global__ __launch_bounds__(512, 1) void edge_mma_kernel(
    const int* __restrict__ src, const int* __restrict__ dst,
    const __half* __restrict__ P, const __half* __restrict__ Q,
    const __half* __restrict__ w2, const __half* __restrict__ w3,
    const float* __restrict__ b2, const float* __restrict__ b3,
    float* __restrict__ agg)
{
    extern __shared__ char sm[];
    const uint32_t sb = smem_u32(sm);
    const int t = threadIdx.x;
    const int w = t >> 5, l = t & 31;
    const int wm = w & 3;
    const int wn = w >> 2;

    int* sdst = (int*)(sm + SM_IDS);
    int* ssrc = sdst + 128;
    float* sb2 = (float*)(sm + SM_B2);
    float* sb3 = (float*)(sm + SM_B3);

    if (t < 128) {
        sdst[t] = dst[blockIdx.x * 128 + t];
        ssrc[t] = src[blockIdx.x * 128 + t];
    }
    if (t < 256) {
        sb2[t] = b2[t];
        sb3[t] = b3[t];
    }
    // kick off B prefetch before A-build
    load_slice(0, sb, t, w2, w3); CP_COMMIT();
    load_slice(1, sb, t, w2, w3); CP_COMMIT();
    __syncthreads();

    // ---- build A = relu(P[dst] + Q[src]) in fp16 (half2 math) ----
    {
        const int e = t & 127, h = t >> 7;        // h in 0..3, 64 cols each
        const int de = sdst[e], se = ssrc[e];
        const uint4* Pr = reinterpret_cast<const uint4*>(P + (size_t)de * Hh + h * 64);
        const uint4* Qr = reinterpret_cast<const uint4*>(Q + (size_t)se * Hh + h * 64);
        const uint32_t arow = (uint32_t)e * AROW + (uint32_t)h * 128u;
        const __half2 z2 = __float2half2_rn(0.f);
#pragma unroll
        for (int j = 0; j < 8; j++) {
            union { uint4 u; __half2 h2[4]; } A_, B_, C_;
            A_.u = Pr[j];
            B_.u = Qr[j];
#pragma unroll
            for (int p = 0; p < 4; p++)
                C_.h2[p] = __hmax2(__hadd2(A_.h2[p], B_.h2[p]), z2);
            *(uint4*)(sm + SM_AHI + arow + j * 16) = C_.u;
        }
    }

    float acc[2][8][4];
#pragma unroll
    for (int mi = 0; mi < 2; mi++)
#pragma unroll
        for (int nj = 0; nj < 8; nj++) {
            acc[mi][nj][0] = 0.f; acc[mi][nj][1] = 0.f;
            acc[mi][nj][2] = 0.f; acc[mi][nj][3] = 0.f;
        }

    const uint32_t a_base = sb + (uint32_t)((32 * wm + (l % 16)) * AROW + (l / 16) * 16);
    const uint32_t b_off = (uint32_t)((l % 16) * 32) +
                           (uint32_t)(((l / 16) * 16) ^ (((l % 16) & 4) ? 16 : 0));

#pragma unroll 1
    for (int s = 0; s < 32; s++) {
        if (s + 2 < 32) { load_slice(s + 2, sb, t, w2, w3); CP_COMMIT(); CP_WAIT2(); }
        else if (s + 2 == 32) { CP_WAIT1(); }
        else { CP_WAIT0(); }
        __syncthreads();   // slice s visible to all; ring slot reuse fence

        const int kt = s & 15;
        uint32_t ah[2][4];
#pragma unroll
        for (int mi = 0; mi < 2; mi++) {
            const uint32_t aa = a_base + (uint32_t)(16 * mi * AROW) + kt * 32;
            LDSM4(ah[mi][0], ah[mi][1], ah[mi][2], ah[mi][3], aa + SM_AHI);
        }

        const uint32_t bbase = sb + SM_BBUF + (uint32_t)(s & 3) * 8192u + b_off
                             + (uint32_t)(wn * 2048);
#pragma unroll
        for (int c = 0; c < 4; c++) {
            uint32_t bh0, bh1, bh2, bh3;
            LDSM4(bh0, bh1, bh2, bh3, bbase + c * 512);
#pragma unroll
            for (int mi = 0; mi < 2; mi++) {
                mma16816(acc[mi][2 * c],     ah[mi][0], ah[mi][1], ah[mi][2], ah[mi][3], bh0, bh2);
                mma16816(acc[mi][2 * c + 1], ah[mi][0], ah[mi][1], ah[mi][2], ah[mi][3], bh1, bh3);
            }
        }

        if (s == 15) {
            // all warps must finish reading A slice-15 frags before overwrite
            __syncthreads();
            // ---- epilogue 1: A := fp16(relu(D1 + b2)) for this warp's 32x64 tile ----
            const int cb = (l % 4) * 2;
#pragma unroll
            for (int mi = 0; mi < 2; mi++) {
                const int r0 = 32 * wm + 16 * mi + l / 4;
#pragma unroll
                for (int nj = 0; nj < 8; nj++) {
                    const int cn = 64 * wn + 8 * nj + cb;
                    const float bz0 = sb2[cn], bz1 = sb2[cn + 1];
                    __half2 hp0 = __floats2half2_rn(fmaxf(acc[mi][nj][0] + bz0, 0.f),
                                                    fmaxf(acc[mi][nj][1] + bz1, 0.f));
                    __half2 hp1 = __floats2half2_rn(fmaxf(acc[mi][nj][2] + bz0, 0.f),
                                                    fmaxf(acc[mi][nj][3] + bz1, 0.f));
                    *(uint32_t*)(sm + SM_AHI + r0 * AROW + cn * 2)       = *(uint32_t*)&hp0;
                    *(uint32_t*)(sm + SM_AHI + (r0 + 8) * AROW + cn * 2) = *(uint32_t*)&hp1;
                    acc[mi][nj][0] = 0.f; acc[mi][nj][1] = 0.f;
                    acc[mi][nj][2] = 0.f; acc[mi][nj][3] = 0.f;
                }
            }
        }
    }

    // ---- epilogue 2: agg[dst] += D2 + b3 (vectorized no-return atomics) ----
    {
        const int cb = (l % 4) * 2;
#pragma unroll
        for (int mi = 0; mi < 2; mi++) {
            const int er = 32 * wm + 16 * mi + l / 4;
            const int d0 = sdst[er], d1 = sdst[er + 8];
            float* a0 = agg + (size_t)d0 * Hh;
            float* a1 = agg + (size_t)d1 * Hh;
#pragma unroll
            for (int nj = 0; nj < 8; nj++) {
                const int cn = 64 * wn + 8 * nj + cb;
                const float bz0 = sb3[cn], bz1 = sb3[cn + 1];
                red_add_v2(a0 + cn, acc[mi][nj][0] + bz0, acc[mi][nj][1] + bz1);
                red_add_v2(a1 + cn, acc[mi][nj][2] + bz0, acc[mi][nj][3] + bz1);
            }
        }
    }
}

// ---------------- fused node GEMM pair: P = A@Wp ; Q = A@Wq + bq ; fp16 outputs ----------------
// A fp32 (AH=false) or fp16 (AH=true); W pre-split fp16 hi/lo -> 2 MMAs per product.
template <int K, bool AH>
__global__ __launch_bounds__(512, 1) void gemm_mma_pq(
    const void* __restrict__ Ain,
    const __half* __restrict__ Wph, const __half* __restrict__ Wpl,
    const __half* __restrict__ Wqh, const __half* __restrict__ Wql,
    const float* __restrict__ biasq,
    __half* __restrict__ Pout, __half* __restrict__ Qout, int M)
{
    constexpr int AROWK = K * 2 + 16;
    constexpr int SA_HI = 0;
    constexpr int S_BB  = 128 * AROWK;
    constexpr int S_BIAS = S_BB + 32768;
    constexpr int NS = K / 16;
    constexpr int TOT = 2 * NS;

    extern __shared__ char sm[];
    const uint32_t sb = smem_u32(sm);
    const int t = threadIdx.x;
    const int w = t >> 5, l = t & 31;
    const int wm = w & 3;
    const int wn = w >> 2;

    float* sbias = (float*)(sm + S_BIAS);
    if (t < 256) sbias[t] = biasq[t];

    // ---- load A rows as fp16 ----
    {
        const int e = t & 127, h = t >> 7;
        const int grow = blockIdx.x * 128 + e;
        constexpr int cpt = K / 4;
        const uint32_t arow = (uint32_t)e * AROWK + (uint32_t)h * (cpt * 2);
        if (grow < M) {
            if (AH) {
                const uint4* Ar = reinterpret_cast<const uint4*>(
                    (const __half*)Ain + (size_t)grow * K + h * cpt);
#pragma unroll
                for (int j = 0; j < cpt / 8; j++)
                    *(uint4*)(sm + SA_HI + arow + j * 16) = Ar[j];
            } else {
                const float4* Ar = reinterpret_cast<const float4*>(
                    (const float*)Ain + (size_t)grow * K) + h * (cpt / 4);
#pragma unroll
                for (int j = 0; j < cpt / 8; j++) {
                    float4 a0 = Ar[2 * j], a1 = Ar[2 * j + 1];
                    union { uint4 u; __half2 h2[4]; } HI;
                    HI.h2[0] = __floats2half2_rn(a0.x, a0.y);
                    HI.h2[1] = __floats2half2_rn(a0.z, a0.w);
                    HI.h2[2] = __floats2half2_rn(a1.x, a1.y);
                    HI.h2[3] = __floats2half2_rn(a1.z, a1.w);
                    *(uint4*)(sm + SA_HI + arow + j * 16) = HI.u;
                }
            }
        } else {
            const uint4 z = make_uint4(0, 0, 0, 0);
#pragma unroll
            for (int j = 0; j < cpt / 8; j++)
                *(uint4*)(sm + SA_HI + arow + j * 16) = z;
        }
    }

    float acc[2][8][4];
#pragma unroll
    for (int mi = 0; mi < 2; mi++)
#pragma unroll
        for (int nj = 0; nj < 8; nj++) {
            acc[mi][nj][0] = 0.f; acc[mi][nj][1] = 0.f;
            acc[mi][nj][2] = 0.f; acc[mi][nj][3] = 0.f;
        }

    const uint32_t a_base = sb + (uint32_t)((32 * wm + (l % 16)) * AROWK + (l / 16) * 16);
    const uint32_t b_off = (uint32_t)((l % 16) * 32) +
                           (uint32_t)(((l / 16) * 16) ^ (((l % 16) & 4) ? 16 : 0));

    auto load_b = [&](int s) {
        const __half* Bh = (s < NS) ? Wph : Wqh;
        const __half* Bl = (s < NS) ? Wpl : Wql;
        const int kt = s & (NS - 1);
        const uint32_t base = sb + S_BB + (uint32_t)(s & 1) * 16384u;
        const int n = t >> 1;
        const int h = t & 1;
        const char* gh = (const char*)(Bh + (size_t)n * K + kt * 16) + h * 16;
        const char* gl = (const char*)(Bl + (size_t)n * K + kt * 16) + h * 16;
        const uint32_t sw4 = (n & 4) ? 16u : 0u;
        const uint32_t doff = base + (uint32_t)n * 32u + (((uint32_t)h * 16u) ^ sw4);
        cp16(doff, gh);
        cp16(doff + 8192u, gl);
    };

    load_b(0); CP_COMMIT();
    load_b(1); CP_COMMIT();

    const int e_r0base = blockIdx.x * 128;

#pragma unroll 1
    for (int s = 0; s < TOT; s++) {
        if (s < TOT - 2) { CP_WAIT1(); } else { CP_WAIT0(); }
        __syncthreads();

        const int kt = s & (NS - 1);
        uint32_t ah[2][4];
#pragma unroll
        for (int mi = 0; mi < 2; mi++) {
            const uint32_t aa = a_base + (uint32_t)(16 * mi * AROWK) + kt * 32;
            LDSM4(ah[mi][0], ah[mi][1], ah[mi][2], ah[mi][3], aa + SA_HI);
        }

        const uint32_t bbase = sb + S_BB + (uint32_t)(s & 1) * 16384u + b_off
                             + (uint32_t)(wn * 2048);
#pragma unroll
        for (int c = 0; c < 4; c++) {
            uint32_t bh0, bh1, bh2, bh3, bl0, bl1, bl2, bl3;
            LDSM4(bh0, bh1, bh2, bh3, bbase + c * 512);
            LDSM4(bl0, bl1, bl2, bl3, bbase + 8192 + c * 512);
#pragma unroll
            for (int mi = 0; mi < 2; mi++) {
                float* c0 = acc[mi][2 * c];
                float* c1 = acc[mi][2 * c + 1];
                mma16816(c0, ah[mi][0], ah[mi][1], ah[mi][2], ah[mi][3], bh0, bh2);
                mma16816(c0, ah[mi][0], ah[mi][1], ah[mi][2], ah[mi][3], bl0, bl2);
                mma16816(c1, ah[mi][0], ah[mi][1], ah[mi][2], ah[mi][3], bh1, bh3);
                mma16816(c1, ah[mi][0], ah[mi][1], ah[mi][2], ah[mi][3], bl1, bl3);
            }
        }

        if (s == NS - 1) {
            // ---- write P (no bias), reset acc ----
            const int cb = (l % 4) * 2;
#pragma unroll
            for (int mi = 0; mi < 2; mi++) {
                const int r0 = 32 * wm + 16 * mi + l / 4;
                const int g0 = e_r0base + r0;
                const int g1 = g0 + 8;
#pragma unroll
                for (int nj = 0; nj < 8; nj++) {
                    const int cn = 64 * wn + 8 * nj + cb;
                    __half2 hp0 = __floats2half2_rn(acc[mi][nj][0], acc[mi][nj][1]);
                    __half2 hp1 = __floats2half2_rn(acc[mi][nj][2], acc[mi][nj][3]);
                    if (g0 < M) *(uint32_t*)(Pout + (size_t)g0 * Hh + cn) = *(uint32_t*)&hp0;
                    if (g1 < M) *(uint32_t*)(Pout + (size_t)g1 * Hh + cn) = *(uint32_t*)&hp1;
                    acc[mi][nj][0] = 0.f; acc[mi][nj][1] = 0.f;
                    acc[mi][nj][2] = 0.f; acc[mi][nj][3] = 0.f;
                }
            }
        }
        __syncthreads();
        if (s + 2 < TOT) {
            load_b(s + 2);
            CP_COMMIT();
        }
    }

    // ---- write Q (+ biasq) ----
    {
        const int cb = (l % 4) * 2;
#pragma unroll
        for (int mi = 0; mi < 2; mi++) {
            const int r0 = 32 * wm + 16 * mi + l / 4;
            const int g0 = e_r0base + r0;
            const int g1 = g0 + 8;
#pragma unroll
            for (int nj = 0; nj < 8; nj++) {
                const int cn = 64 * wn + 8 * nj + cb;
                const float bz0 = sbias[cn], bz1 = sbias[cn + 1];
                __half2 hp0 = __floats2half2_rn(acc[mi][nj][0] + bz0, acc[mi][nj][1] + bz1);
                __half2 hp1 = __floats2half2_rn(acc[mi][nj][2] + bz0, acc[mi][nj][3] + bz1);
                if (g0 < M) *(uint32_t*)(Qout + (size_t)g0 * Hh + cn) = *(uint32_t*)&hp0;
                if (g1 < M) *(uint32_t*)(Qout + (size_t)g1 * Hh + cn) = *(uint32_t*)&hp1;
            }
        }
    }
}

// ---------------- tensor-core node GEMM (fp32 out, for assign hidden; A fp16 in gmem) --------
template <int K, bool RELU>
__global__ __launch_bounds__(512, 1) void gemm_mma(
    const __half* __restrict__ Ain,
    const __half* __restrict__ Whi, const __half* __restrict__ Wlo,
    const float* __restrict__ bias, float* __restrict__ C, int M)
{
    constexpr int AROWK = K * 2 + 16;
    constexpr int SA_HI = 0;
    constexpr int S_BB  = 128 * AROWK;
    constexpr int S_BIAS = S_BB + 32768;
    constexpr int NS = K / 16;

    extern __shared__ char sm[];
    const uint32_t sb = smem_u32(sm);
    const int t = threadIdx.x;
    const int w = t >> 5, l = t & 31;
    const int wm = w & 3;
    const int wn = w >> 2;

    float* sbias = (float*)(sm + S_BIAS);
    if (t < 256) sbias[t] = bias ? bias[t] : 0.f;

    {
        const int e = t & 127, h = t >> 7;
        const int grow = blockIdx.x * 128 + e;
        constexpr int cpt = K / 4;
        const uint32_t arow = (uint32_t)e * AROWK + (uint32_t)h * (cpt * 2);
        if (grow < M) {
            const uint4* Ar = reinterpret_cast<const uint4*>(Ain + (size_t)grow * K + h * cpt);
#pragma unroll
            for (int j = 0; j < cpt / 8; j++)
                *(uint4*)(sm + SA_HI + arow + j * 16) = Ar[j];
        } else {
            const uint4 z = make_uint4(0, 0, 0, 0);
#pragma unroll
            for (int j = 0; j < cpt / 8; j++)
                *(uint4*)(sm + SA_HI + arow + j * 16) = z;
        }
    }

    float acc[2][8][4];
#pragma unroll
    for (int mi = 0; mi < 2; mi++)
#pragma unroll
        for (int nj = 0; nj < 8; nj++) {
            acc[mi][nj][0] = 0.f; acc[mi][nj][1] = 0.f;
            acc[mi][nj][2] = 0.f; acc[mi][nj][3] = 0.f;
        }

    const uint32_t a_base = sb + (uint32_t)((32 * wm + (l % 16)) * AROWK + (l / 16) * 16);
    const uint32_t b_off = (uint32_t)((l % 16) * 32) +
                           (uint32_t)(((l / 16) * 16) ^ (((l % 16) & 4) ? 16 : 0));

    auto load_b = [&](int s) {
        const uint32_t base = sb + S_BB + (uint32_t)(s & 1) * 16384u;
        const int n = t >> 1;
        const int h = t & 1;
        const char* gh = (const char*)(Whi + (size_t)n * K + s * 16) + h * 16;
        const char* gl = (const char*)(Wlo + (size_t)n * K + s * 16) + h * 16;
        const uint32_t sw4 = (n & 4) ? 16u : 0u;
        const uint32_t doff = base + (uint32_t)n * 32u + (((uint32_t)h * 16u) ^ sw4);
        cp16(doff, gh);
        cp16(doff + 8192u, gl);
    };

    load_b(0); CP_COMMIT();
    load_b(1); CP_COMMIT();

#pragma unroll 1
    for (int s = 0; s < NS; s++) {
        if (s < NS - 2) { CP_WAIT1(); } else { CP_WAIT0(); }
        __syncthreads();

        uint32_t ah[2][4];
#pragma unroll
        for (int mi = 0; mi < 2; mi++) {
            const uint32_t aa = a_base + (uint32_t)(16 * mi * AROWK) + s * 32;
            LDSM4(ah[mi][0], ah[mi][1], ah[mi][2], ah[mi][3], aa + SA_HI);
        }

        const uint32_t bbase = sb + S_BB + (uint32_t)(s & 1) * 16384u + b_off
                             + (uint32_t)(wn * 2048);
#pragma unroll
        for (int c = 0; c < 4; c++) {
            uint32_t bh0, bh1, bh2, bh3, bl0, bl1, bl2, bl3;
            LDSM4(bh0, bh1, bh2, bh3, bbase + c * 512);
            LDSM4(bl0, bl1, bl2, bl3, bbase + 8192 + c * 512);
#pragma unroll
            for (int mi = 0; mi < 2; mi++) {
                float* c0 = acc[mi][2 * c];
                float* c1 = acc[mi][2 * c + 1];
                mma16816(c0, ah[mi][0], ah[mi][1], ah[mi][2], ah[mi][3], bh0, bh2);
                mma16816(c0, ah[mi][0], ah[mi][1], ah[mi][2], ah[mi][3], bl0, bl2);
                mma16816(c1, ah[mi][0], ah[mi][1], ah[mi][2], ah[mi][3], bh1, bh3);
                mma16816(c1, ah[mi][0], ah[mi][1], ah[mi][2], ah[mi][3], bl1, bl3);
            }
        }
        __syncthreads();
        if (s + 2 < NS) {
            load_b(s + 2);
            CP_COMMIT();
        }
    }

    {
        const int cb = (l % 4) * 2;
#pragma unroll
        for (int mi = 0; mi < 2; mi++) {
            const int r0 = 32 * wm + 16 * mi + l / 4;
            const int g0 = blockIdx.x * 128 + r0;
            const int g1 = g0 + 8;
#pragma unroll
            for (int nj = 0; nj < 8; nj++) {
                const int cn = 64 * wn + 8 * nj + cb;
                const float bz0 = sbias[cn], bz1 = sbias[cn + 1];
                float v0 = acc[mi][nj][0] + bz0, v1 = acc[mi][nj][1] + bz1;
                float v2 = acc[mi][nj][2] + bz0, v3 = acc[mi][nj][3] + bz1;
                if (RELU) {
                    v0 = fmaxf(v0, 0.f); v1 = fmaxf(v1, 0.f);
                    v2 = fmaxf(v2, 0.f); v3 = fmaxf(v3, 0.f);
                }
                if (g0 < M) { float2 o = make_float2(v0, v1); *(float2*)(C + (size_t)g0 * Hh + cn) = o; }
                if (g1 < M) { float2 o = make_float2(v2, v3); *(float2*)(C + (size_t)g1 * Hh + cn) = o; }
            }
        }
    }
}

// ---------------- zero ----------------
__global__ void zero_kernel(float* p, int n) {
    int i = blockIdx.x * blockDim.x + threadIdx.x;
    if (i < n) p[i] = 0.f;
}

// ---------------- generic row-tiled fp32 GEMM (small outputs only) ----------------
template <int NCOL, int RPB>
__global__ __launch_bounds__(256) void gemm_tiled(
    const float* __restrict__ A, int K,
    const float* __restrict__ W, const float* __restrict__ bias,
    float* __restrict__ C, int M, int do_relu)
{
    __shared__ float As[RPB * 256];
    const int row0 = blockIdx.x * RPB;
    const int tot = RPB * K;
    for (int idx = threadIdx.x; idx < tot; idx += 256) {
        int r = idx / K, k = idx - r * K;
        int gr = row0 + r;
        As[idx] = (gr < M) ? A[gr * K + k] : 0.f;
    }
    __syncthreads();

    const int RG = 256 / NCOL;
    const int RPT = RPB / RG;
    const int col = threadIdx.x % NCOL;
    const int rg = threadIdx.x / NCOL;

    float acc[RPT];
    float bv = bias ? bias[col] : 0.f;
#pragma unroll
    for (int i = 0; i < RPT; i++) acc[i] = bv;

    for (int k = 0; k < K; k += 4) {
        float wv0 = W[(k + 0) * NCOL + col];
        float wv1 = W[(k + 1) * NCOL + col];
        float wv2 = W[(k + 2) * NCOL + col];
        float wv3 = W[(k + 3) * NCOL + col];
#pragma unroll
        for (int i = 0; i < RPT; i++) {
            const float4 a = *(const float4*)&As[(rg + i * RG) * K + k];
            acc[i] = fmaf(a.x, wv0, acc[i]);
            acc[i] = fmaf(a.y, wv1, acc[i]);
            acc[i] = fmaf(a.z, wv2, acc[i]);
            acc[i] = fmaf(a.w, wv3, acc[i]);
        }
    }
#pragma unroll
    for (int i = 0; i < RPT; i++) {
        int gr = row0 + rg + i * RG;
        if (gr < M) {
            float v = acc[i];
            if (do_relu) v = fmaxf(v, 0.f);
            C[gr * NCOL + col] = v;
        }
    }
}

// ---------------- relu + layernorm per node (re-zeroes agg; dual fp32+fp16 output) -----------
__device__ __forceinline__ float warp_sum(float v) {
#pragma unroll
    for (int o = 16; o > 0; o >>= 1) v += __shfl_xor_sync(0xFFFFFFFFu, v, o);
    return v;
}

__global__ __launch_bounds__(256) void relu_ln_kernel(
    float* __restrict__ agg, const float* __restrict__ g,
    const float* __restrict__ b, float* __restrict__ xout,
    __half* __restrict__ xhout)
{
    const int n = blockIdx.x;
    const int j = threadIdx.x;
    const int lane = j & 31, warp = j >> 5;
    __shared__ float red[8];
    __shared__ float s_mu, s_rstd;

    float v = fmaxf(agg[n * Hh + j], 0.f);
    agg[n * Hh + j] = 0.f;             // reset accumulator for the next edge layer
    float t = warp_sum(v);
    if (lane == 0) red[warp] = t;
    __syncthreads();
    if (j == 0) {
        float s = 0.f;
#pragma unroll
        for (int i = 0; i < 8; i++) s += red[i];
        s_mu = s / (float)Hh;
    }
    __syncthreads();
    float d = v - s_mu;
    float t2 = warp_sum(d * d);
    if (lane == 0) red[warp] = t2;
    __syncthreads();
    if (j == 0) {
        float s = 0.f;
#pragma unroll
        for (int i = 0; i < 8; i++) s += red[i];
        s_rstd = rsqrtf(s / (float)Hh + 1e-5f);
    }
    __syncthreads();
    float o = d * s_rstd * g[j] + b[j];
    xout[n * Hh + j] = o;
    xhout[n * Hh + j] = __float2half_rn(o);
}

// ---------------- assignment ----------------
__global__ __launch_bounds__(256) void assign_kernel(
    const float* __restrict__ t1, const float* __restrict__ aw2,
    const float* __restrict__ ab2, const float* __restrict__ u,
    float* __restrict__ s_out, float* __restrict__ entsum, float* __restrict__ colsum)
{
    __shared__ float rows[8 * Hh];
    __shared__ float blk_col[Ss];
    __shared__ float blk_ent;

    const int lane = threadIdx.x & 31, warp = threadIdx.x >> 5;
    if (threadIdx.x < Ss) blk_col[threadIdx.x] = 0.f;
    if (threadIdx.x == 0) blk_ent = 0.f;
    const int n0 = blockIdx.x * 8;
    for (int idx = threadIdx.x; idx < 8 * Hh; idx += 256)
        rows[idx] = t1[n0 * Hh + idx];
    __syncthreads();

    const int n = n0 + warp;
    float acc = ab2[lane];
    for (int k = 0; k < Hh; k += 4) {
        const float4 a = *(const float4*)&rows[warp * Hh + k];
        acc = fmaf(a.x, aw2[(k + 0) * Ss + lane], acc);
        acc = fmaf(a.y, aw2[(k + 1) * Ss + lane], acc);
        acc = fmaf(a.z, aw2[(k + 2) * Ss + lane], acc);
        acc = fmaf(a.w, aw2[(k + 3) * Ss + lane], acc);
    }
    float uu = u[n * Ss + lane];
    float gmb = -logf(-logf(uu + EPS_F) + EPS_F);
    float z = acc + gmb;
    float m = z;
#pragma unroll
    for (int o = 16; o > 0; o >>= 1) m = fmaxf(m, __shfl_xor_sync(0xFFFFFFFFu, m, o));
    float p = expf(z - m);
    float sum = warp_sum(p);
    float sv = p / sum;
    s_out[n * Ss + lane] = sv;

    float ent = warp_sum(sv * logf(sv + EPS_F));
    if (lane == 0) atomicAdd(&blk_ent, ent);
    atomicAdd(&blk_col[lane], sv);
    __syncthreads();
    if (threadIdx.x == 0) atomicAdd(entsum, blk_ent);
    if (threadIdx.x < Ss) atomicAdd(&colsum[threadIdx.x], blk_col[threadIdx.x]);
}

// ---------------- batch segment starts ----------------
__global__ void bstart_kernel(const int* __restrict__ batch, int* __restrict__ bstart) {
    int b = threadIdx.x;
    if (b > Bb) return;
    if (b == Bb) { bstart[Bb] = Nn; return; }
    int lo = 0, hi = Nn;
    while (lo < hi) {
        int mid = (lo + hi) >> 1;
        if (batch[mid] < b) lo = mid + 1; else hi = mid;
    }
    bstart[b] = lo;
}

// ---------------- pooling ----------------
__global__ __launch_bounds__(256) void pool_kernel(
    const float* __restrict__ x, const float* __restrict__ s_out,
    const int* __restrict__ bstart, float* __restrict__ pooled)
{
    const int b = blockIdx.x;
    const int chunk = blockIdx.y;
    const int NCHUNK = gridDim.y;
    const int lo = bstart[b], hi = bstart[b + 1];
    const int cnt = hi - lo;
    const int c0 = lo + (int)(((long long)cnt * chunk) / NCHUNK);
    const int c1 = lo + (int)(((long long)cnt * (chunk + 1)) / NCHUNK);

    __shared__ float ss[Ss];
    const int t = threadIdx.x;
    float acc[Ss];
#pragma unroll
    for (int sl = 0; sl < Ss; sl++) acc[sl] = 0.f;

    for (int n = c0; n < c1; n++) {
        __syncthreads();
        if (t < Ss) ss[t] = s_out[n * Ss + t];
        __syncthreads();
        float xv = x[n * Hh + t];
#pragma unroll
        for (int sl = 0; sl < Ss; sl++) acc[sl] = fmaf(xv, ss[sl], acc[sl]);
    }
#pragma unroll
    for (int sl = 0; sl < Ss; sl++)
        atomicAdd(&pooled[(b * Ss + sl) * Hh + t], acc[sl]);
}

// ---------------- final scalar loss ----------------
__global__ void finalize_kernel(const float* __restrict__ colsum,
                                const float* __restrict__ entsum,
                                float* __restrict__ out_loss)
{
    int l = threadIdx.x;
    float avg = colsum[l] / (float)Nn;
    float dv = avg * logf(avg + EPS_F);
    dv = warp_sum(dv);
    if (l == 0) {
        float entropy = -(entsum[0] / (float)Nn);
        out_loss[0] = entropy + dv;
    }
}

// ---------------- launch ----------------
extern "C" void kernel_launch(void* const* d_in, const int* in_sizes, int n_in,
                              void* d_out, int out_size)
{
    const float* x    = (const float*)d_in[0];
    const float* u    = (const float*)d_in[1];
    const int* eidx   = (const int*)d_in[2];
    const int* batch  = (const int*)d_in[3];
    const float* g1w1 = (const float*)d_in[4];
    const float* g1b1 = (const float*)d_in[5];
    const float* g1w2 = (const float*)d_in[6];
    const float* g1b2 = (const float*)d_in[7];
    const float* g1w3 = (const float*)d_in[8];
    const float* g1b3 = (const float*)d_in[9];
    const float* ln1g = (const float*)d_in[10];
    const float* ln1b = (const float*)d_in[11];
    const float* g2w1 = (const float*)d_in[12];
    const float* g2b1 = (const float*)d_in[13];
    const float* g2w2 = (const float*)d_in[14];
    const float* g2b2 = (const float*)d_in[15];
    const float* g2w3 = (const float*)d_in[16];
    const float* g2b3 = (const float*)d_in[17];
    const float* ln2g = (const float*)d_in[18];
    const float* ln2b = (const float*)d_in[19];
    const float* aw1  = (const float*)d_in[20];
    const float* ab1  = (const float*)d_in[21];
    const float* aw2  = (const float*)d_in[22];
    const float* ab2  = (const float*)d_in[23];
    const float* ow1  = (const float*)d_in[24];
    const float* ob1  = (const float*)d_in[25];
    const float* ow2  = (const float*)d_in[26];
    const float* ob2  = (const float*)d_in[27];

    const int* src = eidx;
    const int* dst = eidx + Ee;

    float* out = (float*)d_out;
    float* out_latent = out;
    float* out_s = out + Bb * Ss * Ll;
    float* out_loss = out + Bb * Ss * Ll + Nn * Ss;

    float *P, *agg, *xc, *pooled, *t2, *colsum, *entsum;
    __half *Ph, *Qh, *xh;
    int* bstart;
    __half *wbf, *wn;
    cudaGetSymbolAddress((void**)&P, d_P);
    cudaGetSymbolAddress((void**)&Ph, d_Ph);
    cudaGetSymbolAddress((void**)&Qh, d_Qh);
    cudaGetSymbolAddress((void**)&agg, d_agg);
    cudaGetSymbolAddress((void**)&xc, d_x);
    cudaGetSymbolAddress((void**)&xh, d_xh);
    cudaGetSymbolAddress((void**)&pooled, d_pooled);
    cudaGetSymbolAddress((void**)&t2, d_t2);
    cudaGetSymbolAddress((void**)&colsum, d_colsum);
    cudaGetSymbolAddress((void**)&entsum, d_entsum);
    cudaGetSymbolAddress((void**)&bstart, d_bstart);
    cudaGetSymbolAddress((void**)&wbf, d_wbf);
    cudaGetSymbolAddress((void**)&wn, d_wnode);

    cudaFuncSetAttribute(edge_mma_kernel, cudaFuncAttributeMaxDynamicSharedMemorySize, SM_TOT);
    cudaFuncSetAttribute(gemm_mma_pq<64, false>,  cudaFuncAttributeMaxDynamicSharedMemorySize, 52224);
    cudaFuncSetAttribute(gemm_mma_pq<256, true>,  cudaFuncAttributeMaxDynamicSharedMemorySize, 101376);
    cudaFuncSetAttribute(gemm_mma<256, true>, cudaFuncAttributeMaxDynamicSharedMemorySize, 101376);

    const int NH = Nn * Hh;
    const int ZB = 256;
    const int WN = Hh * Hh;   // 65536
    const int GB = (Nn + 127) / 128;   // 157

    // node weight split offsets (halfs)
    __half* g1Ph = wn + 0;       __half* g1Pl = wn + 16384;
    __half* g1Qh = wn + 32768;   __half* g1Ql = wn + 49152;
    __half* g2Ph = wn + 65536;   __half* g2Pl = wn + 131072;
    __half* g2Qh = wn + 196608;  __half* g2Ql = wn + 262144;
    __half* awh  = wn + 327680;  __half* awl  = wn + 393216;

    // ---- zero accumulators ----
    zero_kernel<<<(NH + ZB - 1) / ZB, ZB>>>(agg, NH);
    zero_kernel<<<(Bb * Ss * Hh + ZB - 1) / ZB, ZB>>>(pooled, Bb * Ss * Hh);
    zero_kernel<<<1, ZB>>>(colsum, Ss);
    zero_kernel<<<1, ZB>>>(entsum, 1);

    // ---- edge weights: transpose + fp16 ----
    wsplit_kernel<<<256, 256>>>(g1w2, wbf + 0 * WN);
    wsplit_kernel<<<256, 256>>>(g1w3, wbf + 1 * WN);
    wsplit_kernel<<<256, 256>>>(g2w2, wbf + 2 * WN);
    wsplit_kernel<<<256, 256>>>(g2w3, wbf + 3 * WN);

    // ---- node weights: transpose + fp16 hi/lo split ----
    wsplit_node<<<64, 256>>>(g1w1,            64,  g1Ph, g1Pl);
    wsplit_node<<<64, 256>>>(g1w1 + 64 * Hh,  64,  g1Qh, g1Ql);
    wsplit_node<<<256, 256>>>(g2w1,           256, g2Ph, g2Pl);
    wsplit_node<<<256, 256>>>(g2w1 + Hh * Hh, 256, g2Qh, g2Ql);
    wsplit_node<<<256, 256>>>(aw1,            256, awh,  awl);

    // ---- GNN layer 1 ----
    gemm_mma_pq<64, false><<<GB, 512, 52224>>>(x, g1Ph, g1Pl, g1Qh, g1Ql, g1b1, Ph, Qh, Nn);
    edge_mma_kernel<<<Ee / 128, 512, SM_TOT>>>(src, dst, Ph, Qh,
        wbf + 0 * WN, wbf + 1 * WN, g1b2, g1b3, agg);
    relu_ln_kernel<<<Nn, 256>>>(agg, ln1g, ln1b, xc, xh);   // also re-zeroes agg

    // ---- GNN layer 2 ----
    gemm_mma_pq<256, true><<<GB, 512, 101376>>>(xh, g2Ph, g2Pl, g2Qh, g2Ql, g2b1, Ph, Qh, Nn);
    edge_mma_kernel<<<Ee / 128, 512, SM_TOT>>>(src, dst, Ph, Qh,
        wbf + 2 * WN, wbf + 3 * WN, g2b2, g2b3, agg);
    relu_ln_kernel<<<Nn, 256>>>(agg, ln2g, ln2b, xc, xh);

    // ---- assignment ----
    gemm_mma<256, true><<<GB, 512, 101376>>>(xh, awh, awl, ab1, P, Nn);
    assign_kernel<<<Nn / 8, 256>>>(P, aw2, ab2, u, out_s, entsum, colsum);

    // ---- pooling ----
    bstart_kernel<<<1, 32>>>(batch, bstart);
    {
        dim3 grid(Bb, 8);
        pool_kernel<<<grid, 256>>>(xc, out_s, bstart, pooled);
    }

    // ---- output MLP ----
    gemm_tiled<Hh, 32><<<(Bb * Ss) / 32, 256>>>(pooled, Hh, ow1, ob1, t2, Bb * Ss, 1);
    gemm_tiled<Ll, 32><<<(Bb * Ss) / 32, 256>>>(t2, Hh, ow2, ob2, out_latent, Bb * Ss, 0);

    // ---- loss scalar ----
    finalize_kernel<<<1, 32>>>(colsum, entsum, out_loss);
}